// round 7
// baseline (speedup 1.0000x reference)
#include <cuda_runtime.h>
#include <cuda_bf16.h>
#include <cstdint>
#include <math.h>

// ---------------------------------------------------------------------------
// CenterRingFormerPlus: mm1 (K=7168 roll GEMM) via int8 IMMA fixed-point split
// (q = qh*128 + ql, 3 IMMAs per k=32 => 2x fewer MMA instrs than bf16 split);
// remaining GEMMs via bf16 hi/lo split 3-MMA HMMA. 128x128 CTA tiles, BK
// stages with 3-stage cp.async ring, SW128 swizzle, fused epilogues.
// ---------------------------------------------------------------------------

#define MT 16384
#define NT 1024
#define NELE (16384u * 1024u)

// ---- scratch (device globals; no allocation allowed) ----
__device__ int8_t g_q8h[NELE], g_q8l[NELE];          // queries int8 hi/lo
__device__ unsigned g_amaxu;                          // |queries| max (bits)
__device__ float g_qsc;                               // queries scale
__device__ int8_t g_w1qh[1024u*7168u], g_w1ql[1024u*7168u];  // fr_w1^T int8
__device__ float g_w1sc[1024], g_w1inv[1024];         // per-out-col scale
__device__ __nv_bfloat16 g_h1h[NELE], g_h1l[NELE];
__device__ __nv_bfloat16 g_xrh[NELE], g_xrl[NELE];
__device__ __nv_bfloat16 g_t1h[NELE], g_t1l[NELE];
__device__ __nv_bfloat16 g_wth[NELE], g_wtl[NELE];
__device__ __nv_bfloat16 g_hfh[NELE], g_hfl[NELE];
__device__ float g_xrf[NELE];
__device__ float g_tpf[NELE];
__device__ float g_gtf[NELE];
// transposed weights, [N=1024, K] K-major, hi/lo bf16
__device__ __nv_bfloat16 g_w2th[1024u*1024u], g_w2tl[1024u*1024u];
__device__ __nv_bfloat16 g_c1th[1024u*1024u], g_c1tl[1024u*1024u];
__device__ __nv_bfloat16 g_c2th[1024u*1024u], g_c2tl[1024u*1024u];
__device__ __nv_bfloat16 g_f2th[1024u*1024u], g_f2tl[1024u*1024u];
__device__ __nv_bfloat16 g_fcth[1024u*2048u], g_fctl[1024u*2048u];
__device__ __nv_bfloat16 g_gwth[1024u*2048u], g_gwtl[1024u*2048u];

__constant__ int c_shifts[7] = {1, -1, 0, 2, -2, 4, -4};

enum { A_DIRECT = 0, A_ROLL = 1, A_CONCAT = 2 };
enum { EP_GELU_BF = 0, EP_BF_F32 = 1, EP_F32 = 2, EP_SIG = 3, EP_FINAL = 4 };

// ---------------- helpers ----------------
static __device__ __forceinline__ uint32_t s2u(const void* p) {
    return (uint32_t)__cvta_generic_to_shared(p);
}
static __device__ __forceinline__ void cp16(uint32_t d, const void* s) {
    asm volatile("cp.async.cg.shared.global [%0], [%1], 16;\n" :: "r"(d), "l"(s));
}
static __device__ __forceinline__ void cp_commit() {
    asm volatile("cp.async.commit_group;\n" ::: "memory");
}
static __device__ __forceinline__ void ldm4(uint32_t& r0, uint32_t& r1,
                                            uint32_t& r2, uint32_t& r3, uint32_t a) {
    asm volatile("ldmatrix.sync.aligned.m8n8.x4.shared.b16 {%0,%1,%2,%3}, [%4];"
                 : "=r"(r0), "=r"(r1), "=r"(r2), "=r"(r3) : "r"(a));
}
static __device__ __forceinline__ void mma16816(float* d, const uint32_t* a,
                                                const uint32_t* b) {
    asm volatile(
        "mma.sync.aligned.m16n8k16.row.col.f32.bf16.bf16.f32 "
        "{%0,%1,%2,%3}, {%4,%5,%6,%7}, {%8,%9}, {%0,%1,%2,%3};"
        : "+f"(d[0]), "+f"(d[1]), "+f"(d[2]), "+f"(d[3])
        : "r"(a[0]), "r"(a[1]), "r"(a[2]), "r"(a[3]), "r"(b[0]), "r"(b[1]));
}
static __device__ __forceinline__ void imma16832(int* d, const uint32_t* a,
                                                 const uint32_t* b) {
    asm volatile(
        "mma.sync.aligned.m16n8k32.row.col.s32.s8.s8.s32 "
        "{%0,%1,%2,%3}, {%4,%5,%6,%7}, {%8,%9}, {%0,%1,%2,%3};"
        : "+r"(d[0]), "+r"(d[1]), "+r"(d[2]), "+r"(d[3])
        : "r"(a[0]), "r"(a[1]), "r"(a[2]), "r"(a[3]), "r"(b[0]), "r"(b[1]));
}
static __device__ __forceinline__ float gelu_exact(float x) {
    return 0.5f * x * (1.0f + erff(x * 0.7071067811865476f));
}
static __device__ __forceinline__ void split_bf(float v, __nv_bfloat16& h, __nv_bfloat16& l) {
    h = __float2bfloat16(v);
    l = __float2bfloat16(v - __bfloat162float(h));
}

// ---------------- bf16 tile loader (BK=64 elems, SW128, hi/lo A and B) ------
#define STG_BYTES 65536
#define T_AH 0
#define T_AL 16384
#define T_BH 32768
#define T_BL 49152

template <int ASRC>
static __device__ __forceinline__ void load_stage(
    uint32_t buf,
    const __nv_bfloat16* __restrict__ Ah, const __nv_bfloat16* __restrict__ Al,
    const __nv_bfloat16* __restrict__ A2h, const __nv_bfloat16* __restrict__ A2l,
    const __nv_bfloat16* __restrict__ Bh, const __nv_bfloat16* __restrict__ Bl,
    int K, int k0, int bm, int bn, int tid)
{
#pragma unroll
    for (int i = 0; i < 4; i++) {
        const int c = tid + i * 256;
        const int r = c >> 3, ch = c & 7;
        const uint32_t bo = (uint32_t)(r * 128 + ch * 16);
        const uint32_t sw = bo ^ ((bo >> 3) & 0x70);

        const __nv_bfloat16 *pah, *pal;
        size_t aoff;
        if (ASRC == A_DIRECT) {
            aoff = (size_t)(bm + r) * (size_t)K + (size_t)(k0 + ch * 8);
            pah = Ah; pal = Al;
        } else {  // A_CONCAT
            if (k0 < 1024) { pah = Ah; pal = Al; } else { pah = A2h; pal = A2l; }
            aoff = (size_t)(bm + r) * 1024u + (size_t)((k0 & 1023) + ch * 8);
        }
        cp16(buf + T_AH + sw, pah + aoff);
        cp16(buf + T_AL + sw, pal + aoff);

        const size_t boff = (size_t)(bn + r) * (size_t)K + (size_t)(k0 + ch * 8);
        cp16(buf + T_BH + sw, Bh + boff);
        cp16(buf + T_BL + sw, Bl + boff);
    }
}

// ---------------- per-kk fragment load (12 ldmatrix) ----------------
static __device__ __forceinline__ void ldfrag(
    uint32_t buf, int kk, int wm, int wn,
    int a_row, int a_kb, int b_row, int b_kb,
    uint32_t (*ah)[4], uint32_t (*al)[4], uint32_t (*bh)[2], uint32_t (*bl)[2])
{
#pragma unroll
    for (int p = 0; p < 2; p++) {
        const uint32_t bo = (uint32_t)((wn + p * 16 + b_row) * 128 + kk * 32 + b_kb);
        const uint32_t sw = bo ^ ((bo >> 3) & 0x70);
        ldm4(bh[2*p][0], bh[2*p][1], bh[2*p+1][0], bh[2*p+1][1], buf + T_BH + sw);
        ldm4(bl[2*p][0], bl[2*p][1], bl[2*p+1][0], bl[2*p+1][1], buf + T_BL + sw);
    }
#pragma unroll
    for (int mt = 0; mt < 4; mt++) {
        const uint32_t bo = (uint32_t)((wm + mt * 16 + a_row) * 128 + kk * 32 + a_kb);
        const uint32_t sw = bo ^ ((bo >> 3) & 0x70);
        ldm4(ah[mt][0], ah[mt][1], ah[mt][2], ah[mt][3], buf + T_AH + sw);
        ldm4(al[mt][0], al[mt][1], al[mt][2], al[mt][3], buf + T_AL + sw);
    }
}

// hi-only / lo-only fragment loads (int8 path)
static __device__ __forceinline__ void ldfrag_hi(
    uint32_t buf, int kk, int wm, int wn,
    int a_row, int a_kb, int b_row, int b_kb,
    uint32_t (*ah)[4], uint32_t (*bh)[2])
{
#pragma unroll
    for (int p = 0; p < 2; p++) {
        const uint32_t bo = (uint32_t)((wn + p * 16 + b_row) * 128 + kk * 32 + b_kb);
        const uint32_t sw = bo ^ ((bo >> 3) & 0x70);
        ldm4(bh[2*p][0], bh[2*p][1], bh[2*p+1][0], bh[2*p+1][1], buf + T_BH + sw);
    }
#pragma unroll
    for (int mt = 0; mt < 4; mt++) {
        const uint32_t bo = (uint32_t)((wm + mt * 16 + a_row) * 128 + kk * 32 + a_kb);
        const uint32_t sw = bo ^ ((bo >> 3) & 0x70);
        ldm4(ah[mt][0], ah[mt][1], ah[mt][2], ah[mt][3], buf + T_AH + sw);
    }
}
static __device__ __forceinline__ void ldfrag_lo(
    uint32_t buf, int kk, int wm, int wn,
    int a_row, int a_kb, int b_row, int b_kb,
    uint32_t (*al)[4], uint32_t (*bl)[2])
{
#pragma unroll
    for (int p = 0; p < 2; p++) {
        const uint32_t bo = (uint32_t)((wn + p * 16 + b_row) * 128 + kk * 32 + b_kb);
        const uint32_t sw = bo ^ ((bo >> 3) & 0x70);
        ldm4(bl[2*p][0], bl[2*p][1], bl[2*p+1][0], bl[2*p+1][1], buf + T_BL + sw);
    }
#pragma unroll
    for (int mt = 0; mt < 4; mt++) {
        const uint32_t bo = (uint32_t)((wm + mt * 16 + a_row) * 128 + kk * 32 + a_kb);
        const uint32_t sw = bo ^ ((bo >> 3) & 0x70);
        ldm4(al[mt][0], al[mt][1], al[mt][2], al[mt][3], buf + T_AL + sw);
    }
}

// ---------------- bf16 GEMM kernel (mm2..mm8) ----------------
#define SMEM_DYN (1024 + 3 * STG_BYTES)

template <int ASRC, int EPI>
__global__ __launch_bounds__(256, 1)
void mm_k(const __nv_bfloat16* __restrict__ Ah, const __nv_bfloat16* __restrict__ Al,
          const __nv_bfloat16* __restrict__ A2h, const __nv_bfloat16* __restrict__ A2l,
          const __nv_bfloat16* __restrict__ Bth, const __nv_bfloat16* __restrict__ Btl,
          const float* __restrict__ bias, int K,
          __nv_bfloat16* __restrict__ Oh, __nv_bfloat16* __restrict__ Ol,
          float* __restrict__ Of,
          const float* __restrict__ e_gate, const float* __restrict__ e_xr)
{
    extern __shared__ char smraw[];
    const uint32_t bufbase = (s2u(smraw) + 1023u) & ~1023u;
    const int tid = threadIdx.x, wid = tid >> 5, lane = tid & 31;
    const int bn = blockIdx.x * 128, bm = blockIdx.y * 128;
    const int wm = (wid >> 2) * 64, wn = (wid & 3) * 32;

    float acc[4][4][4];
#pragma unroll
    for (int mt = 0; mt < 4; mt++)
#pragma unroll
        for (int nt = 0; nt < 4; nt++)
#pragma unroll
            for (int r = 0; r < 4; r++) acc[mt][nt][r] = 0.0f;

    const int nst = K >> 6;

    load_stage<ASRC>(bufbase,             Ah, Al, A2h, A2l, Bth, Btl, K, 0,  bm, bn, tid);
    cp_commit();
    load_stage<ASRC>(bufbase + STG_BYTES, Ah, Al, A2h, A2l, Bth, Btl, K, 64, bm, bn, tid);
    cp_commit();

    const int a_row = lane & 15;
    const int a_kb  = ((lane >> 4) & 1) * 16;
    const int b_row = (lane & 7) + ((lane >> 4) & 1) * 8;
    const int b_kb  = ((lane >> 3) & 1) * 16;

    uint32_t ah[2][4][4], al[2][4][4], bh[2][4][2], bl[2][4][2];

    for (int s = 0; s < nst; s++) {
        if (s < nst - 1) asm volatile("cp.async.wait_group 1;" ::: "memory");
        else             asm volatile("cp.async.wait_group 0;" ::: "memory");
        __syncthreads();

        const uint32_t buf = bufbase + (uint32_t)(s % 3) * STG_BYTES;

        ldfrag(buf, 0, wm, wn, a_row, a_kb, b_row, b_kb, ah[0], al[0], bh[0], bl[0]);
#pragma unroll
        for (int kk = 0; kk < 4; kk++) {
            const int cur = kk & 1, nxt = cur ^ 1;
#pragma unroll
            for (int mt = 0; mt < 4; mt++)
#pragma unroll
                for (int nt = 0; nt < 4; nt++)
                    mma16816(acc[mt][nt], ah[cur][mt], bh[cur][nt]);
            if (kk < 3)
                ldfrag(buf, kk + 1, wm, wn, a_row, a_kb, b_row, b_kb,
                       ah[nxt], al[nxt], bh[nxt], bl[nxt]);
#pragma unroll
            for (int mt = 0; mt < 4; mt++)
#pragma unroll
                for (int nt = 0; nt < 4; nt++)
                    mma16816(acc[mt][nt], ah[cur][mt], bl[cur][nt]);
#pragma unroll
            for (int mt = 0; mt < 4; mt++)
#pragma unroll
                for (int nt = 0; nt < 4; nt++)
                    mma16816(acc[mt][nt], al[cur][mt], bh[cur][nt]);
        }

        if (s + 2 < nst) {
            load_stage<ASRC>(bufbase + (uint32_t)((s + 2) % 3) * STG_BYTES,
                             Ah, Al, A2h, A2l, Bth, Btl, K, (s + 2) * 64, bm, bn, tid);
            cp_commit();
        }
    }

    const int qr = lane >> 2;
    const int qc = (lane & 3) * 2;
#pragma unroll
    for (int mt = 0; mt < 4; mt++) {
#pragma unroll
        for (int nt = 0; nt < 4; nt++) {
            const int col = bn + wn + nt * 8 + qc;
            const float2 bs = *(const float2*)(bias + col);
#pragma unroll
            for (int h = 0; h < 2; h++) {
                const int row = bm + wm + mt * 16 + qr + h * 8;
                const size_t off = (size_t)row * 1024u + (size_t)col;
                float v0 = acc[mt][nt][2*h]     + bs.x;
                float v1 = acc[mt][nt][2*h + 1] + bs.y;

                if (EPI == EP_GELU_BF) {
                    v0 = gelu_exact(v0);  v1 = gelu_exact(v1);
                    __nv_bfloat162 hh, ll;
                    split_bf(v0, hh.x, ll.x);  split_bf(v1, hh.y, ll.y);
                    *(__nv_bfloat162*)(Oh + off) = hh;
                    *(__nv_bfloat162*)(Ol + off) = ll;
                } else if (EPI == EP_BF_F32) {
                    __nv_bfloat162 hh, ll;
                    split_bf(v0, hh.x, ll.x);  split_bf(v1, hh.y, ll.y);
                    *(__nv_bfloat162*)(Oh + off) = hh;
                    *(__nv_bfloat162*)(Ol + off) = ll;
                    *(float2*)(Of + off) = make_float2(v0, v1);
                } else if (EPI == EP_F32) {
                    *(float2*)(Of + off) = make_float2(v0, v1);
                } else if (EPI == EP_SIG) {
                    v0 = 1.0f / (1.0f + expf(-v0));
                    v1 = 1.0f / (1.0f + expf(-v1));
                    *(float2*)(Of + off) = make_float2(v0, v1);
                } else {
                    const float2 g = *(const float2*)(e_gate + off);
                    const float2 x = *(const float2*)(e_xr + off);
                    *(float2*)(Of + off) = make_float2(
                        g.x * v0 + (1.0f - g.x) * x.x,
                        g.y * v1 + (1.0f - g.y) * x.y);
                }
            }
        }
    }
}

// ---------------- int8 GEMM kernel (mm1 only: roll-gathered, gelu->bf16) ----
// BK = 128 int8 elements per stage (same 64KB layout / swizzle / cp16 count).
__global__ __launch_bounds__(256, 1)
void mm8_k(const int8_t* __restrict__ A8h, const int8_t* __restrict__ A8l,
           const int8_t* __restrict__ B8h, const int8_t* __restrict__ B8l,
           const float* __restrict__ sap, const float* __restrict__ sbp,
           const float* __restrict__ bias, int K,
           __nv_bfloat16* __restrict__ Oh, __nv_bfloat16* __restrict__ Ol)
{
    extern __shared__ char smraw[];
    const uint32_t bufbase = (s2u(smraw) + 1023u) & ~1023u;
    const int tid = threadIdx.x, wid = tid >> 5, lane = tid & 31;
    const int bn = blockIdx.x * 128, bm = blockIdx.y * 128;
    const int wm = (wid >> 2) * 64, wn = (wid & 3) * 32;

    int accA[4][4][4], accX[4][4][4];
#pragma unroll
    for (int mt = 0; mt < 4; mt++)
#pragma unroll
        for (int nt = 0; nt < 4; nt++)
#pragma unroll
            for (int r = 0; r < 4; r++) { accA[mt][nt][r] = 0; accX[mt][nt][r] = 0; }

    const int nst = K >> 7;   // 56 stages for K=7168

    // loader lambda-style macro: one stage = 128 rows x 128 bytes per array
#define LOAD8(bufb, k0v)                                                        \
    {                                                                           \
        const int k0 = (k0v);                                                   \
        const int sh = c_shifts[k0 >> 10];                                      \
        _Pragma("unroll")                                                       \
        for (int i = 0; i < 4; i++) {                                           \
            const int c = tid + i * 256;                                        \
            const int r = c >> 3, ch = c & 7;                                   \
            const uint32_t bo = (uint32_t)(r * 128 + ch * 16);                  \
            const uint32_t sw = bo ^ ((bo >> 3) & 0x70);                        \
            const int m = bm + r, bb = m >> 11, nn = m & 2047;                  \
            const int src = (nn - sh) & 2047;                                   \
            const size_t aoff = ((size_t)((bb << 11) | src)) * 1024u            \
                              + (size_t)((k0 & 1023) + ch * 16);                \
            cp16((bufb) + T_AH + sw, A8h + aoff);                               \
            cp16((bufb) + T_AL + sw, A8l + aoff);                               \
            const size_t boff = (size_t)(bn + r) * (size_t)K                    \
                              + (size_t)(k0 + ch * 16);                         \
            cp16((bufb) + T_BH + sw, B8h + boff);                               \
            cp16((bufb) + T_BL + sw, B8l + boff);                               \
        }                                                                       \
    }

    LOAD8(bufbase, 0);              cp_commit();
    LOAD8(bufbase + STG_BYTES, 128); cp_commit();

    const int a_row = lane & 15;
    const int a_kb  = ((lane >> 4) & 1) * 16;
    const int b_row = (lane & 7) + ((lane >> 4) & 1) * 8;
    const int b_kb  = ((lane >> 3) & 1) * 16;

    uint32_t ah[2][4][4], bh[2][4][2], al[4][4], bl[4][2];

    for (int s = 0; s < nst; s++) {
        if (s < nst - 1) asm volatile("cp.async.wait_group 1;" ::: "memory");
        else             asm volatile("cp.async.wait_group 0;" ::: "memory");
        __syncthreads();

        const uint32_t buf = bufbase + (uint32_t)(s % 3) * STG_BYTES;

        ldfrag_hi(buf, 0, wm, wn, a_row, a_kb, b_row, b_kb, ah[0], bh[0]);
        ldfrag_lo(buf, 0, wm, wn, a_row, a_kb, b_row, b_kb, al, bl);
#pragma unroll
        for (int kk = 0; kk < 4; kk++) {
            const int cur = kk & 1, nxt = cur ^ 1;

            // main: qh*qh (weight 16384)
#pragma unroll
            for (int mt = 0; mt < 4; mt++)
#pragma unroll
                for (int nt = 0; nt < 4; nt++)
                    imma16832(accA[mt][nt], ah[cur][mt], bh[cur][nt]);

            if (kk < 3)
                ldfrag_hi(buf, kk + 1, wm, wn, a_row, a_kb, b_row, b_kb,
                          ah[nxt], bh[nxt]);

            // cross: qh_a*ql_b + ql_a*qh_b (weight 128)
#pragma unroll
            for (int mt = 0; mt < 4; mt++)
#pragma unroll
                for (int nt = 0; nt < 4; nt++)
                    imma16832(accX[mt][nt], ah[cur][mt], bl[nt]);
#pragma unroll
            for (int mt = 0; mt < 4; mt++)
#pragma unroll
                for (int nt = 0; nt < 4; nt++)
                    imma16832(accX[mt][nt], al[mt], bh[cur][nt]);

            if (kk < 3)
                ldfrag_lo(buf, kk + 1, wm, wn, a_row, a_kb, b_row, b_kb, al, bl);
        }

        if (s + 2 < nst) {
            LOAD8(bufbase + (uint32_t)((s + 2) % 3) * STG_BYTES, (s + 2) * 128);
            cp_commit();
        }
    }
#undef LOAD8

    const float sa = *sap;
    const int qr = lane >> 2;
    const int qc = (lane & 3) * 2;
#pragma unroll
    for (int mt = 0; mt < 4; mt++) {
#pragma unroll
        for (int nt = 0; nt < 4; nt++) {
            const int col = bn + wn + nt * 8 + qc;
            const float2 bs = *(const float2*)(bias + col);
            const float2 sb = *(const float2*)(sbp + col);
            const float f0 = sa * sb.x, f1 = sa * sb.y;
#pragma unroll
            for (int h = 0; h < 2; h++) {
                const int row = bm + wm + mt * 16 + qr + h * 8;
                const size_t off = (size_t)row * 1024u + (size_t)col;
                float v0 = f0 * (16384.0f * (float)accA[mt][nt][2*h]
                               + 128.0f * (float)accX[mt][nt][2*h]) + bs.x;
                float v1 = f1 * (16384.0f * (float)accA[mt][nt][2*h+1]
                               + 128.0f * (float)accX[mt][nt][2*h+1]) + bs.y;
                v0 = gelu_exact(v0);  v1 = gelu_exact(v1);
                __nv_bfloat162 hh, ll;
                split_bf(v0, hh.x, ll.x);  split_bf(v1, hh.y, ll.y);
                *(__nv_bfloat162*)(Oh + off) = hh;
                *(__nv_bfloat162*)(Ol + off) = ll;
            }
        }
    }
}

// ---------------- quantization kernels ----------------
__global__ void zero_k(unsigned* amaxu) { *amaxu = 0u; }

__global__ void amax_k(const float* __restrict__ Q, unsigned* amaxu, int n)
{
    __shared__ float sm[8];
    float m = 0.0f;
    for (int i = blockIdx.x * 256 + threadIdx.x; i < n; i += gridDim.x * 256)
        m = fmaxf(m, fabsf(Q[i]));
#pragma unroll
    for (int off = 16; off > 0; off >>= 1)
        m = fmaxf(m, __shfl_xor_sync(0xffffffffu, m, off));
    if ((threadIdx.x & 31) == 0) sm[threadIdx.x >> 5] = m;
    __syncthreads();
    if (threadIdx.x == 0) {
        float b = sm[0];
#pragma unroll
        for (int w = 1; w < 8; w++) b = fmaxf(b, sm[w]);
        atomicMax(amaxu, __float_as_uint(b));
    }
}

__global__ void quantA_k(const float* __restrict__ Q, int8_t* __restrict__ qh8,
                         int8_t* __restrict__ ql8, float* qscp,
                         const unsigned* amaxu, int n)
{
    const float amax = __uint_as_float(*amaxu);
    const float inv = (amax > 0.0f) ? 16256.0f / amax : 0.0f;
    if (blockIdx.x == 0 && threadIdx.x == 0) *qscp = amax / 16256.0f;
    for (int i = blockIdx.x * 256 + threadIdx.x; i * 4 < n; i += gridDim.x * 256) {
        const float4 a = *(const float4*)(Q + i * 4);
        char4 h, l;
        float av[4] = {a.x, a.y, a.z, a.w};
        signed char hv[4], lv[4];
#pragma unroll
        for (int j = 0; j < 4; j++) {
            int q = (int)rintf(av[j] * inv);
            q = max(-16256, min(16256, q));
            const int qh = (int)rintf((float)q * (1.0f / 128.0f));
            const int ql = q - (qh << 7);
            hv[j] = (signed char)qh;  lv[j] = (signed char)ql;
        }
        h.x = hv[0]; h.y = hv[1]; h.z = hv[2]; h.w = hv[3];
        l.x = lv[0]; l.y = lv[1]; l.z = lv[2]; l.w = lv[3];
        *(char4*)(qh8 + i * 4) = h;
        *(char4*)(ql8 + i * 4) = l;
    }
}

// per-output-column max of fr_w1 [7168, 1024] -> scales
__global__ void w1scale_k(const float* __restrict__ W, float* __restrict__ sc,
                          float* __restrict__ invsc)
{
    __shared__ float sm[8][32];
    const int tx = threadIdx.x, ty = threadIdx.y;
    const int nn = blockIdx.x * 32 + tx;
    float m = 0.0f;
    for (int k = ty; k < 7168; k += 8)
        m = fmaxf(m, fabsf(W[(size_t)k * 1024u + nn]));
    sm[ty][tx] = m;
    __syncthreads();
    if (ty == 0) {
        float b = sm[0][tx];
#pragma unroll
        for (int w = 1; w < 8; w++) b = fmaxf(b, sm[w][tx]);
        sc[nn]    = (b > 0.0f) ? b / 16256.0f : 1.0f;
        invsc[nn] = (b > 0.0f) ? 16256.0f / b : 0.0f;
    }
}

// transpose-quantize fr_w1 [7168,1024] f32 -> [1024,7168] int8 hi/lo
__global__ void quantW1_k(const float* __restrict__ W, int8_t* __restrict__ Th,
                          int8_t* __restrict__ Tl, const float* __restrict__ invsc)
{
    __shared__ float t[32 * 33];
    const int n0 = blockIdx.x * 32, k0 = blockIdx.y * 32;
    const int tx = threadIdx.x, ty = threadIdx.y;
#pragma unroll
    for (int i = 0; i < 4; i++)
        t[(ty + i * 8) * 33 + tx] = W[(size_t)(k0 + ty + i * 8) * 1024u + n0 + tx];
    __syncthreads();
#pragma unroll
    for (int i = 0; i < 4; i++) {
        const int nn = n0 + ty + i * 8;
        const float v = t[tx * 33 + ty + i * 8];
        int q = (int)rintf(v * invsc[nn]);
        q = max(-16256, min(16256, q));
        const int qh = (int)rintf((float)q * (1.0f / 128.0f));
        const int ql = q - (qh << 7);
        const size_t o = (size_t)nn * 7168u + k0 + tx;
        Th[o] = (int8_t)qh;  Tl[o] = (int8_t)ql;
    }
}

// ---------------- weight transpose-convert: W[K,N] f32 -> Th/Tl[N,K] bf16 ----
static __device__ __forceinline__ void wconv_body(
    const float* __restrict__ W, __nv_bfloat16* __restrict__ Th,
    __nv_bfloat16* __restrict__ Tl, int K, int N, float* t)
{
    const int n0 = blockIdx.x * 32, k0 = blockIdx.y * 32;
    const int tx = threadIdx.x, ty = threadIdx.y;
#pragma unroll
    for (int i = 0; i < 4; i++)
        t[(ty + i * 8) * 33 + tx] = W[(size_t)(k0 + ty + i * 8) * N + n0 + tx];
    __syncthreads();
#pragma unroll
    for (int i = 0; i < 4; i++) {
        const float v = t[tx * 33 + ty + i * 8];
        __nv_bfloat16 h, l;
        split_bf(v, h, l);
        const size_t o = (size_t)(n0 + ty + i * 8) * K + k0 + tx;
        Th[o] = h;  Tl[o] = l;
    }
}

__global__ void wconv_k(const float* __restrict__ W, __nv_bfloat16* __restrict__ Th,
                        __nv_bfloat16* __restrict__ Tl, int K, int N)
{
    __shared__ float t[32 * 33];
    wconv_body(W, Th, Tl, K, N, t);
}

__global__ void wconv4_k(const float* W0, __nv_bfloat16* T0h, __nv_bfloat16* T0l,
                         const float* W1, __nv_bfloat16* T1h, __nv_bfloat16* T1l,
                         const float* W2, __nv_bfloat16* T2h, __nv_bfloat16* T2l,
                         const float* W3, __nv_bfloat16* T3h, __nv_bfloat16* T3l)
{
    __shared__ float t[32 * 33];
    const int z = blockIdx.z;
    if (z == 0) { if (blockIdx.y >= 32) return; wconv_body(W0, T0h, T0l, 1024, 1024, t); }
    else if (z == 1) { if (blockIdx.y >= 32) return; wconv_body(W1, T1h, T1l, 1024, 1024, t); }
    else if (z == 2) { wconv_body(W2, T2h, T2l, 2048, 1024, t); }
    else { wconv_body(W3, T3h, T3l, 2048, 1024, t); }
}

// ---------------- cluster softmax ----------------
__global__ __launch_bounds__(256)
void cluster_k(const float* __restrict__ tproj, const float* __restrict__ centers,
               __nv_bfloat16* __restrict__ wh, __nv_bfloat16* __restrict__ wl)
{
    __shared__ float sc[4 * 1024];
    const int tid = threadIdx.x;
    for (int i = tid * 4; i < 4096; i += 256 * 4)
        *(float4*)&sc[i] = *(const float4*)&centers[i];
    __syncthreads();

    const int warp = tid >> 5, lane = tid & 31;
    const size_t row = (size_t)blockIdx.x * 8 + warp;
    const float* tp = tproj + row * 1024u;

    float d0 = 0.f, d1 = 0.f, d2 = 0.f, d3 = 0.f;
    for (int d = lane * 4; d < 1024; d += 128) {
        float4 t  = *(const float4*)(tp + d);
        float4 c0 = *(const float4*)(sc + d);
        float4 c1 = *(const float4*)(sc + 1024 + d);
        float4 c2 = *(const float4*)(sc + 2048 + d);
        float4 c3 = *(const float4*)(sc + 3072 + d);
        d0 += t.x*c0.x + t.y*c0.y + t.z*c0.z + t.w*c0.w;
        d1 += t.x*c1.x + t.y*c1.y + t.z*c1.z + t.w*c1.w;
        d2 += t.x*c2.x + t.y*c2.y + t.z*c2.z + t.w*c2.w;
        d3 += t.x*c3.x + t.y*c3.y + t.z*c3.z + t.w*c3.w;
    }
#pragma unroll
    for (int off = 16; off > 0; off >>= 1) {
        d0 += __shfl_xor_sync(0xffffffffu, d0, off);
        d1 += __shfl_xor_sync(0xffffffffu, d1, off);
        d2 += __shfl_xor_sync(0xffffffffu, d2, off);
        d3 += __shfl_xor_sync(0xffffffffu, d3, off);
    }
    const float mx = fmaxf(fmaxf(d0, d1), fmaxf(d2, d3));
    const float e0 = expf(d0 - mx), e1 = expf(d1 - mx),
                e2 = expf(d2 - mx), e3 = expf(d3 - mx);
    const float inv = 1.0f / (e0 + e1 + e2 + e3);
    const float w0 = e0*inv, w1 = e1*inv, w2 = e2*inv, w3 = e3*inv;

    for (int d = lane * 4; d < 1024; d += 128) {
        float4 c0 = *(const float4*)(sc + d);
        float4 c1 = *(const float4*)(sc + 1024 + d);
        float4 c2 = *(const float4*)(sc + 2048 + d);
        float4 c3 = *(const float4*)(sc + 3072 + d);
        float o[4];
        o[0] = w0*c0.x + w1*c1.x + w2*c2.x + w3*c3.x;
        o[1] = w0*c0.y + w1*c1.y + w2*c2.y + w3*c3.y;
        o[2] = w0*c0.z + w1*c1.z + w2*c2.z + w3*c3.z;
        o[3] = w0*c0.w + w1*c1.w + w2*c2.w + w3*c3.w;
        __nv_bfloat162 h2[2], l2[2];
#pragma unroll
        for (int p = 0; p < 2; p++) {
            split_bf(o[2*p],   h2[p].x, l2[p].x);
            split_bf(o[2*p+1], h2[p].y, l2[p].y);
        }
        *(uint2*)(wh + row * 1024u + d) = *(uint2*)h2;
        *(uint2*)(wl + row * 1024u + d) = *(uint2*)l2;
    }
}

// ---------------- launch ----------------
extern "C" void kernel_launch(void* const* d_in, const int* in_sizes, int n_in,
                              void* d_out, int out_size)
{
    const float* queries = (const float*)d_in[0];
    const float* fr_w1   = (const float*)d_in[1];
    const float* fr_b1   = (const float*)d_in[2];
    const float* fr_w2   = (const float*)d_in[3];
    const float* fr_b2   = (const float*)d_in[4];
    const float* tc_w1   = (const float*)d_in[5];
    const float* tc_b1   = (const float*)d_in[6];
    const float* tc_w2   = (const float*)d_in[7];
    const float* tc_b2   = (const float*)d_in[8];
    const float* centers = (const float*)d_in[9];
    const float* fc_w1   = (const float*)d_in[10];
    const float* fc_b1   = (const float*)d_in[11];
    const float* fc_w2   = (const float*)d_in[12];
    const float* fc_b2   = (const float*)d_in[13];
    const float* g_w     = (const float*)d_in[14];
    const float* g_b     = (const float*)d_in[15];
    float* out = (float*)d_out;

#define SYM(p, s) { void* _t; cudaGetSymbolAddress(&_t, s); p = (decltype(p))_t; }
    int8_t *q8h, *q8l, *w1qh, *w1ql;
    unsigned* amaxu;
    float *qsc, *w1sc, *w1inv;
    __nv_bfloat16 *h1h, *h1l, *xrh, *xrl, *t1h, *t1l, *wth, *wtl, *hfh, *hfl;
    __nv_bfloat16 *w2th, *w2tl, *c1th, *c1tl, *c2th, *c2tl;
    __nv_bfloat16 *f2th, *f2tl, *fcth, *fctl, *gwth, *gwtl;
    float *xrf, *tpf, *gtf;
    SYM(q8h, g_q8h);   SYM(q8l, g_q8l);
    SYM(amaxu, g_amaxu); SYM(qsc, g_qsc);
    SYM(w1qh, g_w1qh); SYM(w1ql, g_w1ql);
    SYM(w1sc, g_w1sc); SYM(w1inv, g_w1inv);
    SYM(h1h, g_h1h); SYM(h1l, g_h1l);
    SYM(xrh, g_xrh); SYM(xrl, g_xrl);
    SYM(t1h, g_t1h); SYM(t1l, g_t1l);
    SYM(wth, g_wth); SYM(wtl, g_wtl);
    SYM(hfh, g_hfh); SYM(hfl, g_hfl);
    SYM(xrf, g_xrf); SYM(tpf, g_tpf); SYM(gtf, g_gtf);
    SYM(w2th, g_w2th); SYM(w2tl, g_w2tl);
    SYM(c1th, g_c1th); SYM(c1tl, g_c1tl);
    SYM(c2th, g_c2th); SYM(c2tl, g_c2tl);
    SYM(f2th, g_f2th); SYM(f2tl, g_f2tl);
    SYM(fcth, g_fcth); SYM(fctl, g_fctl);
    SYM(gwth, g_gwth); SYM(gwtl, g_gwtl);
#undef SYM

    cudaFuncSetAttribute(mm8_k, cudaFuncAttributeMaxDynamicSharedMemorySize, SMEM_DYN);
    cudaFuncSetAttribute(mm_k<A_DIRECT, EP_BF_F32>,  cudaFuncAttributeMaxDynamicSharedMemorySize, SMEM_DYN);
    cudaFuncSetAttribute(mm_k<A_DIRECT, EP_GELU_BF>, cudaFuncAttributeMaxDynamicSharedMemorySize, SMEM_DYN);
    cudaFuncSetAttribute(mm_k<A_DIRECT, EP_F32>,     cudaFuncAttributeMaxDynamicSharedMemorySize, SMEM_DYN);
    cudaFuncSetAttribute(mm_k<A_CONCAT, EP_SIG>,     cudaFuncAttributeMaxDynamicSharedMemorySize, SMEM_DYN);
    cudaFuncSetAttribute(mm_k<A_CONCAT, EP_GELU_BF>, cudaFuncAttributeMaxDynamicSharedMemorySize, SMEM_DYN);
    cudaFuncSetAttribute(mm_k<A_DIRECT, EP_FINAL>,   cudaFuncAttributeMaxDynamicSharedMemorySize, SMEM_DYN);

    dim3 wcb(32, 8);

    // ---- quantization + conversions ----
    zero_k<<<1, 1>>>(amaxu);
    amax_k<<<1024, 256>>>(queries, amaxu, (int)NELE);
    quantA_k<<<2048, 256>>>(queries, q8h, q8l, qsc, amaxu, (int)NELE);
    w1scale_k<<<32, wcb>>>(fr_w1, w1sc, w1inv);
    quantW1_k<<<dim3(32, 224), wcb>>>(fr_w1, w1qh, w1ql, w1inv);
    wconv_k<<<dim3(32, 32), wcb>>>(fr_w2, w2th, w2tl, 1024, 1024);
    wconv_k<<<dim3(32, 32), wcb>>>(tc_w1, c1th, c1tl, 1024, 1024);
    wconv4_k<<<dim3(32, 64, 4), wcb>>>(tc_w2, c2th, c2tl, fc_w2, f2th, f2tl,
                                       fc_w1, fcth, fctl, g_w, gwth, gwtl);

    dim3 grid(8, 128), block(256);

    // h1 = gelu(fusion @ fr_w1 + fr_b1)   K=7168 (roll-gathered, int8 IMMA)
    mm8_k<<<grid, block, SMEM_DYN>>>(q8h, q8l, w1qh, w1ql, qsc, w1sc,
                                     fr_b1, 7168, h1h, h1l);
    // x_ring = h1 @ fr_w2 + fr_b2
    mm_k<A_DIRECT, EP_BF_F32><<<grid, block, SMEM_DYN>>>(
        h1h, h1l, nullptr, nullptr, w2th, w2tl, fr_b2, 1024,
        xrh, xrl, xrf, nullptr, nullptr);
    // t1 = gelu(x_ring @ tc_w1 + tc_b1)
    mm_k<A_DIRECT, EP_GELU_BF><<<grid, block, SMEM_DYN>>>(
        xrh, xrl, nullptr, nullptr, c1th, c1tl, tc_b1, 1024,
        t1h, t1l, nullptr, nullptr, nullptr);
    // token_proj = t1 @ tc_w2 + tc_b2
    mm_k<A_DIRECT, EP_F32><<<grid, block, SMEM_DYN>>>(
        t1h, t1l, nullptr, nullptr, c2th, c2tl, tc_b2, 1024,
        nullptr, nullptr, tpf, nullptr, nullptr);
    // weighted = softmax(tp @ centers^T) @ centers
    cluster_k<<<MT / 8, 256>>>(tpf, centers, wth, wtl);
    // gate = sigmoid([xr|wt] @ g_w + g_b)
    mm_k<A_CONCAT, EP_SIG><<<grid, block, SMEM_DYN>>>(
        xrh, xrl, wth, wtl, gwth, gwtl, g_b, 2048,
        nullptr, nullptr, gtf, nullptr, nullptr);
    // h_fc = gelu([xr|wt] @ fc_w1 + fc_b1)
    mm_k<A_CONCAT, EP_GELU_BF><<<grid, block, SMEM_DYN>>>(
        xrh, xrl, wth, wtl, fcth, fctl, fc_b1, 2048,
        hfh, hfl, nullptr, nullptr, nullptr);
    // out = gate * (h_fc @ fc_w2 + fc_b2) + (1-gate) * x_ring
    mm_k<A_DIRECT, EP_FINAL><<<grid, block, SMEM_DYN>>>(
        hfh, hfl, nullptr, nullptr, f2th, f2tl, fc_b2, 1024,
        nullptr, nullptr, out, gtf, xrf);
}

// round 8
// speedup vs baseline: 4.1861x; 4.1861x over previous
#include <cuda_runtime.h>
#include <cuda_bf16.h>
#include <cuda_fp16.h>
#include <cstdint>
#include <math.h>

// ---------------------------------------------------------------------------
// CenterRingFormerPlus: mm1 (K=7168 roll GEMM) via SINGLE fp16 HMMA per k=16
// (fp16 11-bit mantissa => ~4e-4 per-output error, measured chain
// amplification ~1x from the R7 int8 experiment => final ~4e-4 < 1e-3).
// Remaining GEMMs: bf16 hi/lo split 3-MMA HMMA (R6 code, proven 3.4e-5).
// 128x128 CTA tiles, 3-stage cp.async ring, SW128 swizzle, fused epilogues.
// ---------------------------------------------------------------------------

#define MT 16384
#define NT 1024
#define NELE (16384u * 1024u)

// ---- scratch (device globals; no allocation allowed) ----
__device__ __half g_qf[NELE];                        // queries fp16
__device__ __half g_w1f[1024u*7168u];                // fr_w1^T fp16 [N,K]
__device__ __nv_bfloat16 g_h1h[NELE], g_h1l[NELE];
__device__ __nv_bfloat16 g_xrh[NELE], g_xrl[NELE];
__device__ __nv_bfloat16 g_t1h[NELE], g_t1l[NELE];
__device__ __nv_bfloat16 g_wth[NELE], g_wtl[NELE];
__device__ __nv_bfloat16 g_hfh[NELE], g_hfl[NELE];
__device__ float g_xrf[NELE];
__device__ float g_tpf[NELE];
__device__ float g_gtf[NELE];
// transposed weights, [N=1024, K] K-major, hi/lo bf16
__device__ __nv_bfloat16 g_w2th[1024u*1024u], g_w2tl[1024u*1024u];
__device__ __nv_bfloat16 g_c1th[1024u*1024u], g_c1tl[1024u*1024u];
__device__ __nv_bfloat16 g_c2th[1024u*1024u], g_c2tl[1024u*1024u];
__device__ __nv_bfloat16 g_f2th[1024u*1024u], g_f2tl[1024u*1024u];
__device__ __nv_bfloat16 g_fcth[1024u*2048u], g_fctl[1024u*2048u];
__device__ __nv_bfloat16 g_gwth[1024u*2048u], g_gwtl[1024u*2048u];

__constant__ int c_shifts[7] = {1, -1, 0, 2, -2, 4, -4};

enum { A_DIRECT = 0, A_CONCAT = 2 };
enum { EP_GELU_BF = 0, EP_BF_F32 = 1, EP_F32 = 2, EP_SIG = 3, EP_FINAL = 4 };

// ---------------- helpers ----------------
static __device__ __forceinline__ uint32_t s2u(const void* p) {
    return (uint32_t)__cvta_generic_to_shared(p);
}
static __device__ __forceinline__ void cp16(uint32_t d, const void* s) {
    asm volatile("cp.async.cg.shared.global [%0], [%1], 16;\n" :: "r"(d), "l"(s));
}
static __device__ __forceinline__ void cp_commit() {
    asm volatile("cp.async.commit_group;\n" ::: "memory");
}
static __device__ __forceinline__ void ldm4(uint32_t& r0, uint32_t& r1,
                                            uint32_t& r2, uint32_t& r3, uint32_t a) {
    asm volatile("ldmatrix.sync.aligned.m8n8.x4.shared.b16 {%0,%1,%2,%3}, [%4];"
                 : "=r"(r0), "=r"(r1), "=r"(r2), "=r"(r3) : "r"(a));
}
static __device__ __forceinline__ void mma16816(float* d, const uint32_t* a,
                                                const uint32_t* b) {
    asm volatile(
        "mma.sync.aligned.m16n8k16.row.col.f32.bf16.bf16.f32 "
        "{%0,%1,%2,%3}, {%4,%5,%6,%7}, {%8,%9}, {%0,%1,%2,%3};"
        : "+f"(d[0]), "+f"(d[1]), "+f"(d[2]), "+f"(d[3])
        : "r"(a[0]), "r"(a[1]), "r"(a[2]), "r"(a[3]), "r"(b[0]), "r"(b[1]));
}
static __device__ __forceinline__ void mma16816h(float* d, const uint32_t* a,
                                                 const uint32_t* b) {
    asm volatile(
        "mma.sync.aligned.m16n8k16.row.col.f32.f16.f16.f32 "
        "{%0,%1,%2,%3}, {%4,%5,%6,%7}, {%8,%9}, {%0,%1,%2,%3};"
        : "+f"(d[0]), "+f"(d[1]), "+f"(d[2]), "+f"(d[3])
        : "r"(a[0]), "r"(a[1]), "r"(a[2]), "r"(a[3]), "r"(b[0]), "r"(b[1]));
}
static __device__ __forceinline__ float gelu_exact(float x) {
    return 0.5f * x * (1.0f + erff(x * 0.7071067811865476f));
}
static __device__ __forceinline__ void split_bf(float v, __nv_bfloat16& h, __nv_bfloat16& l) {
    h = __float2bfloat16(v);
    l = __float2bfloat16(v - __bfloat162float(h));
}

// ---------------- bf16 tile loader (BK=64 elems, SW128, hi/lo A and B) ------
#define STG_BYTES 65536
#define T_AH 0
#define T_AL 16384
#define T_BH 32768
#define T_BL 49152

template <int ASRC>
static __device__ __forceinline__ void load_stage(
    uint32_t buf,
    const __nv_bfloat16* __restrict__ Ah, const __nv_bfloat16* __restrict__ Al,
    const __nv_bfloat16* __restrict__ A2h, const __nv_bfloat16* __restrict__ A2l,
    const __nv_bfloat16* __restrict__ Bh, const __nv_bfloat16* __restrict__ Bl,
    int K, int k0, int bm, int bn, int tid)
{
#pragma unroll
    for (int i = 0; i < 4; i++) {
        const int c = tid + i * 256;
        const int r = c >> 3, ch = c & 7;
        const uint32_t bo = (uint32_t)(r * 128 + ch * 16);
        const uint32_t sw = bo ^ ((bo >> 3) & 0x70);

        const __nv_bfloat16 *pah, *pal;
        size_t aoff;
        if (ASRC == A_DIRECT) {
            aoff = (size_t)(bm + r) * (size_t)K + (size_t)(k0 + ch * 8);
            pah = Ah; pal = Al;
        } else {  // A_CONCAT
            if (k0 < 1024) { pah = Ah; pal = Al; } else { pah = A2h; pal = A2l; }
            aoff = (size_t)(bm + r) * 1024u + (size_t)((k0 & 1023) + ch * 8);
        }
        cp16(buf + T_AH + sw, pah + aoff);
        cp16(buf + T_AL + sw, pal + aoff);

        const size_t boff = (size_t)(bn + r) * (size_t)K + (size_t)(k0 + ch * 8);
        cp16(buf + T_BH + sw, Bh + boff);
        cp16(buf + T_BL + sw, Bl + boff);
    }
}

// ---------------- per-kk fragment load (12 ldmatrix, bf16 path) ------------
static __device__ __forceinline__ void ldfrag(
    uint32_t buf, int kk, int wm, int wn,
    int a_row, int a_kb, int b_row, int b_kb,
    uint32_t (*ah)[4], uint32_t (*al)[4], uint32_t (*bh)[2], uint32_t (*bl)[2])
{
#pragma unroll
    for (int p = 0; p < 2; p++) {
        const uint32_t bo = (uint32_t)((wn + p * 16 + b_row) * 128 + kk * 32 + b_kb);
        const uint32_t sw = bo ^ ((bo >> 3) & 0x70);
        ldm4(bh[2*p][0], bh[2*p][1], bh[2*p+1][0], bh[2*p+1][1], buf + T_BH + sw);
        ldm4(bl[2*p][0], bl[2*p][1], bl[2*p+1][0], bl[2*p+1][1], buf + T_BL + sw);
    }
#pragma unroll
    for (int mt = 0; mt < 4; mt++) {
        const uint32_t bo = (uint32_t)((wm + mt * 16 + a_row) * 128 + kk * 32 + a_kb);
        const uint32_t sw = bo ^ ((bo >> 3) & 0x70);
        ldm4(ah[mt][0], ah[mt][1], ah[mt][2], ah[mt][3], buf + T_AH + sw);
        ldm4(al[mt][0], al[mt][1], al[mt][2], al[mt][3], buf + T_AL + sw);
    }
}

// ---------------- bf16 GEMM kernel (mm2..mm8) ----------------
#define SMEM_DYN (1024 + 3 * STG_BYTES)

template <int ASRC, int EPI>
__global__ __launch_bounds__(256, 1)
void mm_k(const __nv_bfloat16* __restrict__ Ah, const __nv_bfloat16* __restrict__ Al,
          const __nv_bfloat16* __restrict__ A2h, const __nv_bfloat16* __restrict__ A2l,
          const __nv_bfloat16* __restrict__ Bth, const __nv_bfloat16* __restrict__ Btl,
          const float* __restrict__ bias, int K,
          __nv_bfloat16* __restrict__ Oh, __nv_bfloat16* __restrict__ Ol,
          float* __restrict__ Of,
          const float* __restrict__ e_gate, const float* __restrict__ e_xr)
{
    extern __shared__ char smraw[];
    const uint32_t bufbase = (s2u(smraw) + 1023u) & ~1023u;
    const int tid = threadIdx.x, wid = tid >> 5, lane = tid & 31;
    const int bn = blockIdx.x * 128, bm = blockIdx.y * 128;
    const int wm = (wid >> 2) * 64, wn = (wid & 3) * 32;

    float acc[4][4][4];
#pragma unroll
    for (int mt = 0; mt < 4; mt++)
#pragma unroll
        for (int nt = 0; nt < 4; nt++)
#pragma unroll
            for (int r = 0; r < 4; r++) acc[mt][nt][r] = 0.0f;

    const int nst = K >> 6;

    load_stage<ASRC>(bufbase,             Ah, Al, A2h, A2l, Bth, Btl, K, 0,  bm, bn, tid);
    cp_commit();
    load_stage<ASRC>(bufbase + STG_BYTES, Ah, Al, A2h, A2l, Bth, Btl, K, 64, bm, bn, tid);
    cp_commit();

    const int a_row = lane & 15;
    const int a_kb  = ((lane >> 4) & 1) * 16;
    const int b_row = (lane & 7) + ((lane >> 4) & 1) * 8;
    const int b_kb  = ((lane >> 3) & 1) * 16;

    uint32_t ah[2][4][4], al[2][4][4], bh[2][4][2], bl[2][4][2];

    for (int s = 0; s < nst; s++) {
        if (s < nst - 1) asm volatile("cp.async.wait_group 1;" ::: "memory");
        else             asm volatile("cp.async.wait_group 0;" ::: "memory");
        __syncthreads();

        const uint32_t buf = bufbase + (uint32_t)(s % 3) * STG_BYTES;

        ldfrag(buf, 0, wm, wn, a_row, a_kb, b_row, b_kb, ah[0], al[0], bh[0], bl[0]);
#pragma unroll
        for (int kk = 0; kk < 4; kk++) {
            const int cur = kk & 1, nxt = cur ^ 1;
#pragma unroll
            for (int mt = 0; mt < 4; mt++)
#pragma unroll
                for (int nt = 0; nt < 4; nt++)
                    mma16816(acc[mt][nt], ah[cur][mt], bh[cur][nt]);
            if (kk < 3)
                ldfrag(buf, kk + 1, wm, wn, a_row, a_kb, b_row, b_kb,
                       ah[nxt], al[nxt], bh[nxt], bl[nxt]);
#pragma unroll
            for (int mt = 0; mt < 4; mt++)
#pragma unroll
                for (int nt = 0; nt < 4; nt++)
                    mma16816(acc[mt][nt], ah[cur][mt], bl[cur][nt]);
#pragma unroll
            for (int mt = 0; mt < 4; mt++)
#pragma unroll
                for (int nt = 0; nt < 4; nt++)
                    mma16816(acc[mt][nt], al[cur][mt], bh[cur][nt]);
        }

        if (s + 2 < nst) {
            load_stage<ASRC>(bufbase + (uint32_t)((s + 2) % 3) * STG_BYTES,
                             Ah, Al, A2h, A2l, Bth, Btl, K, (s + 2) * 64, bm, bn, tid);
            cp_commit();
        }
    }

    const int qr = lane >> 2;
    const int qc = (lane & 3) * 2;
#pragma unroll
    for (int mt = 0; mt < 4; mt++) {
#pragma unroll
        for (int nt = 0; nt < 4; nt++) {
            const int col = bn + wn + nt * 8 + qc;
            const float2 bs = *(const float2*)(bias + col);
#pragma unroll
            for (int h = 0; h < 2; h++) {
                const int row = bm + wm + mt * 16 + qr + h * 8;
                const size_t off = (size_t)row * 1024u + (size_t)col;
                float v0 = acc[mt][nt][2*h]     + bs.x;
                float v1 = acc[mt][nt][2*h + 1] + bs.y;

                if (EPI == EP_GELU_BF) {
                    v0 = gelu_exact(v0);  v1 = gelu_exact(v1);
                    __nv_bfloat162 hh, ll;
                    split_bf(v0, hh.x, ll.x);  split_bf(v1, hh.y, ll.y);
                    *(__nv_bfloat162*)(Oh + off) = hh;
                    *(__nv_bfloat162*)(Ol + off) = ll;
                } else if (EPI == EP_BF_F32) {
                    __nv_bfloat162 hh, ll;
                    split_bf(v0, hh.x, ll.x);  split_bf(v1, hh.y, ll.y);
                    *(__nv_bfloat162*)(Oh + off) = hh;
                    *(__nv_bfloat162*)(Ol + off) = ll;
                    *(float2*)(Of + off) = make_float2(v0, v1);
                } else if (EPI == EP_F32) {
                    *(float2*)(Of + off) = make_float2(v0, v1);
                } else if (EPI == EP_SIG) {
                    v0 = 1.0f / (1.0f + expf(-v0));
                    v1 = 1.0f / (1.0f + expf(-v1));
                    *(float2*)(Of + off) = make_float2(v0, v1);
                } else {
                    const float2 g = *(const float2*)(e_gate + off);
                    const float2 x = *(const float2*)(e_xr + off);
                    *(float2*)(Of + off) = make_float2(
                        g.x * v0 + (1.0f - g.x) * x.x,
                        g.y * v1 + (1.0f - g.y) * x.y);
                }
            }
        }
    }
}

// ---------------- fp16 single-MMA GEMM kernel (mm1: roll gather) -----------
#define STGH_BYTES 32768
#define TH_A 0
#define TH_B 16384
#define SMEM_DYN_H (1024 + 3 * STGH_BYTES)

__global__ __launch_bounds__(256, 1)
void mmh_k(const __half* __restrict__ A, const __half* __restrict__ B,
           const float* __restrict__ bias, int K,
           __nv_bfloat16* __restrict__ Oh, __nv_bfloat16* __restrict__ Ol)
{
    extern __shared__ char smraw[];
    const uint32_t bufbase = (s2u(smraw) + 1023u) & ~1023u;
    const int tid = threadIdx.x, wid = tid >> 5, lane = tid & 31;
    const int bn = blockIdx.x * 128, bm = blockIdx.y * 128;
    const int wm = (wid >> 2) * 64, wn = (wid & 3) * 32;

    float acc[4][4][4];
#pragma unroll
    for (int mt = 0; mt < 4; mt++)
#pragma unroll
        for (int nt = 0; nt < 4; nt++)
#pragma unroll
            for (int r = 0; r < 4; r++) acc[mt][nt][r] = 0.0f;

    const int nst = K >> 6;   // 112 stages

    // stage = A(128x64 fp16) + B(128x64 fp16), SW128, roll-gathered A
#define LOADH(bufb, k0v)                                                        \
    {                                                                           \
        const int k0 = (k0v);                                                   \
        const int sh = c_shifts[k0 >> 10];                                      \
        _Pragma("unroll")                                                       \
        for (int i = 0; i < 4; i++) {                                           \
            const int c = tid + i * 256;                                        \
            const int r = c >> 3, ch = c & 7;                                   \
            const uint32_t bo = (uint32_t)(r * 128 + ch * 16);                  \
            const uint32_t sw = bo ^ ((bo >> 3) & 0x70);                        \
            const int m = bm + r, bb = m >> 11, nn = m & 2047;                  \
            const int src = (nn - sh) & 2047;                                   \
            const size_t aoff = ((size_t)((bb << 11) | src)) * 1024u            \
                              + (size_t)((k0 & 1023) + ch * 8);                 \
            cp16((bufb) + TH_A + sw, A + aoff);                                 \
            const size_t boff = (size_t)(bn + r) * (size_t)K                    \
                              + (size_t)(k0 + ch * 8);                          \
            cp16((bufb) + TH_B + sw, B + boff);                                 \
        }                                                                       \
    }

    LOADH(bufbase, 0);               cp_commit();
    LOADH(bufbase + STGH_BYTES, 64); cp_commit();

    const int a_row = lane & 15;
    const int a_kb  = ((lane >> 4) & 1) * 16;
    const int b_row = (lane & 7) + ((lane >> 4) & 1) * 8;
    const int b_kb  = ((lane >> 3) & 1) * 16;

    uint32_t af[2][4][4], bf[2][4][2];

#define LDFRAGH(buf, kk, d)                                                     \
    {                                                                           \
        _Pragma("unroll")                                                       \
        for (int p = 0; p < 2; p++) {                                           \
            const uint32_t bo =                                                 \
                (uint32_t)((wn + p * 16 + b_row) * 128 + (kk) * 32 + b_kb);     \
            const uint32_t sw = bo ^ ((bo >> 3) & 0x70);                        \
            ldm4(bf[d][2*p][0], bf[d][2*p][1],                                  \
                 bf[d][2*p+1][0], bf[d][2*p+1][1], (buf) + TH_B + sw);          \
        }                                                                       \
        _Pragma("unroll")                                                       \
        for (int mt = 0; mt < 4; mt++) {                                        \
            const uint32_t bo =                                                 \
                (uint32_t)((wm + mt * 16 + a_row) * 128 + (kk) * 32 + a_kb);    \
            const uint32_t sw = bo ^ ((bo >> 3) & 0x70);                        \
            ldm4(af[d][mt][0], af[d][mt][1], af[d][mt][2], af[d][mt][3],        \
                 (buf) + TH_A + sw);                                            \
        }                                                                       \
    }

    for (int s = 0; s < nst; s++) {
        if (s < nst - 1) asm volatile("cp.async.wait_group 1;" ::: "memory");
        else             asm volatile("cp.async.wait_group 0;" ::: "memory");
        __syncthreads();

        const uint32_t buf = bufbase + (uint32_t)(s % 3) * STGH_BYTES;

        LDFRAGH(buf, 0, 0);
#pragma unroll
        for (int kk = 0; kk < 4; kk++) {
            const int cur = kk & 1, nxt = cur ^ 1;
            if (kk < 3) LDFRAGH(buf, kk + 1, nxt);
#pragma unroll
            for (int mt = 0; mt < 4; mt++)
#pragma unroll
                for (int nt = 0; nt < 4; nt++)
                    mma16816h(acc[mt][nt], af[cur][mt], bf[cur][nt]);
        }

        if (s + 2 < nst) {
            LOADH(bufbase + (uint32_t)((s + 2) % 3) * STGH_BYTES, (s + 2) * 64);
            cp_commit();
        }
    }
#undef LOADH
#undef LDFRAGH

    const int qr = lane >> 2;
    const int qc = (lane & 3) * 2;
#pragma unroll
    for (int mt = 0; mt < 4; mt++) {
#pragma unroll
        for (int nt = 0; nt < 4; nt++) {
            const int col = bn + wn + nt * 8 + qc;
            const float2 bs = *(const float2*)(bias + col);
#pragma unroll
            for (int h = 0; h < 2; h++) {
                const int row = bm + wm + mt * 16 + qr + h * 8;
                const size_t off = (size_t)row * 1024u + (size_t)col;
                float v0 = gelu_exact(acc[mt][nt][2*h]     + bs.x);
                float v1 = gelu_exact(acc[mt][nt][2*h + 1] + bs.y);
                __nv_bfloat162 hh, ll;
                split_bf(v0, hh.x, ll.x);  split_bf(v1, hh.y, ll.y);
                *(__nv_bfloat162*)(Oh + off) = hh;
                *(__nv_bfloat162*)(Ol + off) = ll;
            }
        }
    }
}

// ---------------- conversions ----------------
__global__ void qhconv_k(const float* __restrict__ Q, __half* __restrict__ H, int n)
{
    for (int i = blockIdx.x * 256 + threadIdx.x; i * 4 < n; i += gridDim.x * 256) {
        const float4 a = *(const float4*)(Q + i * 4);
        __half2 h0 = __floats2half2_rn(a.x, a.y);
        __half2 h1 = __floats2half2_rn(a.z, a.w);
        uint2 v;
        v.x = *(uint32_t*)&h0;  v.y = *(uint32_t*)&h1;
        *(uint2*)(H + i * 4) = v;
    }
}

// transpose-convert fr_w1 [7168,1024] f32 -> [1024,7168] fp16
__global__ void whconv_k(const float* __restrict__ W, __half* __restrict__ T)
{
    __shared__ float t[32 * 33];
    const int n0 = blockIdx.x * 32, k0 = blockIdx.y * 32;
    const int tx = threadIdx.x, ty = threadIdx.y;
#pragma unroll
    for (int i = 0; i < 4; i++)
        t[(ty + i * 8) * 33 + tx] = W[(size_t)(k0 + ty + i * 8) * 1024u + n0 + tx];
    __syncthreads();
#pragma unroll
    for (int i = 0; i < 4; i++) {
        const size_t o = (size_t)(n0 + ty + i * 8) * 7168u + k0 + tx;
        T[o] = __float2half_rn(t[tx * 33 + ty + i * 8]);
    }
}

// ---------------- weight transpose-convert: W[K,N] f32 -> Th/Tl[N,K] bf16 ----
static __device__ __forceinline__ void wconv_body(
    const float* __restrict__ W, __nv_bfloat16* __restrict__ Th,
    __nv_bfloat16* __restrict__ Tl, int K, int N, float* t)
{
    const int n0 = blockIdx.x * 32, k0 = blockIdx.y * 32;
    const int tx = threadIdx.x, ty = threadIdx.y;
#pragma unroll
    for (int i = 0; i < 4; i++)
        t[(ty + i * 8) * 33 + tx] = W[(size_t)(k0 + ty + i * 8) * N + n0 + tx];
    __syncthreads();
#pragma unroll
    for (int i = 0; i < 4; i++) {
        const float v = t[tx * 33 + ty + i * 8];
        __nv_bfloat16 h, l;
        split_bf(v, h, l);
        const size_t o = (size_t)(n0 + ty + i * 8) * K + k0 + tx;
        Th[o] = h;  Tl[o] = l;
    }
}

__global__ void wconv_k(const float* __restrict__ W, __nv_bfloat16* __restrict__ Th,
                        __nv_bfloat16* __restrict__ Tl, int K, int N)
{
    __shared__ float t[32 * 33];
    wconv_body(W, Th, Tl, K, N, t);
}

__global__ void wconv4_k(const float* W0, __nv_bfloat16* T0h, __nv_bfloat16* T0l,
                         const float* W1, __nv_bfloat16* T1h, __nv_bfloat16* T1l,
                         const float* W2, __nv_bfloat16* T2h, __nv_bfloat16* T2l,
                         const float* W3, __nv_bfloat16* T3h, __nv_bfloat16* T3l)
{
    __shared__ float t[32 * 33];
    const int z = blockIdx.z;
    if (z == 0) { if (blockIdx.y >= 32) return; wconv_body(W0, T0h, T0l, 1024, 1024, t); }
    else if (z == 1) { if (blockIdx.y >= 32) return; wconv_body(W1, T1h, T1l, 1024, 1024, t); }
    else if (z == 2) { wconv_body(W2, T2h, T2l, 2048, 1024, t); }
    else { wconv_body(W3, T3h, T3l, 2048, 1024, t); }
}

// ---------------- cluster softmax ----------------
__global__ __launch_bounds__(256)
void cluster_k(const float* __restrict__ tproj, const float* __restrict__ centers,
               __nv_bfloat16* __restrict__ wh, __nv_bfloat16* __restrict__ wl)
{
    __shared__ float sc[4 * 1024];
    const int tid = threadIdx.x;
    for (int i = tid * 4; i < 4096; i += 256 * 4)
        *(float4*)&sc[i] = *(const float4*)&centers[i];
    __syncthreads();

    const int warp = tid >> 5, lane = tid & 31;
    const size_t row = (size_t)blockIdx.x * 8 + warp;
    const float* tp = tproj + row * 1024u;

    float d0 = 0.f, d1 = 0.f, d2 = 0.f, d3 = 0.f;
    for (int d = lane * 4; d < 1024; d += 128) {
        float4 t  = *(const float4*)(tp + d);
        float4 c0 = *(const float4*)(sc + d);
        float4 c1 = *(const float4*)(sc + 1024 + d);
        float4 c2 = *(const float4*)(sc + 2048 + d);
        float4 c3 = *(const float4*)(sc + 3072 + d);
        d0 += t.x*c0.x + t.y*c0.y + t.z*c0.z + t.w*c0.w;
        d1 += t.x*c1.x + t.y*c1.y + t.z*c1.z + t.w*c1.w;
        d2 += t.x*c2.x + t.y*c2.y + t.z*c2.z + t.w*c2.w;
        d3 += t.x*c3.x + t.y*c3.y + t.z*c3.z + t.w*c3.w;
    }
#pragma unroll
    for (int off = 16; off > 0; off >>= 1) {
        d0 += __shfl_xor_sync(0xffffffffu, d0, off);
        d1 += __shfl_xor_sync(0xffffffffu, d1, off);
        d2 += __shfl_xor_sync(0xffffffffu, d2, off);
        d3 += __shfl_xor_sync(0xffffffffu, d3, off);
    }
    const float mx = fmaxf(fmaxf(d0, d1), fmaxf(d2, d3));
    const float e0 = expf(d0 - mx), e1 = expf(d1 - mx),
                e2 = expf(d2 - mx), e3 = expf(d3 - mx);
    const float inv = 1.0f / (e0 + e1 + e2 + e3);
    const float w0 = e0*inv, w1 = e1*inv, w2 = e2*inv, w3 = e3*inv;

    for (int d = lane * 4; d < 1024; d += 128) {
        float4 c0 = *(const float4*)(sc + d);
        float4 c1 = *(const float4*)(sc + 1024 + d);
        float4 c2 = *(const float4*)(sc + 2048 + d);
        float4 c3 = *(const float4*)(sc + 3072 + d);
        float o[4];
        o[0] = w0*c0.x + w1*c1.x + w2*c2.x + w3*c3.x;
        o[1] = w0*c0.y + w1*c1.y + w2*c2.y + w3*c3.y;
        o[2] = w0*c0.z + w1*c1.z + w2*c2.z + w3*c3.z;
        o[3] = w0*c0.w + w1*c1.w + w2*c2.w + w3*c3.w;
        __nv_bfloat162 h2[2], l2[2];
#pragma unroll
        for (int p = 0; p < 2; p++) {
            split_bf(o[2*p],   h2[p].x, l2[p].x);
            split_bf(o[2*p+1], h2[p].y, l2[p].y);
        }
        *(uint2*)(wh + row * 1024u + d) = *(uint2*)h2;
        *(uint2*)(wl + row * 1024u + d) = *(uint2*)l2;
    }
}

// ---------------- launch ----------------
extern "C" void kernel_launch(void* const* d_in, const int* in_sizes, int n_in,
                              void* d_out, int out_size)
{
    const float* queries = (const float*)d_in[0];
    const float* fr_w1   = (const float*)d_in[1];
    const float* fr_b1   = (const float*)d_in[2];
    const float* fr_w2   = (const float*)d_in[3];
    const float* fr_b2   = (const float*)d_in[4];
    const float* tc_w1   = (const float*)d_in[5];
    const float* tc_b1   = (const float*)d_in[6];
    const float* tc_w2   = (const float*)d_in[7];
    const float* tc_b2   = (const float*)d_in[8];
    const float* centers = (const float*)d_in[9];
    const float* fc_w1   = (const float*)d_in[10];
    const float* fc_b1   = (const float*)d_in[11];
    const float* fc_w2   = (const float*)d_in[12];
    const float* fc_b2   = (const float*)d_in[13];
    const float* g_w     = (const float*)d_in[14];
    const float* g_b     = (const float*)d_in[15];
    float* out = (float*)d_out;

#define SYM(p, s) { void* _t; cudaGetSymbolAddress(&_t, s); p = (decltype(p))_t; }
    __half *qf, *w1f;
    __nv_bfloat16 *h1h, *h1l, *xrh, *xrl, *t1h, *t1l, *wth, *wtl, *hfh, *hfl;
    __nv_bfloat16 *w2th, *w2tl, *c1th, *c1tl, *c2th, *c2tl;
    __nv_bfloat16 *f2th, *f2tl, *fcth, *fctl, *gwth, *gwtl;
    float *xrf, *tpf, *gtf;
    SYM(qf, g_qf);   SYM(w1f, g_w1f);
    SYM(h1h, g_h1h); SYM(h1l, g_h1l);
    SYM(xrh, g_xrh); SYM(xrl, g_xrl);
    SYM(t1h, g_t1h); SYM(t1l, g_t1l);
    SYM(wth, g_wth); SYM(wtl, g_wtl);
    SYM(hfh, g_hfh); SYM(hfl, g_hfl);
    SYM(xrf, g_xrf); SYM(tpf, g_tpf); SYM(gtf, g_gtf);
    SYM(w2th, g_w2th); SYM(w2tl, g_w2tl);
    SYM(c1th, g_c1th); SYM(c1tl, g_c1tl);
    SYM(c2th, g_c2th); SYM(c2tl, g_c2tl);
    SYM(f2th, g_f2th); SYM(f2tl, g_f2tl);
    SYM(fcth, g_fcth); SYM(fctl, g_fctl);
    SYM(gwth, g_gwth); SYM(gwtl, g_gwtl);
#undef SYM

    cudaFuncSetAttribute(mmh_k, cudaFuncAttributeMaxDynamicSharedMemorySize, SMEM_DYN_H);
    cudaFuncSetAttribute(mm_k<A_DIRECT, EP_BF_F32>,  cudaFuncAttributeMaxDynamicSharedMemorySize, SMEM_DYN);
    cudaFuncSetAttribute(mm_k<A_DIRECT, EP_GELU_BF>, cudaFuncAttributeMaxDynamicSharedMemorySize, SMEM_DYN);
    cudaFuncSetAttribute(mm_k<A_DIRECT, EP_F32>,     cudaFuncAttributeMaxDynamicSharedMemorySize, SMEM_DYN);
    cudaFuncSetAttribute(mm_k<A_CONCAT, EP_SIG>,     cudaFuncAttributeMaxDynamicSharedMemorySize, SMEM_DYN);
    cudaFuncSetAttribute(mm_k<A_CONCAT, EP_GELU_BF>, cudaFuncAttributeMaxDynamicSharedMemorySize, SMEM_DYN);
    cudaFuncSetAttribute(mm_k<A_DIRECT, EP_FINAL>,   cudaFuncAttributeMaxDynamicSharedMemorySize, SMEM_DYN);

    dim3 wcb(32, 8);

    // ---- conversions ----
    qhconv_k<<<2048, 256>>>(queries, qf, (int)NELE);
    whconv_k<<<dim3(32, 224), wcb>>>(fr_w1, w1f);
    wconv_k<<<dim3(32, 32), wcb>>>(fr_w2, w2th, w2tl, 1024, 1024);
    wconv_k<<<dim3(32, 32), wcb>>>(tc_w1, c1th, c1tl, 1024, 1024);
    wconv4_k<<<dim3(32, 64, 4), wcb>>>(tc_w2, c2th, c2tl, fc_w2, f2th, f2tl,
                                       fc_w1, fcth, fctl, g_w, gwth, gwtl);

    dim3 grid(8, 128), block(256);

    // h1 = gelu(fusion @ fr_w1 + fr_b1)   K=7168 (roll-gathered, fp16 single)
    mmh_k<<<grid, block, SMEM_DYN_H>>>(qf, w1f, fr_b1, 7168, h1h, h1l);
    // x_ring = h1 @ fr_w2 + fr_b2
    mm_k<A_DIRECT, EP_BF_F32><<<grid, block, SMEM_DYN>>>(
        h1h, h1l, nullptr, nullptr, w2th, w2tl, fr_b2, 1024,
        xrh, xrl, xrf, nullptr, nullptr);
    // t1 = gelu(x_ring @ tc_w1 + tc_b1)
    mm_k<A_DIRECT, EP_GELU_BF><<<grid, block, SMEM_DYN>>>(
        xrh, xrl, nullptr, nullptr, c1th, c1tl, tc_b1, 1024,
        t1h, t1l, nullptr, nullptr, nullptr);
    // token_proj = t1 @ tc_w2 + tc_b2
    mm_k<A_DIRECT, EP_F32><<<grid, block, SMEM_DYN>>>(
        t1h, t1l, nullptr, nullptr, c2th, c2tl, tc_b2, 1024,
        nullptr, nullptr, tpf, nullptr, nullptr);
    // weighted = softmax(tp @ centers^T) @ centers
    cluster_k<<<MT / 8, 256>>>(tpf, centers, wth, wtl);
    // gate = sigmoid([xr|wt] @ g_w + g_b)
    mm_k<A_CONCAT, EP_SIG><<<grid, block, SMEM_DYN>>>(
        xrh, xrl, wth, wtl, gwth, gwtl, g_b, 2048,
        nullptr, nullptr, gtf, nullptr, nullptr);
    // h_fc = gelu([xr|wt] @ fc_w1 + fc_b1)
    mm_k<A_CONCAT, EP_GELU_BF><<<grid, block, SMEM_DYN>>>(
        xrh, xrl, wth, wtl, fcth, fctl, fc_b1, 2048,
        hfh, hfl, nullptr, nullptr, nullptr);
    // out = gate * (h_fc @ fc_w2 + fc_b2) + (1-gate) * x_ring
    mm_k<A_DIRECT, EP_FINAL><<<grid, block, SMEM_DYN>>>(
        hfh, hfl, nullptr, nullptr, f2th, f2tl, fc_b2, 1024,
        nullptr, nullptr, out, gtf, xrf);
}

// round 9
// speedup vs baseline: 5.0491x; 1.2061x over previous
#include <cuda_runtime.h>
#include <cuda_bf16.h>
#include <cuda_fp16.h>
#include <cstdint>
#include <math.h>

// ---------------------------------------------------------------------------
// CenterRingFormerPlus: mm1 (K=7168 roll), mm6 (gate), mm7 (h_fc) via SINGLE
// fp16 HMMA per k=16 (measured ~3.5e-4/GEMM, chain amplification ~1x,
// deterministic inputs => quadrature total ~6e-4 < 1e-3).
// mm2/mm3/mm4/mm8 stay bf16 hi/lo split 3-MMA (3.4e-5).
// 128x128 CTA tiles, 3-stage cp.async ring, SW128 swizzle, fused epilogues.
// ---------------------------------------------------------------------------

#define MT 16384
#define NT 1024
#define NELE (16384u * 1024u)

// ---- scratch (device globals; no allocation allowed) ----
__device__ __half g_qf[NELE];                        // queries fp16
__device__ __half g_w1f[1024u*7168u];                // fr_w1^T fp16 [N,K]
__device__ __half g_fc1f[1024u*2048u];               // fc_w1^T fp16
__device__ __half g_gwf[1024u*2048u];                // g_w^T fp16
__device__ __half g_xrf16[NELE];                     // x_ring fp16
__device__ __half g_wtf[NELE];                       // weighted fp16
__device__ __nv_bfloat16 g_h1h[NELE], g_h1l[NELE];
__device__ __nv_bfloat16 g_xrh[NELE], g_xrl[NELE];
__device__ __nv_bfloat16 g_t1h[NELE], g_t1l[NELE];
__device__ __nv_bfloat16 g_hfh[NELE], g_hfl[NELE];
__device__ float g_xrf[NELE];
__device__ float g_tpf[NELE];
__device__ float g_gtf[NELE];
// transposed weights, [N=1024, K] K-major, hi/lo bf16
__device__ __nv_bfloat16 g_w2th[1024u*1024u], g_w2tl[1024u*1024u];
__device__ __nv_bfloat16 g_c1th[1024u*1024u], g_c1tl[1024u*1024u];
__device__ __nv_bfloat16 g_c2th[1024u*1024u], g_c2tl[1024u*1024u];
__device__ __nv_bfloat16 g_f2th[1024u*1024u], g_f2tl[1024u*1024u];

__constant__ int c_shifts[7] = {1, -1, 0, 2, -2, 4, -4};

enum { A_DIRECT = 0, A_ROLL = 1, A_CONCAT = 2 };
enum { EP_GELU_BF = 0, EP_BF_F32 = 1, EP_F32 = 2, EP_SIG = 3, EP_FINAL = 4 };

// ---------------- helpers ----------------
static __device__ __forceinline__ uint32_t s2u(const void* p) {
    return (uint32_t)__cvta_generic_to_shared(p);
}
static __device__ __forceinline__ void cp16(uint32_t d, const void* s) {
    asm volatile("cp.async.cg.shared.global [%0], [%1], 16;\n" :: "r"(d), "l"(s));
}
static __device__ __forceinline__ void cp_commit() {
    asm volatile("cp.async.commit_group;\n" ::: "memory");
}
static __device__ __forceinline__ void ldm4(uint32_t& r0, uint32_t& r1,
                                            uint32_t& r2, uint32_t& r3, uint32_t a) {
    asm volatile("ldmatrix.sync.aligned.m8n8.x4.shared.b16 {%0,%1,%2,%3}, [%4];"
                 : "=r"(r0), "=r"(r1), "=r"(r2), "=r"(r3) : "r"(a));
}
static __device__ __forceinline__ void mma16816(float* d, const uint32_t* a,
                                                const uint32_t* b) {
    asm volatile(
        "mma.sync.aligned.m16n8k16.row.col.f32.bf16.bf16.f32 "
        "{%0,%1,%2,%3}, {%4,%5,%6,%7}, {%8,%9}, {%0,%1,%2,%3};"
        : "+f"(d[0]), "+f"(d[1]), "+f"(d[2]), "+f"(d[3])
        : "r"(a[0]), "r"(a[1]), "r"(a[2]), "r"(a[3]), "r"(b[0]), "r"(b[1]));
}
static __device__ __forceinline__ void mma16816h(float* d, const uint32_t* a,
                                                 const uint32_t* b) {
    asm volatile(
        "mma.sync.aligned.m16n8k16.row.col.f32.f16.f16.f32 "
        "{%0,%1,%2,%3}, {%4,%5,%6,%7}, {%8,%9}, {%0,%1,%2,%3};"
        : "+f"(d[0]), "+f"(d[1]), "+f"(d[2]), "+f"(d[3])
        : "r"(a[0]), "r"(a[1]), "r"(a[2]), "r"(a[3]), "r"(b[0]), "r"(b[1]));
}
static __device__ __forceinline__ float gelu_exact(float x) {
    return 0.5f * x * (1.0f + erff(x * 0.7071067811865476f));
}
static __device__ __forceinline__ void split_bf(float v, __nv_bfloat16& h, __nv_bfloat16& l) {
    h = __float2bfloat16(v);
    l = __float2bfloat16(v - __bfloat162float(h));
}

// ---------------- bf16 tile loader (BK=64 elems, SW128, hi/lo A and B) ------
#define STG_BYTES 65536
#define T_AH 0
#define T_AL 16384
#define T_BH 32768
#define T_BL 49152

template <int ASRC>
static __device__ __forceinline__ void load_stage(
    uint32_t buf,
    const __nv_bfloat16* __restrict__ Ah, const __nv_bfloat16* __restrict__ Al,
    const __nv_bfloat16* __restrict__ Bh, const __nv_bfloat16* __restrict__ Bl,
    int K, int k0, int bm, int bn, int tid)
{
#pragma unroll
    for (int i = 0; i < 4; i++) {
        const int c = tid + i * 256;
        const int r = c >> 3, ch = c & 7;
        const uint32_t bo = (uint32_t)(r * 128 + ch * 16);
        const uint32_t sw = bo ^ ((bo >> 3) & 0x70);

        const size_t aoff = (size_t)(bm + r) * (size_t)K + (size_t)(k0 + ch * 8);
        cp16(buf + T_AH + sw, Ah + aoff);
        cp16(buf + T_AL + sw, Al + aoff);

        const size_t boff = (size_t)(bn + r) * (size_t)K + (size_t)(k0 + ch * 8);
        cp16(buf + T_BH + sw, Bh + boff);
        cp16(buf + T_BL + sw, Bl + boff);
    }
}

// ---------------- per-kk fragment load (12 ldmatrix, bf16 path) ------------
static __device__ __forceinline__ void ldfrag(
    uint32_t buf, int kk, int wm, int wn,
    int a_row, int a_kb, int b_row, int b_kb,
    uint32_t (*ah)[4], uint32_t (*al)[4], uint32_t (*bh)[2], uint32_t (*bl)[2])
{
#pragma unroll
    for (int p = 0; p < 2; p++) {
        const uint32_t bo = (uint32_t)((wn + p * 16 + b_row) * 128 + kk * 32 + b_kb);
        const uint32_t sw = bo ^ ((bo >> 3) & 0x70);
        ldm4(bh[2*p][0], bh[2*p][1], bh[2*p+1][0], bh[2*p+1][1], buf + T_BH + sw);
        ldm4(bl[2*p][0], bl[2*p][1], bl[2*p+1][0], bl[2*p+1][1], buf + T_BL + sw);
    }
#pragma unroll
    for (int mt = 0; mt < 4; mt++) {
        const uint32_t bo = (uint32_t)((wm + mt * 16 + a_row) * 128 + kk * 32 + a_kb);
        const uint32_t sw = bo ^ ((bo >> 3) & 0x70);
        ldm4(ah[mt][0], ah[mt][1], ah[mt][2], ah[mt][3], buf + T_AH + sw);
        ldm4(al[mt][0], al[mt][1], al[mt][2], al[mt][3], buf + T_AL + sw);
    }
}

// ---------------- bf16 GEMM kernel (mm2, mm3, mm4, mm8) ----------------
#define SMEM_DYN (1024 + 3 * STG_BYTES)

template <int EPI>
__global__ __launch_bounds__(256, 1)
void mm_k(const __nv_bfloat16* __restrict__ Ah, const __nv_bfloat16* __restrict__ Al,
          const __nv_bfloat16* __restrict__ Bth, const __nv_bfloat16* __restrict__ Btl,
          const float* __restrict__ bias, int K,
          __nv_bfloat16* __restrict__ Oh, __nv_bfloat16* __restrict__ Ol,
          float* __restrict__ Of, __half* __restrict__ Oh16,
          const float* __restrict__ e_gate, const float* __restrict__ e_xr)
{
    extern __shared__ char smraw[];
    const uint32_t bufbase = (s2u(smraw) + 1023u) & ~1023u;
    const int tid = threadIdx.x, wid = tid >> 5, lane = tid & 31;
    const int bn = blockIdx.x * 128, bm = blockIdx.y * 128;
    const int wm = (wid >> 2) * 64, wn = (wid & 3) * 32;

    float acc[4][4][4];
#pragma unroll
    for (int mt = 0; mt < 4; mt++)
#pragma unroll
        for (int nt = 0; nt < 4; nt++)
#pragma unroll
            for (int r = 0; r < 4; r++) acc[mt][nt][r] = 0.0f;

    const int nst = K >> 6;

    load_stage<A_DIRECT>(bufbase,             Ah, Al, Bth, Btl, K, 0,  bm, bn, tid);
    cp_commit();
    load_stage<A_DIRECT>(bufbase + STG_BYTES, Ah, Al, Bth, Btl, K, 64, bm, bn, tid);
    cp_commit();

    const int a_row = lane & 15;
    const int a_kb  = ((lane >> 4) & 1) * 16;
    const int b_row = (lane & 7) + ((lane >> 4) & 1) * 8;
    const int b_kb  = ((lane >> 3) & 1) * 16;

    uint32_t ah[2][4][4], al[2][4][4], bh[2][4][2], bl[2][4][2];

    for (int s = 0; s < nst; s++) {
        if (s < nst - 1) asm volatile("cp.async.wait_group 1;" ::: "memory");
        else             asm volatile("cp.async.wait_group 0;" ::: "memory");
        __syncthreads();

        const uint32_t buf = bufbase + (uint32_t)(s % 3) * STG_BYTES;

        ldfrag(buf, 0, wm, wn, a_row, a_kb, b_row, b_kb, ah[0], al[0], bh[0], bl[0]);
#pragma unroll
        for (int kk = 0; kk < 4; kk++) {
            const int cur = kk & 1, nxt = cur ^ 1;
#pragma unroll
            for (int mt = 0; mt < 4; mt++)
#pragma unroll
                for (int nt = 0; nt < 4; nt++)
                    mma16816(acc[mt][nt], ah[cur][mt], bh[cur][nt]);
            if (kk < 3)
                ldfrag(buf, kk + 1, wm, wn, a_row, a_kb, b_row, b_kb,
                       ah[nxt], al[nxt], bh[nxt], bl[nxt]);
#pragma unroll
            for (int mt = 0; mt < 4; mt++)
#pragma unroll
                for (int nt = 0; nt < 4; nt++)
                    mma16816(acc[mt][nt], ah[cur][mt], bl[cur][nt]);
#pragma unroll
            for (int mt = 0; mt < 4; mt++)
#pragma unroll
                for (int nt = 0; nt < 4; nt++)
                    mma16816(acc[mt][nt], al[cur][mt], bh[cur][nt]);
        }

        if (s + 2 < nst) {
            load_stage<A_DIRECT>(bufbase + (uint32_t)((s + 2) % 3) * STG_BYTES,
                                 Ah, Al, Bth, Btl, K, (s + 2) * 64, bm, bn, tid);
            cp_commit();
        }
    }

    const int qr = lane >> 2;
    const int qc = (lane & 3) * 2;
#pragma unroll
    for (int mt = 0; mt < 4; mt++) {
#pragma unroll
        for (int nt = 0; nt < 4; nt++) {
            const int col = bn + wn + nt * 8 + qc;
            const float2 bs = *(const float2*)(bias + col);
#pragma unroll
            for (int h = 0; h < 2; h++) {
                const int row = bm + wm + mt * 16 + qr + h * 8;
                const size_t off = (size_t)row * 1024u + (size_t)col;
                float v0 = acc[mt][nt][2*h]     + bs.x;
                float v1 = acc[mt][nt][2*h + 1] + bs.y;

                if (EPI == EP_GELU_BF) {
                    v0 = gelu_exact(v0);  v1 = gelu_exact(v1);
                    __nv_bfloat162 hh, ll;
                    split_bf(v0, hh.x, ll.x);  split_bf(v1, hh.y, ll.y);
                    *(__nv_bfloat162*)(Oh + off) = hh;
                    *(__nv_bfloat162*)(Ol + off) = ll;
                } else if (EPI == EP_BF_F32) {
                    __nv_bfloat162 hh, ll;
                    split_bf(v0, hh.x, ll.x);  split_bf(v1, hh.y, ll.y);
                    *(__nv_bfloat162*)(Oh + off) = hh;
                    *(__nv_bfloat162*)(Ol + off) = ll;
                    *(float2*)(Of + off) = make_float2(v0, v1);
                    *(__half2*)(Oh16 + off) = __floats2half2_rn(v0, v1);
                } else if (EPI == EP_F32) {
                    *(float2*)(Of + off) = make_float2(v0, v1);
                } else {  // EP_FINAL
                    const float2 g = *(const float2*)(e_gate + off);
                    const float2 x = *(const float2*)(e_xr + off);
                    *(float2*)(Of + off) = make_float2(
                        g.x * v0 + (1.0f - g.x) * x.x,
                        g.y * v1 + (1.0f - g.y) * x.y);
                }
            }
        }
    }
}

// ---------------- fp16 single-MMA GEMM kernel (mm1, mm6, mm7) --------------
#define STGH_BYTES 32768
#define TH_A 0
#define TH_B 16384
#define SMEM_DYN_H (1024 + 3 * STGH_BYTES)

template <int ASRC>
static __device__ __forceinline__ void loadh_stage(
    uint32_t buf, const __half* __restrict__ A, const __half* __restrict__ A2,
    const __half* __restrict__ B, int K, int k0, int bm, int bn, int tid)
{
#pragma unroll
    for (int i = 0; i < 4; i++) {
        const int c = tid + i * 256;
        const int r = c >> 3, ch = c & 7;
        const uint32_t bo = (uint32_t)(r * 128 + ch * 16);
        const uint32_t sw = bo ^ ((bo >> 3) & 0x70);

        const __half* pa;
        size_t aoff;
        if (ASRC == A_ROLL) {
            const int sh = c_shifts[k0 >> 10];
            const int m = bm + r, bb = m >> 11, nn = m & 2047;
            const int src = (nn - sh) & 2047;
            aoff = ((size_t)((bb << 11) | src)) * 1024u + (size_t)((k0 & 1023) + ch * 8);
            pa = A;
        } else {  // A_CONCAT
            pa = (k0 < 1024) ? A : A2;
            aoff = (size_t)(bm + r) * 1024u + (size_t)((k0 & 1023) + ch * 8);
        }
        cp16(buf + TH_A + sw, pa + aoff);

        const size_t boff = (size_t)(bn + r) * (size_t)K + (size_t)(k0 + ch * 8);
        cp16(buf + TH_B + sw, B + boff);
    }
}

static __device__ __forceinline__ void ldfragh(
    uint32_t buf, int kk, int wm, int wn,
    int a_row, int a_kb, int b_row, int b_kb,
    uint32_t (*af)[4], uint32_t (*bf)[2])
{
#pragma unroll
    for (int p = 0; p < 2; p++) {
        const uint32_t bo = (uint32_t)((wn + p * 16 + b_row) * 128 + kk * 32 + b_kb);
        const uint32_t sw = bo ^ ((bo >> 3) & 0x70);
        ldm4(bf[2*p][0], bf[2*p][1], bf[2*p+1][0], bf[2*p+1][1], buf + TH_B + sw);
    }
#pragma unroll
    for (int mt = 0; mt < 4; mt++) {
        const uint32_t bo = (uint32_t)((wm + mt * 16 + a_row) * 128 + kk * 32 + a_kb);
        const uint32_t sw = bo ^ ((bo >> 3) & 0x70);
        ldm4(af[mt][0], af[mt][1], af[mt][2], af[mt][3], buf + TH_A + sw);
    }
}

template <int ASRC, int EPI>
__global__ __launch_bounds__(256, 1)
void mmh_k(const __half* __restrict__ A, const __half* __restrict__ A2,
           const __half* __restrict__ B,
           const float* __restrict__ bias, int K,
           __nv_bfloat16* __restrict__ Oh, __nv_bfloat16* __restrict__ Ol,
           float* __restrict__ Of)
{
    extern __shared__ char smraw[];
    const uint32_t bufbase = (s2u(smraw) + 1023u) & ~1023u;
    const int tid = threadIdx.x, wid = tid >> 5, lane = tid & 31;
    const int bn = blockIdx.x * 128, bm = blockIdx.y * 128;
    const int wm = (wid >> 2) * 64, wn = (wid & 3) * 32;

    float acc[4][4][4];
#pragma unroll
    for (int mt = 0; mt < 4; mt++)
#pragma unroll
        for (int nt = 0; nt < 4; nt++)
#pragma unroll
            for (int r = 0; r < 4; r++) acc[mt][nt][r] = 0.0f;

    const int nst = K >> 6;

    loadh_stage<ASRC>(bufbase,              A, A2, B, K, 0,  bm, bn, tid);
    cp_commit();
    loadh_stage<ASRC>(bufbase + STGH_BYTES, A, A2, B, K, 64, bm, bn, tid);
    cp_commit();

    const int a_row = lane & 15;
    const int a_kb  = ((lane >> 4) & 1) * 16;
    const int b_row = (lane & 7) + ((lane >> 4) & 1) * 8;
    const int b_kb  = ((lane >> 3) & 1) * 16;

    uint32_t af[2][4][4], bf[2][4][2];

    for (int s = 0; s < nst; s++) {
        if (s < nst - 1) asm volatile("cp.async.wait_group 1;" ::: "memory");
        else             asm volatile("cp.async.wait_group 0;" ::: "memory");
        __syncthreads();

        const uint32_t buf = bufbase + (uint32_t)(s % 3) * STGH_BYTES;

        ldfragh(buf, 0, wm, wn, a_row, a_kb, b_row, b_kb, af[0], bf[0]);
#pragma unroll
        for (int kk = 0; kk < 4; kk++) {
            const int cur = kk & 1, nxt = cur ^ 1;
            if (kk < 3)
                ldfragh(buf, kk + 1, wm, wn, a_row, a_kb, b_row, b_kb, af[nxt], bf[nxt]);
#pragma unroll
            for (int mt = 0; mt < 4; mt++)
#pragma unroll
                for (int nt = 0; nt < 4; nt++)
                    mma16816h(acc[mt][nt], af[cur][mt], bf[cur][nt]);
        }

        if (s + 2 < nst) {
            loadh_stage<ASRC>(bufbase + (uint32_t)((s + 2) % 3) * STGH_BYTES,
                              A, A2, B, K, (s + 2) * 64, bm, bn, tid);
            cp_commit();
        }
    }

    const int qr = lane >> 2;
    const int qc = (lane & 3) * 2;
#pragma unroll
    for (int mt = 0; mt < 4; mt++) {
#pragma unroll
        for (int nt = 0; nt < 4; nt++) {
            const int col = bn + wn + nt * 8 + qc;
            const float2 bs = *(const float2*)(bias + col);
#pragma unroll
            for (int h = 0; h < 2; h++) {
                const int row = bm + wm + mt * 16 + qr + h * 8;
                const size_t off = (size_t)row * 1024u + (size_t)col;
                float v0 = acc[mt][nt][2*h]     + bs.x;
                float v1 = acc[mt][nt][2*h + 1] + bs.y;
                if (EPI == EP_GELU_BF) {
                    v0 = gelu_exact(v0);  v1 = gelu_exact(v1);
                    __nv_bfloat162 hh, ll;
                    split_bf(v0, hh.x, ll.x);  split_bf(v1, hh.y, ll.y);
                    *(__nv_bfloat162*)(Oh + off) = hh;
                    *(__nv_bfloat162*)(Ol + off) = ll;
                } else {  // EP_SIG
                    v0 = 1.0f / (1.0f + expf(-v0));
                    v1 = 1.0f / (1.0f + expf(-v1));
                    *(float2*)(Of + off) = make_float2(v0, v1);
                }
            }
        }
    }
}

// ---------------- conversions ----------------
__global__ void qhconv_k(const float* __restrict__ Q, __half* __restrict__ H, int n)
{
    for (int i = blockIdx.x * 256 + threadIdx.x; i * 4 < n; i += gridDim.x * 256) {
        const float4 a = *(const float4*)(Q + i * 4);
        __half2 h0 = __floats2half2_rn(a.x, a.y);
        __half2 h1 = __floats2half2_rn(a.z, a.w);
        uint2 v;
        v.x = *(uint32_t*)&h0;  v.y = *(uint32_t*)&h1;
        *(uint2*)(H + i * 4) = v;
    }
}

// transpose-convert W [K,1024] f32 -> [1024,K] fp16
__global__ void whconv_k(const float* __restrict__ W, __half* __restrict__ T, int K)
{
    __shared__ float t[32 * 33];
    const int n0 = blockIdx.x * 32, k0 = blockIdx.y * 32;
    const int tx = threadIdx.x, ty = threadIdx.y;
#pragma unroll
    for (int i = 0; i < 4; i++)
        t[(ty + i * 8) * 33 + tx] = W[(size_t)(k0 + ty + i * 8) * 1024u + n0 + tx];
    __syncthreads();
#pragma unroll
    for (int i = 0; i < 4; i++) {
        const size_t o = (size_t)(n0 + ty + i * 8) * (size_t)K + k0 + tx;
        T[o] = __float2half_rn(t[tx * 33 + ty + i * 8]);
    }
}

// transpose-convert W [K,N] f32 -> Th/Tl [N,K] bf16 hi/lo
static __device__ __forceinline__ void wconv_body(
    const float* __restrict__ W, __nv_bfloat16* __restrict__ Th,
    __nv_bfloat16* __restrict__ Tl, int K, int N, float* t)
{
    const int n0 = blockIdx.x * 32, k0 = blockIdx.y * 32;
    const int tx = threadIdx.x, ty = threadIdx.y;
#pragma unroll
    for (int i = 0; i < 4; i++)
        t[(ty + i * 8) * 33 + tx] = W[(size_t)(k0 + ty + i * 8) * N + n0 + tx];
    __syncthreads();
#pragma unroll
    for (int i = 0; i < 4; i++) {
        const float v = t[tx * 33 + ty + i * 8];
        __nv_bfloat16 h, l;
        split_bf(v, h, l);
        const size_t o = (size_t)(n0 + ty + i * 8) * K + k0 + tx;
        Th[o] = h;  Tl[o] = l;
    }
}

// 4 square weights in one launch: fr_w2, tc_w1, tc_w2, fc_w2 (all 1024x1024)
__global__ void wconv4_k(const float* W0, __nv_bfloat16* T0h, __nv_bfloat16* T0l,
                         const float* W1, __nv_bfloat16* T1h, __nv_bfloat16* T1l,
                         const float* W2, __nv_bfloat16* T2h, __nv_bfloat16* T2l,
                         const float* W3, __nv_bfloat16* T3h, __nv_bfloat16* T3l)
{
    __shared__ float t[32 * 33];
    const int z = blockIdx.z;
    if (z == 0)      wconv_body(W0, T0h, T0l, 1024, 1024, t);
    else if (z == 1) wconv_body(W1, T1h, T1l, 1024, 1024, t);
    else if (z == 2) wconv_body(W2, T2h, T2l, 1024, 1024, t);
    else             wconv_body(W3, T3h, T3l, 1024, 1024, t);
}

// ---------------- cluster softmax (emits fp16 weighted only) ---------------
__global__ __launch_bounds__(256)
void cluster_k(const float* __restrict__ tproj, const float* __restrict__ centers,
               __half* __restrict__ wtf)
{
    __shared__ float sc[4 * 1024];
    const int tid = threadIdx.x;
    for (int i = tid * 4; i < 4096; i += 256 * 4)
        *(float4*)&sc[i] = *(const float4*)&centers[i];
    __syncthreads();

    const int warp = tid >> 5, lane = tid & 31;
    const size_t row = (size_t)blockIdx.x * 8 + warp;
    const float* tp = tproj + row * 1024u;

    float d0 = 0.f, d1 = 0.f, d2 = 0.f, d3 = 0.f;
    for (int d = lane * 4; d < 1024; d += 128) {
        float4 t  = *(const float4*)(tp + d);
        float4 c0 = *(const float4*)(sc + d);
        float4 c1 = *(const float4*)(sc + 1024 + d);
        float4 c2 = *(const float4*)(sc + 2048 + d);
        float4 c3 = *(const float4*)(sc + 3072 + d);
        d0 += t.x*c0.x + t.y*c0.y + t.z*c0.z + t.w*c0.w;
        d1 += t.x*c1.x + t.y*c1.y + t.z*c1.z + t.w*c1.w;
        d2 += t.x*c2.x + t.y*c2.y + t.z*c2.z + t.w*c2.w;
        d3 += t.x*c3.x + t.y*c3.y + t.z*c3.z + t.w*c3.w;
    }
#pragma unroll
    for (int off = 16; off > 0; off >>= 1) {
        d0 += __shfl_xor_sync(0xffffffffu, d0, off);
        d1 += __shfl_xor_sync(0xffffffffu, d1, off);
        d2 += __shfl_xor_sync(0xffffffffu, d2, off);
        d3 += __shfl_xor_sync(0xffffffffu, d3, off);
    }
    const float mx = fmaxf(fmaxf(d0, d1), fmaxf(d2, d3));
    const float e0 = expf(d0 - mx), e1 = expf(d1 - mx),
                e2 = expf(d2 - mx), e3 = expf(d3 - mx);
    const float inv = 1.0f / (e0 + e1 + e2 + e3);
    const float w0 = e0*inv, w1 = e1*inv, w2 = e2*inv, w3 = e3*inv;

    for (int d = lane * 4; d < 1024; d += 128) {
        float4 c0 = *(const float4*)(sc + d);
        float4 c1 = *(const float4*)(sc + 1024 + d);
        float4 c2 = *(const float4*)(sc + 2048 + d);
        float4 c3 = *(const float4*)(sc + 3072 + d);
        float o0 = w0*c0.x + w1*c1.x + w2*c2.x + w3*c3.x;
        float o1 = w0*c0.y + w1*c1.y + w2*c2.y + w3*c3.y;
        float o2 = w0*c0.z + w1*c1.z + w2*c2.z + w3*c3.z;
        float o3 = w0*c0.w + w1*c1.w + w2*c2.w + w3*c3.w;
        __half2 p0 = __floats2half2_rn(o0, o1);
        __half2 p1 = __floats2half2_rn(o2, o3);
        uint2 v;
        v.x = *(uint32_t*)&p0;  v.y = *(uint32_t*)&p1;
        *(uint2*)(wtf + row * 1024u + d) = v;
    }
}

// ---------------- launch ----------------
extern "C" void kernel_launch(void* const* d_in, const int* in_sizes, int n_in,
                              void* d_out, int out_size)
{
    const float* queries = (const float*)d_in[0];
    const float* fr_w1   = (const float*)d_in[1];
    const float* fr_b1   = (const float*)d_in[2];
    const float* fr_w2   = (const float*)d_in[3];
    const float* fr_b2   = (const float*)d_in[4];
    const float* tc_w1   = (const float*)d_in[5];
    const float* tc_b1   = (const float*)d_in[6];
    const float* tc_w2   = (const float*)d_in[7];
    const float* tc_b2   = (const float*)d_in[8];
    const float* centers = (const float*)d_in[9];
    const float* fc_w1   = (const float*)d_in[10];
    const float* fc_b1   = (const float*)d_in[11];
    const float* fc_w2   = (const float*)d_in[12];
    const float* fc_b2   = (const float*)d_in[13];
    const float* g_w     = (const float*)d_in[14];
    const float* g_b     = (const float*)d_in[15];
    float* out = (float*)d_out;

#define SYM(p, s) { void* _t; cudaGetSymbolAddress(&_t, s); p = (decltype(p))_t; }
    __half *qf, *w1f, *fc1f, *gwf, *xrf16, *wtf;
    __nv_bfloat16 *h1h, *h1l, *xrh, *xrl, *t1h, *t1l, *hfh, *hfl;
    __nv_bfloat16 *w2th, *w2tl, *c1th, *c1tl, *c2th, *c2tl, *f2th, *f2tl;
    float *xrf, *tpf, *gtf;
    SYM(qf, g_qf);     SYM(w1f, g_w1f);
    SYM(fc1f, g_fc1f); SYM(gwf, g_gwf);
    SYM(xrf16, g_xrf16); SYM(wtf, g_wtf);
    SYM(h1h, g_h1h); SYM(h1l, g_h1l);
    SYM(xrh, g_xrh); SYM(xrl, g_xrl);
    SYM(t1h, g_t1h); SYM(t1l, g_t1l);
    SYM(hfh, g_hfh); SYM(hfl, g_hfl);
    SYM(xrf, g_xrf); SYM(tpf, g_tpf); SYM(gtf, g_gtf);
    SYM(w2th, g_w2th); SYM(w2tl, g_w2tl);
    SYM(c1th, g_c1th); SYM(c1tl, g_c1tl);
    SYM(c2th, g_c2th); SYM(c2tl, g_c2tl);
    SYM(f2th, g_f2th); SYM(f2tl, g_f2tl);
#undef SYM

    cudaFuncSetAttribute(mmh_k<A_ROLL,   EP_GELU_BF>, cudaFuncAttributeMaxDynamicSharedMemorySize, SMEM_DYN_H);
    cudaFuncSetAttribute(mmh_k<A_CONCAT, EP_SIG>,     cudaFuncAttributeMaxDynamicSharedMemorySize, SMEM_DYN_H);
    cudaFuncSetAttribute(mmh_k<A_CONCAT, EP_GELU_BF>, cudaFuncAttributeMaxDynamicSharedMemorySize, SMEM_DYN_H);
    cudaFuncSetAttribute(mm_k<EP_BF_F32>,  cudaFuncAttributeMaxDynamicSharedMemorySize, SMEM_DYN);
    cudaFuncSetAttribute(mm_k<EP_GELU_BF>, cudaFuncAttributeMaxDynamicSharedMemorySize, SMEM_DYN);
    cudaFuncSetAttribute(mm_k<EP_F32>,     cudaFuncAttributeMaxDynamicSharedMemorySize, SMEM_DYN);
    cudaFuncSetAttribute(mm_k<EP_FINAL>,   cudaFuncAttributeMaxDynamicSharedMemorySize, SMEM_DYN);

    dim3 wcb(32, 8);

    // ---- conversions ----
    qhconv_k<<<2048, 256>>>(queries, qf, (int)NELE);
    whconv_k<<<dim3(32, 224), wcb>>>(fr_w1, w1f, 7168);
    whconv_k<<<dim3(32, 64),  wcb>>>(fc_w1, fc1f, 2048);
    whconv_k<<<dim3(32, 64),  wcb>>>(g_w,   gwf,  2048);
    wconv4_k<<<dim3(32, 32, 4), wcb>>>(fr_w2, w2th, w2tl, tc_w1, c1th, c1tl,
                                       tc_w2, c2th, c2tl, fc_w2, f2th, f2tl);

    dim3 grid(8, 128), block(256);

    // mm1: h1 = gelu(fusion @ fr_w1 + fr_b1)   K=7168, fp16 roll-gathered
    mmh_k<A_ROLL, EP_GELU_BF><<<grid, block, SMEM_DYN_H>>>(
        qf, nullptr, w1f, fr_b1, 7168, h1h, h1l, nullptr);
    // mm2: x_ring = h1 @ fr_w2 + fr_b2   (bf16 split; emits bf16 h/l + f32 + fp16)
    mm_k<EP_BF_F32><<<grid, block, SMEM_DYN>>>(
        h1h, h1l, w2th, w2tl, fr_b2, 1024,
        xrh, xrl, xrf, xrf16, nullptr, nullptr);
    // mm3: t1 = gelu(x_ring @ tc_w1 + tc_b1)   (bf16 split)
    mm_k<EP_GELU_BF><<<grid, block, SMEM_DYN>>>(
        xrh, xrl, c1th, c1tl, tc_b1, 1024,
        t1h, t1l, nullptr, nullptr, nullptr, nullptr);
    // mm4: token_proj = t1 @ tc_w2 + tc_b2   (bf16 split)
    mm_k<EP_F32><<<grid, block, SMEM_DYN>>>(
        t1h, t1l, c2th, c2tl, tc_b2, 1024,
        nullptr, nullptr, tpf, nullptr, nullptr, nullptr);
    // mm5: weighted = softmax(tp @ centers^T) @ centers  (fp16 out)
    cluster_k<<<MT / 8, 256>>>(tpf, centers, wtf);
    // mm6: gate = sigmoid([xr|wt] @ g_w + g_b)   K=2048, fp16 single
    mmh_k<A_CONCAT, EP_SIG><<<grid, block, SMEM_DYN_H>>>(
        xrf16, wtf, gwf, g_b, 2048, nullptr, nullptr, gtf);
    // mm7: h_fc = gelu([xr|wt] @ fc_w1 + fc_b1)  K=2048, fp16 single
    mmh_k<A_CONCAT, EP_GELU_BF><<<grid, block, SMEM_DYN_H>>>(
        xrf16, wtf, fc1f, fc_b1, 2048, hfh, hfl, nullptr);
    // mm8: out = gate * (h_fc @ fc_w2 + fc_b2) + (1-gate) * x_ring  (bf16 split)
    mm_k<EP_FINAL><<<grid, block, SMEM_DYN>>>(
        hfh, hfl, f2th, f2tl, fc_b2, 1024,
        nullptr, nullptr, out, nullptr, gtf, xrf);
}

// round 10
// speedup vs baseline: 6.1825x; 1.2245x over previous
#include <cuda_runtime.h>
#include <cuda_bf16.h>
#include <cuda_fp16.h>
#include <cstdint>
#include <math.h>

// ---------------------------------------------------------------------------
// CenterRingFormerPlus: all GEMMs except mm2 via SINGLE fp16 HMMA per k=16.
// mm2 (x_ring, feeds everything incl. final mix) stays bf16 hi/lo 3-MMA.
// Error model (measured over R7-R9): ~3.5e-4/fp16 GEMM, strong downstream
// attenuation; deterministic inputs. 128x128 CTA tiles, 3-stage cp.async
// ring, SW128 swizzle, fused epilogues.
// ---------------------------------------------------------------------------

#define MT 16384
#define NT 1024
#define NELE (16384u * 1024u)

// ---- scratch (device globals; no allocation allowed) ----
__device__ __half g_qf[NELE];                        // queries fp16
__device__ __half g_w1f[1024u*7168u];                // fr_w1^T fp16 [N,K]
__device__ __half g_fc1f[1024u*2048u];               // fc_w1^T fp16
__device__ __half g_gwf[1024u*2048u];                // g_w^T fp16
__device__ __half g_c1f[1024u*1024u];                // tc_w1^T fp16
__device__ __half g_c2f[1024u*1024u];                // tc_w2^T fp16
__device__ __half g_f2f[1024u*1024u];                // fc_w2^T fp16
__device__ __half g_xrf16[NELE];                     // x_ring fp16
__device__ __half g_wtf[NELE];                       // weighted fp16
__device__ __half g_t1f[NELE];                       // t1 fp16
__device__ __half g_hff[NELE];                       // h_fc fp16
__device__ __nv_bfloat16 g_h1h[NELE], g_h1l[NELE];   // h1 bf16 hi/lo
__device__ float g_xrf[NELE];
__device__ float g_tpf[NELE];
__device__ float g_gtf[NELE];
__device__ __nv_bfloat16 g_w2th[1024u*1024u], g_w2tl[1024u*1024u];  // fr_w2^T

__constant__ int c_shifts[7] = {1, -1, 0, 2, -2, 4, -4};

enum { A_DIRECT = 0, A_ROLL = 1, A_CONCAT = 2 };
enum { EP_GELU_BF = 0, EP_F32_F16 = 1, EP_F32 = 2, EP_SIG = 3, EP_FINAL = 4,
       EP_GELU_F16 = 5 };

// ---------------- helpers ----------------
static __device__ __forceinline__ uint32_t s2u(const void* p) {
    return (uint32_t)__cvta_generic_to_shared(p);
}
static __device__ __forceinline__ void cp16(uint32_t d, const void* s) {
    asm volatile("cp.async.cg.shared.global [%0], [%1], 16;\n" :: "r"(d), "l"(s));
}
static __device__ __forceinline__ void cp_commit() {
    asm volatile("cp.async.commit_group;\n" ::: "memory");
}
static __device__ __forceinline__ void ldm4(uint32_t& r0, uint32_t& r1,
                                            uint32_t& r2, uint32_t& r3, uint32_t a) {
    asm volatile("ldmatrix.sync.aligned.m8n8.x4.shared.b16 {%0,%1,%2,%3}, [%4];"
                 : "=r"(r0), "=r"(r1), "=r"(r2), "=r"(r3) : "r"(a));
}
static __device__ __forceinline__ void mma16816(float* d, const uint32_t* a,
                                                const uint32_t* b) {
    asm volatile(
        "mma.sync.aligned.m16n8k16.row.col.f32.bf16.bf16.f32 "
        "{%0,%1,%2,%3}, {%4,%5,%6,%7}, {%8,%9}, {%0,%1,%2,%3};"
        : "+f"(d[0]), "+f"(d[1]), "+f"(d[2]), "+f"(d[3])
        : "r"(a[0]), "r"(a[1]), "r"(a[2]), "r"(a[3]), "r"(b[0]), "r"(b[1]));
}
static __device__ __forceinline__ void mma16816h(float* d, const uint32_t* a,
                                                 const uint32_t* b) {
    asm volatile(
        "mma.sync.aligned.m16n8k16.row.col.f32.f16.f16.f32 "
        "{%0,%1,%2,%3}, {%4,%5,%6,%7}, {%8,%9}, {%0,%1,%2,%3};"
        : "+f"(d[0]), "+f"(d[1]), "+f"(d[2]), "+f"(d[3])
        : "r"(a[0]), "r"(a[1]), "r"(a[2]), "r"(a[3]), "r"(b[0]), "r"(b[1]));
}
static __device__ __forceinline__ float gelu_exact(float x) {
    return 0.5f * x * (1.0f + erff(x * 0.7071067811865476f));
}
static __device__ __forceinline__ void split_bf(float v, __nv_bfloat16& h, __nv_bfloat16& l) {
    h = __float2bfloat16(v);
    l = __float2bfloat16(v - __bfloat162float(h));
}

// ---------------- bf16 tile loader (mm2 only) ----------------
#define STG_BYTES 65536
#define T_AH 0
#define T_AL 16384
#define T_BH 32768
#define T_BL 49152

static __device__ __forceinline__ void load_stage(
    uint32_t buf,
    const __nv_bfloat16* __restrict__ Ah, const __nv_bfloat16* __restrict__ Al,
    const __nv_bfloat16* __restrict__ Bh, const __nv_bfloat16* __restrict__ Bl,
    int K, int k0, int bm, int bn, int tid)
{
#pragma unroll
    for (int i = 0; i < 4; i++) {
        const int c = tid + i * 256;
        const int r = c >> 3, ch = c & 7;
        const uint32_t bo = (uint32_t)(r * 128 + ch * 16);
        const uint32_t sw = bo ^ ((bo >> 3) & 0x70);
        const size_t aoff = (size_t)(bm + r) * (size_t)K + (size_t)(k0 + ch * 8);
        cp16(buf + T_AH + sw, Ah + aoff);
        cp16(buf + T_AL + sw, Al + aoff);
        const size_t boff = (size_t)(bn + r) * (size_t)K + (size_t)(k0 + ch * 8);
        cp16(buf + T_BH + sw, Bh + boff);
        cp16(buf + T_BL + sw, Bl + boff);
    }
}

static __device__ __forceinline__ void ldfrag(
    uint32_t buf, int kk, int wm, int wn,
    int a_row, int a_kb, int b_row, int b_kb,
    uint32_t (*ah)[4], uint32_t (*al)[4], uint32_t (*bh)[2], uint32_t (*bl)[2])
{
#pragma unroll
    for (int p = 0; p < 2; p++) {
        const uint32_t bo = (uint32_t)((wn + p * 16 + b_row) * 128 + kk * 32 + b_kb);
        const uint32_t sw = bo ^ ((bo >> 3) & 0x70);
        ldm4(bh[2*p][0], bh[2*p][1], bh[2*p+1][0], bh[2*p+1][1], buf + T_BH + sw);
        ldm4(bl[2*p][0], bl[2*p][1], bl[2*p+1][0], bl[2*p+1][1], buf + T_BL + sw);
    }
#pragma unroll
    for (int mt = 0; mt < 4; mt++) {
        const uint32_t bo = (uint32_t)((wm + mt * 16 + a_row) * 128 + kk * 32 + a_kb);
        const uint32_t sw = bo ^ ((bo >> 3) & 0x70);
        ldm4(ah[mt][0], ah[mt][1], ah[mt][2], ah[mt][3], buf + T_AH + sw);
        ldm4(al[mt][0], al[mt][1], al[mt][2], al[mt][3], buf + T_AL + sw);
    }
}

// ---------------- bf16 GEMM kernel (mm2 only: h1 @ fr_w2) ----------------
#define SMEM_DYN (1024 + 3 * STG_BYTES)

__global__ __launch_bounds__(256, 1)
void mm_k(const __nv_bfloat16* __restrict__ Ah, const __nv_bfloat16* __restrict__ Al,
          const __nv_bfloat16* __restrict__ Bth, const __nv_bfloat16* __restrict__ Btl,
          const float* __restrict__ bias, int K,
          float* __restrict__ Of, __half* __restrict__ Oh16)
{
    extern __shared__ char smraw[];
    const uint32_t bufbase = (s2u(smraw) + 1023u) & ~1023u;
    const int tid = threadIdx.x, wid = tid >> 5, lane = tid & 31;
    const int bn = blockIdx.x * 128, bm = blockIdx.y * 128;
    const int wm = (wid >> 2) * 64, wn = (wid & 3) * 32;

    float acc[4][4][4];
#pragma unroll
    for (int mt = 0; mt < 4; mt++)
#pragma unroll
        for (int nt = 0; nt < 4; nt++)
#pragma unroll
            for (int r = 0; r < 4; r++) acc[mt][nt][r] = 0.0f;

    const int nst = K >> 6;

    load_stage(bufbase,             Ah, Al, Bth, Btl, K, 0,  bm, bn, tid);
    cp_commit();
    load_stage(bufbase + STG_BYTES, Ah, Al, Bth, Btl, K, 64, bm, bn, tid);
    cp_commit();

    const int a_row = lane & 15;
    const int a_kb  = ((lane >> 4) & 1) * 16;
    const int b_row = (lane & 7) + ((lane >> 4) & 1) * 8;
    const int b_kb  = ((lane >> 3) & 1) * 16;

    uint32_t ah[2][4][4], al[2][4][4], bh[2][4][2], bl[2][4][2];

    for (int s = 0; s < nst; s++) {
        if (s < nst - 1) asm volatile("cp.async.wait_group 1;" ::: "memory");
        else             asm volatile("cp.async.wait_group 0;" ::: "memory");
        __syncthreads();

        const uint32_t buf = bufbase + (uint32_t)(s % 3) * STG_BYTES;

        ldfrag(buf, 0, wm, wn, a_row, a_kb, b_row, b_kb, ah[0], al[0], bh[0], bl[0]);
#pragma unroll
        for (int kk = 0; kk < 4; kk++) {
            const int cur = kk & 1, nxt = cur ^ 1;
#pragma unroll
            for (int mt = 0; mt < 4; mt++)
#pragma unroll
                for (int nt = 0; nt < 4; nt++)
                    mma16816(acc[mt][nt], ah[cur][mt], bh[cur][nt]);
            if (kk < 3)
                ldfrag(buf, kk + 1, wm, wn, a_row, a_kb, b_row, b_kb,
                       ah[nxt], al[nxt], bh[nxt], bl[nxt]);
#pragma unroll
            for (int mt = 0; mt < 4; mt++)
#pragma unroll
                for (int nt = 0; nt < 4; nt++)
                    mma16816(acc[mt][nt], ah[cur][mt], bl[cur][nt]);
#pragma unroll
            for (int mt = 0; mt < 4; mt++)
#pragma unroll
                for (int nt = 0; nt < 4; nt++)
                    mma16816(acc[mt][nt], al[cur][mt], bh[cur][nt]);
        }

        if (s + 2 < nst) {
            load_stage(bufbase + (uint32_t)((s + 2) % 3) * STG_BYTES,
                       Ah, Al, Bth, Btl, K, (s + 2) * 64, bm, bn, tid);
            cp_commit();
        }
    }

    const int qr = lane >> 2;
    const int qc = (lane & 3) * 2;
#pragma unroll
    for (int mt = 0; mt < 4; mt++) {
#pragma unroll
        for (int nt = 0; nt < 4; nt++) {
            const int col = bn + wn + nt * 8 + qc;
            const float2 bs = *(const float2*)(bias + col);
#pragma unroll
            for (int h = 0; h < 2; h++) {
                const int row = bm + wm + mt * 16 + qr + h * 8;
                const size_t off = (size_t)row * 1024u + (size_t)col;
                const float v0 = acc[mt][nt][2*h]     + bs.x;
                const float v1 = acc[mt][nt][2*h + 1] + bs.y;
                *(float2*)(Of + off) = make_float2(v0, v1);
                *(__half2*)(Oh16 + off) = __floats2half2_rn(v0, v1);
            }
        }
    }
}

// ---------------- fp16 single-MMA GEMM kernel (mm1,3,4,6,7,8) --------------
#define STGH_BYTES 32768
#define TH_A 0
#define TH_B 16384
#define SMEM_DYN_H (1024 + 3 * STGH_BYTES)

template <int ASRC>
static __device__ __forceinline__ void loadh_stage(
    uint32_t buf, const __half* __restrict__ A, const __half* __restrict__ A2,
    const __half* __restrict__ B, int K, int k0, int bm, int bn, int tid)
{
#pragma unroll
    for (int i = 0; i < 4; i++) {
        const int c = tid + i * 256;
        const int r = c >> 3, ch = c & 7;
        const uint32_t bo = (uint32_t)(r * 128 + ch * 16);
        const uint32_t sw = bo ^ ((bo >> 3) & 0x70);

        const __half* pa;
        size_t aoff;
        if (ASRC == A_ROLL) {
            const int sh = c_shifts[k0 >> 10];
            const int m = bm + r, bb = m >> 11, nn = m & 2047;
            const int src = (nn - sh) & 2047;
            aoff = ((size_t)((bb << 11) | src)) * 1024u + (size_t)((k0 & 1023) + ch * 8);
            pa = A;
        } else if (ASRC == A_CONCAT) {
            pa = (k0 < 1024) ? A : A2;
            aoff = (size_t)(bm + r) * 1024u + (size_t)((k0 & 1023) + ch * 8);
        } else {  // A_DIRECT
            pa = A;
            aoff = (size_t)(bm + r) * (size_t)K + (size_t)(k0 + ch * 8);
        }
        cp16(buf + TH_A + sw, pa + aoff);

        const size_t boff = (size_t)(bn + r) * (size_t)K + (size_t)(k0 + ch * 8);
        cp16(buf + TH_B + sw, B + boff);
    }
}

static __device__ __forceinline__ void ldfragh(
    uint32_t buf, int kk, int wm, int wn,
    int a_row, int a_kb, int b_row, int b_kb,
    uint32_t (*af)[4], uint32_t (*bf)[2])
{
#pragma unroll
    for (int p = 0; p < 2; p++) {
        const uint32_t bo = (uint32_t)((wn + p * 16 + b_row) * 128 + kk * 32 + b_kb);
        const uint32_t sw = bo ^ ((bo >> 3) & 0x70);
        ldm4(bf[2*p][0], bf[2*p][1], bf[2*p+1][0], bf[2*p+1][1], buf + TH_B + sw);
    }
#pragma unroll
    for (int mt = 0; mt < 4; mt++) {
        const uint32_t bo = (uint32_t)((wm + mt * 16 + a_row) * 128 + kk * 32 + a_kb);
        const uint32_t sw = bo ^ ((bo >> 3) & 0x70);
        ldm4(af[mt][0], af[mt][1], af[mt][2], af[mt][3], buf + TH_A + sw);
    }
}

template <int ASRC, int EPI>
__global__ __launch_bounds__(256, 1)
void mmh_k(const __half* __restrict__ A, const __half* __restrict__ A2,
           const __half* __restrict__ B,
           const float* __restrict__ bias, int K,
           __nv_bfloat16* __restrict__ Oh, __nv_bfloat16* __restrict__ Ol,
           float* __restrict__ Of, __half* __restrict__ Oh16,
           const float* __restrict__ e_gate, const float* __restrict__ e_xr)
{
    extern __shared__ char smraw[];
    const uint32_t bufbase = (s2u(smraw) + 1023u) & ~1023u;
    const int tid = threadIdx.x, wid = tid >> 5, lane = tid & 31;
    const int bn = blockIdx.x * 128, bm = blockIdx.y * 128;
    const int wm = (wid >> 2) * 64, wn = (wid & 3) * 32;

    float acc[4][4][4];
#pragma unroll
    for (int mt = 0; mt < 4; mt++)
#pragma unroll
        for (int nt = 0; nt < 4; nt++)
#pragma unroll
            for (int r = 0; r < 4; r++) acc[mt][nt][r] = 0.0f;

    const int nst = K >> 6;

    loadh_stage<ASRC>(bufbase,              A, A2, B, K, 0,  bm, bn, tid);
    cp_commit();
    loadh_stage<ASRC>(bufbase + STGH_BYTES, A, A2, B, K, 64, bm, bn, tid);
    cp_commit();

    const int a_row = lane & 15;
    const int a_kb  = ((lane >> 4) & 1) * 16;
    const int b_row = (lane & 7) + ((lane >> 4) & 1) * 8;
    const int b_kb  = ((lane >> 3) & 1) * 16;

    uint32_t af[2][4][4], bf[2][4][2];

    for (int s = 0; s < nst; s++) {
        if (s < nst - 1) asm volatile("cp.async.wait_group 1;" ::: "memory");
        else             asm volatile("cp.async.wait_group 0;" ::: "memory");
        __syncthreads();

        const uint32_t buf = bufbase + (uint32_t)(s % 3) * STGH_BYTES;

        ldfragh(buf, 0, wm, wn, a_row, a_kb, b_row, b_kb, af[0], bf[0]);
#pragma unroll
        for (int kk = 0; kk < 4; kk++) {
            const int cur = kk & 1, nxt = cur ^ 1;
            if (kk < 3)
                ldfragh(buf, kk + 1, wm, wn, a_row, a_kb, b_row, b_kb, af[nxt], bf[nxt]);
#pragma unroll
            for (int mt = 0; mt < 4; mt++)
#pragma unroll
                for (int nt = 0; nt < 4; nt++)
                    mma16816h(acc[mt][nt], af[cur][mt], bf[cur][nt]);
        }

        if (s + 2 < nst) {
            loadh_stage<ASRC>(bufbase + (uint32_t)((s + 2) % 3) * STGH_BYTES,
                              A, A2, B, K, (s + 2) * 64, bm, bn, tid);
            cp_commit();
        }
    }

    const int qr = lane >> 2;
    const int qc = (lane & 3) * 2;
#pragma unroll
    for (int mt = 0; mt < 4; mt++) {
#pragma unroll
        for (int nt = 0; nt < 4; nt++) {
            const int col = bn + wn + nt * 8 + qc;
            const float2 bs = *(const float2*)(bias + col);
#pragma unroll
            for (int h = 0; h < 2; h++) {
                const int row = bm + wm + mt * 16 + qr + h * 8;
                const size_t off = (size_t)row * 1024u + (size_t)col;
                float v0 = acc[mt][nt][2*h]     + bs.x;
                float v1 = acc[mt][nt][2*h + 1] + bs.y;
                if (EPI == EP_GELU_BF) {
                    v0 = gelu_exact(v0);  v1 = gelu_exact(v1);
                    __nv_bfloat162 hh, ll;
                    split_bf(v0, hh.x, ll.x);  split_bf(v1, hh.y, ll.y);
                    *(__nv_bfloat162*)(Oh + off) = hh;
                    *(__nv_bfloat162*)(Ol + off) = ll;
                } else if (EPI == EP_GELU_F16) {
                    v0 = gelu_exact(v0);  v1 = gelu_exact(v1);
                    *(__half2*)(Oh16 + off) = __floats2half2_rn(v0, v1);
                } else if (EPI == EP_F32) {
                    *(float2*)(Of + off) = make_float2(v0, v1);
                } else if (EPI == EP_SIG) {
                    v0 = 1.0f / (1.0f + expf(-v0));
                    v1 = 1.0f / (1.0f + expf(-v1));
                    *(float2*)(Of + off) = make_float2(v0, v1);
                } else {  // EP_FINAL
                    const float2 g = *(const float2*)(e_gate + off);
                    const float2 x = *(const float2*)(e_xr + off);
                    *(float2*)(Of + off) = make_float2(
                        g.x * v0 + (1.0f - g.x) * x.x,
                        g.y * v1 + (1.0f - g.y) * x.y);
                }
            }
        }
    }
}

// ---------------- conversions ----------------
__global__ void qhconv_k(const float* __restrict__ Q, __half* __restrict__ H, int n)
{
    for (int i = blockIdx.x * 256 + threadIdx.x; i * 4 < n; i += gridDim.x * 256) {
        const float4 a = *(const float4*)(Q + i * 4);
        __half2 h0 = __floats2half2_rn(a.x, a.y);
        __half2 h1 = __floats2half2_rn(a.z, a.w);
        uint2 v;
        v.x = *(uint32_t*)&h0;  v.y = *(uint32_t*)&h1;
        *(uint2*)(H + i * 4) = v;
    }
}

// transpose-convert W [K,1024] f32 -> [1024,K] fp16
static __device__ __forceinline__ void whconv_body(
    const float* __restrict__ W, __half* __restrict__ T, int K, float* t)
{
    const int n0 = blockIdx.x * 32, k0 = blockIdx.y * 32;
    const int tx = threadIdx.x, ty = threadIdx.y;
#pragma unroll
    for (int i = 0; i < 4; i++)
        t[(ty + i * 8) * 33 + tx] = W[(size_t)(k0 + ty + i * 8) * 1024u + n0 + tx];
    __syncthreads();
#pragma unroll
    for (int i = 0; i < 4; i++) {
        const size_t o = (size_t)(n0 + ty + i * 8) * (size_t)K + k0 + tx;
        T[o] = __float2half_rn(t[tx * 33 + ty + i * 8]);
    }
}

__global__ void whconv_k(const float* __restrict__ W, __half* __restrict__ T, int K)
{
    __shared__ float t[32 * 33];
    whconv_body(W, T, K, t);
}

// 3 square fp16 weights in one launch: tc_w1, tc_w2, fc_w2
__global__ void whconv3_k(const float* W0, __half* T0,
                          const float* W1, __half* T1,
                          const float* W2, __half* T2)
{
    __shared__ float t[32 * 33];
    const int z = blockIdx.z;
    if (z == 0)      whconv_body(W0, T0, 1024, t);
    else if (z == 1) whconv_body(W1, T1, 1024, t);
    else             whconv_body(W2, T2, 1024, t);
}

// fr_w2 [1024,1024] f32 -> bf16 hi/lo transposed
__global__ void wconv_k(const float* __restrict__ W, __nv_bfloat16* __restrict__ Th,
                        __nv_bfloat16* __restrict__ Tl)
{
    __shared__ float t[32 * 33];
    const int n0 = blockIdx.x * 32, k0 = blockIdx.y * 32;
    const int tx = threadIdx.x, ty = threadIdx.y;
#pragma unroll
    for (int i = 0; i < 4; i++)
        t[(ty + i * 8) * 33 + tx] = W[(size_t)(k0 + ty + i * 8) * 1024u + n0 + tx];
    __syncthreads();
#pragma unroll
    for (int i = 0; i < 4; i++) {
        const float v = t[tx * 33 + ty + i * 8];
        __nv_bfloat16 h, l;
        split_bf(v, h, l);
        const size_t o = (size_t)(n0 + ty + i * 8) * 1024u + k0 + tx;
        Th[o] = h;  Tl[o] = l;
    }
}

// ---------------- cluster softmax (fp16 weighted out) ----------------------
__global__ __launch_bounds__(256)
void cluster_k(const float* __restrict__ tproj, const float* __restrict__ centers,
               __half* __restrict__ wtf)
{
    __shared__ float sc[4 * 1024];
    const int tid = threadIdx.x;
    for (int i = tid * 4; i < 4096; i += 256 * 4)
        *(float4*)&sc[i] = *(const float4*)&centers[i];
    __syncthreads();

    const int warp = tid >> 5, lane = tid & 31;
    const size_t row = (size_t)blockIdx.x * 8 + warp;
    const float* tp = tproj + row * 1024u;

    float d0 = 0.f, d1 = 0.f, d2 = 0.f, d3 = 0.f;
    for (int d = lane * 4; d < 1024; d += 128) {
        float4 t  = *(const float4*)(tp + d);
        float4 c0 = *(const float4*)(sc + d);
        float4 c1 = *(const float4*)(sc + 1024 + d);
        float4 c2 = *(const float4*)(sc + 2048 + d);
        float4 c3 = *(const float4*)(sc + 3072 + d);
        d0 += t.x*c0.x + t.y*c0.y + t.z*c0.z + t.w*c0.w;
        d1 += t.x*c1.x + t.y*c1.y + t.z*c1.z + t.w*c1.w;
        d2 += t.x*c2.x + t.y*c2.y + t.z*c2.z + t.w*c2.w;
        d3 += t.x*c3.x + t.y*c3.y + t.z*c3.z + t.w*c3.w;
    }
#pragma unroll
    for (int off = 16; off > 0; off >>= 1) {
        d0 += __shfl_xor_sync(0xffffffffu, d0, off);
        d1 += __shfl_xor_sync(0xffffffffu, d1, off);
        d2 += __shfl_xor_sync(0xffffffffu, d2, off);
        d3 += __shfl_xor_sync(0xffffffffu, d3, off);
    }
    const float mx = fmaxf(fmaxf(d0, d1), fmaxf(d2, d3));
    const float e0 = expf(d0 - mx), e1 = expf(d1 - mx),
                e2 = expf(d2 - mx), e3 = expf(d3 - mx);
    const float inv = 1.0f / (e0 + e1 + e2 + e3);
    const float w0 = e0*inv, w1 = e1*inv, w2 = e2*inv, w3 = e3*inv;

    for (int d = lane * 4; d < 1024; d += 128) {
        float4 c0 = *(const float4*)(sc + d);
        float4 c1 = *(const float4*)(sc + 1024 + d);
        float4 c2 = *(const float4*)(sc + 2048 + d);
        float4 c3 = *(const float4*)(sc + 3072 + d);
        float o0 = w0*c0.x + w1*c1.x + w2*c2.x + w3*c3.x;
        float o1 = w0*c0.y + w1*c1.y + w2*c2.y + w3*c3.y;
        float o2 = w0*c0.z + w1*c1.z + w2*c2.z + w3*c3.z;
        float o3 = w0*c0.w + w1*c1.w + w2*c2.w + w3*c3.w;
        __half2 p0 = __floats2half2_rn(o0, o1);
        __half2 p1 = __floats2half2_rn(o2, o3);
        uint2 v;
        v.x = *(uint32_t*)&p0;  v.y = *(uint32_t*)&p1;
        *(uint2*)(wtf + row * 1024u + d) = v;
    }
}

// ---------------- launch ----------------
extern "C" void kernel_launch(void* const* d_in, const int* in_sizes, int n_in,
                              void* d_out, int out_size)
{
    const float* queries = (const float*)d_in[0];
    const float* fr_w1   = (const float*)d_in[1];
    const float* fr_b1   = (const float*)d_in[2];
    const float* fr_w2   = (const float*)d_in[3];
    const float* fr_b2   = (const float*)d_in[4];
    const float* tc_w1   = (const float*)d_in[5];
    const float* tc_b1   = (const float*)d_in[6];
    const float* tc_w2   = (const float*)d_in[7];
    const float* tc_b2   = (const float*)d_in[8];
    const float* centers = (const float*)d_in[9];
    const float* fc_w1   = (const float*)d_in[10];
    const float* fc_b1   = (const float*)d_in[11];
    const float* fc_w2   = (const float*)d_in[12];
    const float* fc_b2   = (const float*)d_in[13];
    const float* g_w     = (const float*)d_in[14];
    const float* g_b     = (const float*)d_in[15];
    float* out = (float*)d_out;

#define SYM(p, s) { void* _t; cudaGetSymbolAddress(&_t, s); p = (decltype(p))_t; }
    __half *qf, *w1f, *fc1f, *gwf, *c1f, *c2f, *f2f;
    __half *xrf16, *wtf, *t1f, *hff;
    __nv_bfloat16 *h1h, *h1l, *w2th, *w2tl;
    float *xrf, *tpf, *gtf;
    SYM(qf, g_qf);     SYM(w1f, g_w1f);
    SYM(fc1f, g_fc1f); SYM(gwf, g_gwf);
    SYM(c1f, g_c1f);   SYM(c2f, g_c2f);   SYM(f2f, g_f2f);
    SYM(xrf16, g_xrf16); SYM(wtf, g_wtf);
    SYM(t1f, g_t1f);   SYM(hff, g_hff);
    SYM(h1h, g_h1h);   SYM(h1l, g_h1l);
    SYM(w2th, g_w2th); SYM(w2tl, g_w2tl);
    SYM(xrf, g_xrf);   SYM(tpf, g_tpf);   SYM(gtf, g_gtf);
#undef SYM

    cudaFuncSetAttribute(mmh_k<A_ROLL,   EP_GELU_BF>,  cudaFuncAttributeMaxDynamicSharedMemorySize, SMEM_DYN_H);
    cudaFuncSetAttribute(mmh_k<A_DIRECT, EP_GELU_F16>, cudaFuncAttributeMaxDynamicSharedMemorySize, SMEM_DYN_H);
    cudaFuncSetAttribute(mmh_k<A_DIRECT, EP_F32>,      cudaFuncAttributeMaxDynamicSharedMemorySize, SMEM_DYN_H);
    cudaFuncSetAttribute(mmh_k<A_CONCAT, EP_SIG>,      cudaFuncAttributeMaxDynamicSharedMemorySize, SMEM_DYN_H);
    cudaFuncSetAttribute(mmh_k<A_CONCAT, EP_GELU_F16>, cudaFuncAttributeMaxDynamicSharedMemorySize, SMEM_DYN_H);
    cudaFuncSetAttribute(mmh_k<A_DIRECT, EP_FINAL>,    cudaFuncAttributeMaxDynamicSharedMemorySize, SMEM_DYN_H);
    cudaFuncSetAttribute(mm_k, cudaFuncAttributeMaxDynamicSharedMemorySize, SMEM_DYN);

    dim3 wcb(32, 8);

    // ---- conversions ----
    qhconv_k<<<2048, 256>>>(queries, qf, (int)NELE);
    whconv_k<<<dim3(32, 224), wcb>>>(fr_w1, w1f, 7168);
    whconv_k<<<dim3(32, 64),  wcb>>>(fc_w1, fc1f, 2048);
    whconv_k<<<dim3(32, 64),  wcb>>>(g_w,   gwf,  2048);
    whconv3_k<<<dim3(32, 32, 3), wcb>>>(tc_w1, c1f, tc_w2, c2f, fc_w2, f2f);
    wconv_k<<<dim3(32, 32), wcb>>>(fr_w2, w2th, w2tl);

    dim3 grid(8, 128), block(256);

    // mm1: h1 = gelu(fusion @ fr_w1 + fr_b1)   K=7168, fp16 roll, bf16 h/l out
    mmh_k<A_ROLL, EP_GELU_BF><<<grid, block, SMEM_DYN_H>>>(
        qf, nullptr, w1f, fr_b1, 7168, h1h, h1l, nullptr, nullptr, nullptr, nullptr);
    // mm2: x_ring = h1 @ fr_w2 + fr_b2   (bf16 split; f32 + fp16 out)
    mm_k<<<grid, block, SMEM_DYN>>>(h1h, h1l, w2th, w2tl, fr_b2, 1024, xrf, xrf16);
    // mm3: t1 = gelu(x_ring @ tc_w1 + tc_b1)   fp16 single -> fp16
    mmh_k<A_DIRECT, EP_GELU_F16><<<grid, block, SMEM_DYN_H>>>(
        xrf16, nullptr, c1f, tc_b1, 1024, nullptr, nullptr, nullptr, t1f, nullptr, nullptr);
    // mm4: token_proj = t1 @ tc_w2 + tc_b2   fp16 single -> f32
    mmh_k<A_DIRECT, EP_F32><<<grid, block, SMEM_DYN_H>>>(
        t1f, nullptr, c2f, tc_b2, 1024, nullptr, nullptr, tpf, nullptr, nullptr, nullptr);
    // mm5: weighted = softmax(tp @ centers^T) @ centers  (fp16 out)
    cluster_k<<<MT / 8, 256>>>(tpf, centers, wtf);
    // mm6: gate = sigmoid([xr|wt] @ g_w + g_b)   fp16 single -> f32
    mmh_k<A_CONCAT, EP_SIG><<<grid, block, SMEM_DYN_H>>>(
        xrf16, wtf, gwf, g_b, 2048, nullptr, nullptr, gtf, nullptr, nullptr, nullptr);
    // mm7: h_fc = gelu([xr|wt] @ fc_w1 + fc_b1)  fp16 single -> fp16
    mmh_k<A_CONCAT, EP_GELU_F16><<<grid, block, SMEM_DYN_H>>>(
        xrf16, wtf, fc1f, fc_b1, 2048, nullptr, nullptr, nullptr, hff, nullptr, nullptr);
    // mm8: out = gate * (h_fc @ fc_w2 + fc_b2) + (1-gate) * x_ring  fp16 single
    mmh_k<A_DIRECT, EP_FINAL><<<grid, block, SMEM_DYN_H>>>(
        hff, nullptr, f2f, fc_b2, 1024, nullptr, nullptr, out, nullptr, gtf, xrf);
}

// round 12
// speedup vs baseline: 7.9054x; 1.2787x over previous
#include <cuda_runtime.h>
#include <cuda_fp16.h>
#include <cstdint>
#include <math.h>

// ---------------------------------------------------------------------------
// CenterRingFormerPlus: ALL GEMMs via single fp16 HMMA per k=16.
// Error model (validated R7-R10): ~3.5e-4 per fp16 GEMM, quadrature with
// strong downstream attenuation, deterministic inputs => ~6e-4 < 1e-3.
// 128x128 CTA tiles, 2-stage cp.async ring, 2 CTAs/SM, SW128 swizzle,
// fused epilogues (gelu / sigmoid / final gate-mix).
// ---------------------------------------------------------------------------

#define MT 16384
#define NT 1024
#define NELE (16384u * 1024u)

// ---- scratch (device globals; no allocation allowed) ----
__device__ __half g_qf[NELE];                        // queries fp16
__device__ __half g_w1f[1024u*7168u];                // fr_w1^T fp16 [N,K]
__device__ __half g_fc1f[1024u*2048u];               // fc_w1^T fp16
__device__ __half g_gwf[1024u*2048u];                // g_w^T fp16
__device__ __half g_w2f[1024u*1024u];                // fr_w2^T fp16
__device__ __half g_c1f[1024u*1024u];                // tc_w1^T fp16
__device__ __half g_c2f[1024u*1024u];                // tc_w2^T fp16
__device__ __half g_f2f[1024u*1024u];                // fc_w2^T fp16
__device__ __half g_h1f[NELE];                       // h1 fp16
__device__ __half g_xrf16[NELE];                     // x_ring fp16
__device__ __half g_wtf[NELE];                       // weighted fp16
__device__ __half g_t1f[NELE];                       // t1 fp16
__device__ __half g_hff[NELE];                       // h_fc fp16
__device__ float g_xrf[NELE];                        // x_ring f32
__device__ float g_tpf[NELE];                        // token_proj f32
__device__ float g_gtf[NELE];                        // gate f32

__constant__ int c_shifts[7] = {1, -1, 0, 2, -2, 4, -4};

enum { A_DIRECT = 0, A_ROLL = 1, A_CONCAT = 2 };
enum { EP_GELU_F16 = 0, EP_F32_F16 = 1, EP_F32 = 2, EP_SIG = 3, EP_FINAL = 4 };

// ---------------- helpers ----------------
static __device__ __forceinline__ uint32_t s2u(const void* p) {
    return (uint32_t)__cvta_generic_to_shared(p);
}
static __device__ __forceinline__ void cp16(uint32_t d, const void* s) {
    asm volatile("cp.async.cg.shared.global [%0], [%1], 16;\n" :: "r"(d), "l"(s));
}
static __device__ __forceinline__ void cp_commit() {
    asm volatile("cp.async.commit_group;\n" ::: "memory");
}
static __device__ __forceinline__ void ldm4(uint32_t& r0, uint32_t& r1,
                                            uint32_t& r2, uint32_t& r3, uint32_t a) {
    asm volatile("ldmatrix.sync.aligned.m8n8.x4.shared.b16 {%0,%1,%2,%3}, [%4];"
                 : "=r"(r0), "=r"(r1), "=r"(r2), "=r"(r3) : "r"(a));
}
static __device__ __forceinline__ void mma16816h(float* d, const uint32_t* a,
                                                 const uint32_t* b) {
    asm volatile(
        "mma.sync.aligned.m16n8k16.row.col.f32.f16.f16.f32 "
        "{%0,%1,%2,%3}, {%4,%5,%6,%7}, {%8,%9}, {%0,%1,%2,%3};"
        : "+f"(d[0]), "+f"(d[1]), "+f"(d[2]), "+f"(d[3])
        : "r"(a[0]), "r"(a[1]), "r"(a[2]), "r"(a[3]), "r"(b[0]), "r"(b[1]));
}
static __device__ __forceinline__ float gelu_exact(float x) {
    return 0.5f * x * (1.0f + erff(x * 0.7071067811865476f));
}

// ---------------- fp16 tile loader (BK=64, SW128) ----------------
#define STGH_BYTES 32768
#define TH_A 0
#define TH_B 16384
#define SMEM_DYN_H (1024 + 2 * STGH_BYTES)

template <int ASRC>
static __device__ __forceinline__ void loadh_stage(
    uint32_t buf, const __half* __restrict__ A, const __half* __restrict__ A2,
    const __half* __restrict__ B, int K, int k0, int bm, int bn, int tid)
{
#pragma unroll
    for (int i = 0; i < 4; i++) {
        const int c = tid + i * 256;
        const int r = c >> 3, ch = c & 7;
        const uint32_t bo = (uint32_t)(r * 128 + ch * 16);
        const uint32_t sw = bo ^ ((bo >> 3) & 0x70);

        const __half* pa;
        size_t aoff;
        if (ASRC == A_ROLL) {
            const int sh = c_shifts[k0 >> 10];
            const int m = bm + r, bb = m >> 11, nn = m & 2047;
            const int src = (nn - sh) & 2047;
            aoff = ((size_t)((bb << 11) | src)) * 1024u + (size_t)((k0 & 1023) + ch * 8);
            pa = A;
        } else if (ASRC == A_CONCAT) {
            pa = (k0 < 1024) ? A : A2;
            aoff = (size_t)(bm + r) * 1024u + (size_t)((k0 & 1023) + ch * 8);
        } else {  // A_DIRECT
            pa = A;
            aoff = (size_t)(bm + r) * (size_t)K + (size_t)(k0 + ch * 8);
        }
        cp16(buf + TH_A + sw, pa + aoff);

        const size_t boff = (size_t)(bn + r) * (size_t)K + (size_t)(k0 + ch * 8);
        cp16(buf + TH_B + sw, B + boff);
    }
}

static __device__ __forceinline__ void ldfragh(
    uint32_t buf, int kk, int wm, int wn,
    int a_row, int a_kb, int b_row, int b_kb,
    uint32_t (*af)[4], uint32_t (*bf)[2])
{
#pragma unroll
    for (int p = 0; p < 2; p++) {
        const uint32_t bo = (uint32_t)((wn + p * 16 + b_row) * 128 + kk * 32 + b_kb);
        const uint32_t sw = bo ^ ((bo >> 3) & 0x70);
        ldm4(bf[2*p][0], bf[2*p][1], bf[2*p+1][0], bf[2*p+1][1], buf + TH_B + sw);
    }
#pragma unroll
    for (int mt = 0; mt < 4; mt++) {
        const uint32_t bo = (uint32_t)((wm + mt * 16 + a_row) * 128 + kk * 32 + a_kb);
        const uint32_t sw = bo ^ ((bo >> 3) & 0x70);
        ldm4(af[mt][0], af[mt][1], af[mt][2], af[mt][3], buf + TH_A + sw);
    }
}

// ---------------- fp16 single-MMA GEMM (all 7 dense GEMMs) ------------------
template <int ASRC, int EPI>
__global__ __launch_bounds__(256, 2)
void mmh_k(const __half* __restrict__ A, const __half* __restrict__ A2,
           const __half* __restrict__ B,
           const float* __restrict__ bias, int K,
           float* __restrict__ Of, __half* __restrict__ Oh16,
           const float* __restrict__ e_gate, const float* __restrict__ e_xr)
{
    extern __shared__ char smraw[];
    const uint32_t bufbase = (s2u(smraw) + 1023u) & ~1023u;
    const int tid = threadIdx.x, wid = tid >> 5, lane = tid & 31;
    const int bn = blockIdx.x * 128, bm = blockIdx.y * 128;
    const int wm = (wid >> 2) * 64, wn = (wid & 3) * 32;

    float acc[4][4][4];
#pragma unroll
    for (int mt = 0; mt < 4; mt++)
#pragma unroll
        for (int nt = 0; nt < 4; nt++)
#pragma unroll
            for (int r = 0; r < 4; r++) acc[mt][nt][r] = 0.0f;

    const int nst = K >> 6;

    // 2-stage ring: stages s and s+1 in flight
    loadh_stage<ASRC>(bufbase,              A, A2, B, K, 0,  bm, bn, tid);
    cp_commit();
    loadh_stage<ASRC>(bufbase + STGH_BYTES, A, A2, B, K, 64, bm, bn, tid);
    cp_commit();

    const int a_row = lane & 15;
    const int a_kb  = ((lane >> 4) & 1) * 16;
    const int b_row = (lane & 7) + ((lane >> 4) & 1) * 8;
    const int b_kb  = ((lane >> 3) & 1) * 16;

    uint32_t af[4][4], bf[4][2];

    for (int s = 0; s < nst; s++) {
        if (s < nst - 1) asm volatile("cp.async.wait_group 1;" ::: "memory");
        else             asm volatile("cp.async.wait_group 0;" ::: "memory");
        __syncthreads();   // stage s data visible to all warps

        const uint32_t buf = bufbase + (uint32_t)(s & 1) * STGH_BYTES;

#pragma unroll
        for (int kk = 0; kk < 4; kk++) {
            ldfragh(buf, kk, wm, wn, a_row, a_kb, b_row, b_kb, af, bf);
#pragma unroll
            for (int mt = 0; mt < 4; mt++)
#pragma unroll
                for (int nt = 0; nt < 4; nt++)
                    mma16816h(acc[mt][nt], af[mt], bf[nt]);
        }

        __syncthreads();   // all warps done reading buf before overwrite

        if (s + 2 < nst) {
            loadh_stage<ASRC>(bufbase + (uint32_t)(s & 1) * STGH_BYTES,
                              A, A2, B, K, (s + 2) * 64, bm, bn, tid);
            cp_commit();
        }
    }

    const int qr = lane >> 2;
    const int qc = (lane & 3) * 2;
#pragma unroll
    for (int mt = 0; mt < 4; mt++) {
#pragma unroll
        for (int nt = 0; nt < 4; nt++) {
            const int col = bn + wn + nt * 8 + qc;
            const float2 bs = *(const float2*)(bias + col);
#pragma unroll
            for (int h = 0; h < 2; h++) {
                const int row = bm + wm + mt * 16 + qr + h * 8;
                const size_t off = (size_t)row * 1024u + (size_t)col;
                float v0 = acc[mt][nt][2*h]     + bs.x;
                float v1 = acc[mt][nt][2*h + 1] + bs.y;
                if (EPI == EP_GELU_F16) {
                    v0 = gelu_exact(v0);  v1 = gelu_exact(v1);
                    *(__half2*)(Oh16 + off) = __floats2half2_rn(v0, v1);
                } else if (EPI == EP_F32_F16) {
                    *(float2*)(Of + off) = make_float2(v0, v1);
                    *(__half2*)(Oh16 + off) = __floats2half2_rn(v0, v1);
                } else if (EPI == EP_F32) {
                    *(float2*)(Of + off) = make_float2(v0, v1);
                } else if (EPI == EP_SIG) {
                    v0 = 1.0f / (1.0f + expf(-v0));
                    v1 = 1.0f / (1.0f + expf(-v1));
                    *(float2*)(Of + off) = make_float2(v0, v1);
                } else {  // EP_FINAL
                    const float2 g = *(const float2*)(e_gate + off);
                    const float2 x = *(const float2*)(e_xr + off);
                    *(float2*)(Of + off) = make_float2(
                        g.x * v0 + (1.0f - g.x) * x.x,
                        g.y * v1 + (1.0f - g.y) * x.y);
                }
            }
        }
    }
}

// ---------------- conversions ----------------
__global__ void qhconv_k(const float* __restrict__ Q, __half* __restrict__ H, int n)
{
    for (int i = blockIdx.x * 256 + threadIdx.x; i * 4 < n; i += gridDim.x * 256) {
        const float4 a = *(const float4*)(Q + i * 4);
        __half2 h0 = __floats2half2_rn(a.x, a.y);
        __half2 h1 = __floats2half2_rn(a.z, a.w);
        uint2 v;
        v.x = *(uint32_t*)&h0;  v.y = *(uint32_t*)&h1;
        *(uint2*)(H + i * 4) = v;
    }
}

// transpose-convert W [K,1024] f32 -> [1024,K] fp16
static __device__ __forceinline__ void whconv_body(
    const float* __restrict__ W, __half* __restrict__ T, int K, float* t)
{
    const int n0 = blockIdx.x * 32, k0 = blockIdx.y * 32;
    const int tx = threadIdx.x, ty = threadIdx.y;
#pragma unroll
    for (int i = 0; i < 4; i++)
        t[(ty + i * 8) * 33 + tx] = W[(size_t)(k0 + ty + i * 8) * 1024u + n0 + tx];
    __syncthreads();
#pragma unroll
    for (int i = 0; i < 4; i++) {
        const size_t o = (size_t)(n0 + ty + i * 8) * (size_t)K + k0 + tx;
        T[o] = __float2half_rn(t[tx * 33 + ty + i * 8]);
    }
}

__global__ void whconv_k(const float* __restrict__ W, __half* __restrict__ T, int K)
{
    __shared__ float t[32 * 33];
    whconv_body(W, T, K, t);
}

// 4 square fp16 weights in one launch: fr_w2, tc_w1, tc_w2, fc_w2
__global__ void whconv4_k(const float* W0, __half* T0, const float* W1, __half* T1,
                          const float* W2, __half* T2, const float* W3, __half* T3)
{
    __shared__ float t[32 * 33];
    const int z = blockIdx.z;
    if (z == 0)      whconv_body(W0, T0, 1024, t);
    else if (z == 1) whconv_body(W1, T1, 1024, t);
    else if (z == 2) whconv_body(W2, T2, 1024, t);
    else             whconv_body(W3, T3, 1024, t);
}

// ---------------- cluster softmax (fp16 weighted out) ----------------------
__global__ __launch_bounds__(256)
void cluster_k(const float* __restrict__ tproj, const float* __restrict__ centers,
               __half* __restrict__ wtf)
{
    __shared__ float sc[4 * 1024];
    const int tid = threadIdx.x;
    for (int i = tid * 4; i < 4096; i += 256 * 4)
        *(float4*)&sc[i] = *(const float4*)&centers[i];
    __syncthreads();

    const int warp = tid >> 5, lane = tid & 31;
    const size_t row = (size_t)blockIdx.x * 8 + warp;
    const float* tp = tproj + row * 1024u;

    float d0 = 0.f, d1 = 0.f, d2 = 0.f, d3 = 0.f;
    for (int d = lane * 4; d < 1024; d += 128) {
        float4 t  = *(const float4*)(tp + d);
        float4 c0 = *(const float4*)(sc + d);
        float4 c1 = *(const float4*)(sc + 1024 + d);
        float4 c2 = *(const float4*)(sc + 2048 + d);
        float4 c3 = *(const float4*)(sc + 3072 + d);
        d0 += t.x*c0.x + t.y*c0.y + t.z*c0.z + t.w*c0.w;
        d1 += t.x*c1.x + t.y*c1.y + t.z*c1.z + t.w*c1.w;
        d2 += t.x*c2.x + t.y*c2.y + t.z*c2.z + t.w*c2.w;
        d3 += t.x*c3.x + t.y*c3.y + t.z*c3.z + t.w*c3.w;
    }
#pragma unroll
    for (int off = 16; off > 0; off >>= 1) {
        d0 += __shfl_xor_sync(0xffffffffu, d0, off);
        d1 += __shfl_xor_sync(0xffffffffu, d1, off);
        d2 += __shfl_xor_sync(0xffffffffu, d2, off);
        d3 += __shfl_xor_sync(0xffffffffu, d3, off);
    }
    const float mx = fmaxf(fmaxf(d0, d1), fmaxf(d2, d3));
    const float e0 = expf(d0 - mx), e1 = expf(d1 - mx),
                e2 = expf(d2 - mx), e3 = expf(d3 - mx);
    const float inv = 1.0f / (e0 + e1 + e2 + e3);
    const float w0 = e0*inv, w1 = e1*inv, w2 = e2*inv, w3 = e3*inv;

    for (int d = lane * 4; d < 1024; d += 128) {
        float4 c0 = *(const float4*)(sc + d);
        float4 c1 = *(const float4*)(sc + 1024 + d);
        float4 c2 = *(const float4*)(sc + 2048 + d);
        float4 c3 = *(const float4*)(sc + 3072 + d);
        float o0 = w0*c0.x + w1*c1.x + w2*c2.x + w3*c3.x;
        float o1 = w0*c0.y + w1*c1.y + w2*c2.y + w3*c3.y;
        float o2 = w0*c0.z + w1*c1.z + w2*c2.z + w3*c3.z;
        float o3 = w0*c0.w + w1*c1.w + w2*c2.w + w3*c3.w;
        __half2 p0 = __floats2half2_rn(o0, o1);
        __half2 p1 = __floats2half2_rn(o2, o3);
        uint2 v;
        v.x = *(uint32_t*)&p0;  v.y = *(uint32_t*)&p1;
        *(uint2*)(wtf + row * 1024u + d) = v;
    }
}

// ---------------- launch ----------------
extern "C" void kernel_launch(void* const* d_in, const int* in_sizes, int n_in,
                              void* d_out, int out_size)
{
    const float* queries = (const float*)d_in[0];
    const float* fr_w1   = (const float*)d_in[1];
    const float* fr_b1   = (const float*)d_in[2];
    const float* fr_w2   = (const float*)d_in[3];
    const float* fr_b2   = (const float*)d_in[4];
    const float* tc_w1   = (const float*)d_in[5];
    const float* tc_b1   = (const float*)d_in[6];
    const float* tc_w2   = (const float*)d_in[7];
    const float* tc_b2   = (const float*)d_in[8];
    const float* centers = (const float*)d_in[9];
    const float* fc_w1   = (const float*)d_in[10];
    const float* fc_b1   = (const float*)d_in[11];
    const float* fc_w2   = (const float*)d_in[12];
    const float* fc_b2   = (const float*)d_in[13];
    const float* g_w     = (const float*)d_in[14];
    const float* g_b     = (const float*)d_in[15];
    float* out = (float*)d_out;

#define SYM(p, s) { void* _t; cudaGetSymbolAddress(&_t, s); p = (decltype(p))_t; }
    __half *qf, *w1f, *fc1f, *gwf, *w2f, *c1f, *c2f, *f2f;
    __half *h1f, *xrf16, *wtf, *t1f, *hff;
    float *xrf, *tpf, *gtf;
    SYM(qf, g_qf);     SYM(w1f, g_w1f);
    SYM(fc1f, g_fc1f); SYM(gwf, g_gwf);
    SYM(w2f, g_w2f);   SYM(c1f, g_c1f);
    SYM(c2f, g_c2f);   SYM(f2f, g_f2f);
    SYM(h1f, g_h1f);   SYM(xrf16, g_xrf16);
    SYM(wtf, g_wtf);   SYM(t1f, g_t1f);   SYM(hff, g_hff);
    SYM(xrf, g_xrf);   SYM(tpf, g_tpf);   SYM(gtf, g_gtf);
#undef SYM

    cudaFuncSetAttribute(mmh_k<A_ROLL,   EP_GELU_F16>, cudaFuncAttributeMaxDynamicSharedMemorySize, SMEM_DYN_H);
    cudaFuncSetAttribute(mmh_k<A_DIRECT, EP_F32_F16>,  cudaFuncAttributeMaxDynamicSharedMemorySize, SMEM_DYN_H);
    cudaFuncSetAttribute(mmh_k<A_DIRECT, EP_GELU_F16>, cudaFuncAttributeMaxDynamicSharedMemorySize, SMEM_DYN_H);
    cudaFuncSetAttribute(mmh_k<A_DIRECT, EP_F32>,      cudaFuncAttributeMaxDynamicSharedMemorySize, SMEM_DYN_H);
    cudaFuncSetAttribute(mmh_k<A_CONCAT, EP_SIG>,      cudaFuncAttributeMaxDynamicSharedMemorySize, SMEM_DYN_H);
    cudaFuncSetAttribute(mmh_k<A_CONCAT, EP_GELU_F16>, cudaFuncAttributeMaxDynamicSharedMemorySize, SMEM_DYN_H);
    cudaFuncSetAttribute(mmh_k<A_DIRECT, EP_FINAL>,    cudaFuncAttributeMaxDynamicSharedMemorySize, SMEM_DYN_H);

    dim3 wcb(32, 8);

    // ---- conversions ----
    qhconv_k<<<2048, 256>>>(queries, qf, (int)NELE);
    whconv_k<<<dim3(32, 224), wcb>>>(fr_w1, w1f, 7168);
    whconv_k<<<dim3(32, 64),  wcb>>>(fc_w1, fc1f, 2048);
    whconv_k<<<dim3(32, 64),  wcb>>>(g_w,   gwf,  2048);
    whconv4_k<<<dim3(32, 32, 4), wcb>>>(fr_w2, w2f, tc_w1, c1f, tc_w2, c2f, fc_w2, f2f);

    dim3 grid(8, 128), block(256);

    // mm1: h1 = gelu(fusion @ fr_w1 + fr_b1)   K=7168, roll-gathered
    mmh_k<A_ROLL, EP_GELU_F16><<<grid, block, SMEM_DYN_H>>>(
        qf, nullptr, w1f, fr_b1, 7168, nullptr, h1f, nullptr, nullptr);
    // mm2: x_ring = h1 @ fr_w2 + fr_b2   -> f32 + fp16
    mmh_k<A_DIRECT, EP_F32_F16><<<grid, block, SMEM_DYN_H>>>(
        h1f, nullptr, w2f, fr_b2, 1024, xrf, xrf16, nullptr, nullptr);
    // mm3: t1 = gelu(x_ring @ tc_w1 + tc_b1)   -> fp16
    mmh_k<A_DIRECT, EP_GELU_F16><<<grid, block, SMEM_DYN_H>>>(
        xrf16, nullptr, c1f, tc_b1, 1024, nullptr, t1f, nullptr, nullptr);
    // mm4: token_proj = t1 @ tc_w2 + tc_b2   -> f32
    mmh_k<A_DIRECT, EP_F32><<<grid, block, SMEM_DYN_H>>>(
        t1f, nullptr, c2f, tc_b2, 1024, tpf, nullptr, nullptr, nullptr);
    // mm5: weighted = softmax(tp @ centers^T) @ centers  -> fp16
    cluster_k<<<MT / 8, 256>>>(tpf, centers, wtf);
    // mm6: gate = sigmoid([xr|wt] @ g_w + g_b)   -> f32
    mmh_k<A_CONCAT, EP_SIG><<<grid, block, SMEM_DYN_H>>>(
        xrf16, wtf, gwf, g_b, 2048, gtf, nullptr, nullptr, nullptr);
    // mm7: h_fc = gelu([xr|wt] @ fc_w1 + fc_b1)  -> fp16
    mmh_k<A_CONCAT, EP_GELU_F16><<<grid, block, SMEM_DYN_H>>>(
        xrf16, wtf, fc1f, fc_b1, 2048, nullptr, hff, nullptr, nullptr);
    // mm8: out = gate * (h_fc @ fc_w2 + fc_b2) + (1-gate) * x_ring
    mmh_k<A_DIRECT, EP_FINAL><<<grid, block, SMEM_DYN_H>>>(
        hff, nullptr, f2f, fc_b2, 1024, out, nullptr, gtf, xrf);
}

// round 13
// speedup vs baseline: 8.3563x; 1.0570x over previous
#include <cuda_runtime.h>
#include <cuda_fp16.h>
#include <cstdint>
#include <math.h>

// ---------------------------------------------------------------------------
// CenterRingFormerPlus: ALL GEMMs via single fp16 HMMA per k=16.
// Error model (validated R7-R12): ~3.5e-4 per fp16 GEMM, quadrature with
// strong downstream attenuation, deterministic inputs => ~5.7e-4 < 1e-3.
// 128x128 CTA tiles, 3-stage cp.async ring (ONE sync/stage), 2 CTAs/SM,
// SW128 swizzle, fused epilogues; mm6+mm7 merged into one launch.
// ---------------------------------------------------------------------------

#define MT 16384
#define NT 1024
#define NELE (16384u * 1024u)

// ---- scratch (device globals; no allocation allowed) ----
__device__ __half g_qf[NELE];                        // queries fp16
__device__ __half g_w1f[1024u*7168u];                // fr_w1^T fp16 [N,K]
__device__ __half g_fc1f[1024u*2048u];               // fc_w1^T fp16
__device__ __half g_gwf[1024u*2048u];                // g_w^T fp16
__device__ __half g_w2f[1024u*1024u];                // fr_w2^T fp16
__device__ __half g_c1f[1024u*1024u];                // tc_w1^T fp16
__device__ __half g_c2f[1024u*1024u];                // tc_w2^T fp16
__device__ __half g_f2f[1024u*1024u];                // fc_w2^T fp16
__device__ __half g_h1f[NELE];                       // h1 fp16
__device__ __half g_xrf16[NELE];                     // x_ring fp16
__device__ __half g_wtf[NELE];                       // weighted fp16
__device__ __half g_t1f[NELE];                       // t1 fp16
__device__ __half g_hff[NELE];                       // h_fc fp16
__device__ float g_xrf[NELE];                        // x_ring f32
__device__ float g_tpf[NELE];                        // token_proj f32
__device__ float g_gtf[NELE];                        // gate f32

__constant__ int c_shifts[7] = {1, -1, 0, 2, -2, 4, -4};

enum { A_DIRECT = 0, A_ROLL = 1, A_CONCAT = 2 };
enum { EP_GELU_F16 = 0, EP_F32_F16 = 1, EP_F32 = 2, EP_SIG = 3, EP_FINAL = 4 };

// ---------------- helpers ----------------
static __device__ __forceinline__ uint32_t s2u(const void* p) {
    return (uint32_t)__cvta_generic_to_shared(p);
}
static __device__ __forceinline__ void cp16(uint32_t d, const void* s) {
    asm volatile("cp.async.cg.shared.global [%0], [%1], 16;\n" :: "r"(d), "l"(s));
}
static __device__ __forceinline__ void cp_commit() {
    asm volatile("cp.async.commit_group;\n" ::: "memory");
}
static __device__ __forceinline__ void ldm4(uint32_t& r0, uint32_t& r1,
                                            uint32_t& r2, uint32_t& r3, uint32_t a) {
    asm volatile("ldmatrix.sync.aligned.m8n8.x4.shared.b16 {%0,%1,%2,%3}, [%4];"
                 : "=r"(r0), "=r"(r1), "=r"(r2), "=r"(r3) : "r"(a));
}
static __device__ __forceinline__ void mma16816h(float* d, const uint32_t* a,
                                                 const uint32_t* b) {
    asm volatile(
        "mma.sync.aligned.m16n8k16.row.col.f32.f16.f16.f32 "
        "{%0,%1,%2,%3}, {%4,%5,%6,%7}, {%8,%9}, {%0,%1,%2,%3};"
        : "+f"(d[0]), "+f"(d[1]), "+f"(d[2]), "+f"(d[3])
        : "r"(a[0]), "r"(a[1]), "r"(a[2]), "r"(a[3]), "r"(b[0]), "r"(b[1]));
}
static __device__ __forceinline__ float gelu_exact(float x) {
    return 0.5f * x * (1.0f + erff(x * 0.7071067811865476f));
}

// ---------------- fp16 tile loader (BK=64, SW128) ----------------
#define STGH_BYTES 32768
#define TH_A 0
#define TH_B 16384
#define SMEM_DYN_H (1024 + 3 * STGH_BYTES)

template <int ASRC>
static __device__ __forceinline__ void loadh_stage(
    uint32_t buf, const __half* __restrict__ A, const __half* __restrict__ A2,
    const __half* __restrict__ B, int K, int k0, int bm, int bn, int tid)
{
#pragma unroll
    for (int i = 0; i < 4; i++) {
        const int c = tid + i * 256;
        const int r = c >> 3, ch = c & 7;
        const uint32_t bo = (uint32_t)(r * 128 + ch * 16);
        const uint32_t sw = bo ^ ((bo >> 3) & 0x70);

        const __half* pa;
        size_t aoff;
        if (ASRC == A_ROLL) {
            const int sh = c_shifts[k0 >> 10];
            const int m = bm + r, bb = m >> 11, nn = m & 2047;
            const int src = (nn - sh) & 2047;
            aoff = ((size_t)((bb << 11) | src)) * 1024u + (size_t)((k0 & 1023) + ch * 8);
            pa = A;
        } else if (ASRC == A_CONCAT) {
            pa = (k0 < 1024) ? A : A2;
            aoff = (size_t)(bm + r) * 1024u + (size_t)((k0 & 1023) + ch * 8);
        } else {  // A_DIRECT
            pa = A;
            aoff = (size_t)(bm + r) * (size_t)K + (size_t)(k0 + ch * 8);
        }
        cp16(buf + TH_A + sw, pa + aoff);

        const size_t boff = (size_t)(bn + r) * (size_t)K + (size_t)(k0 + ch * 8);
        cp16(buf + TH_B + sw, B + boff);
    }
}

static __device__ __forceinline__ void ldfragh(
    uint32_t buf, int kk, int wm, int wn,
    int a_row, int a_kb, int b_row, int b_kb,
    uint32_t (*af)[4], uint32_t (*bf)[2])
{
#pragma unroll
    for (int p = 0; p < 2; p++) {
        const uint32_t bo = (uint32_t)((wn + p * 16 + b_row) * 128 + kk * 32 + b_kb);
        const uint32_t sw = bo ^ ((bo >> 3) & 0x70);
        ldm4(bf[2*p][0], bf[2*p][1], bf[2*p+1][0], bf[2*p+1][1], buf + TH_B + sw);
    }
#pragma unroll
    for (int mt = 0; mt < 4; mt++) {
        const uint32_t bo = (uint32_t)((wm + mt * 16 + a_row) * 128 + kk * 32 + a_kb);
        const uint32_t sw = bo ^ ((bo >> 3) & 0x70);
        ldm4(af[mt][0], af[mt][1], af[mt][2], af[mt][3], buf + TH_A + sw);
    }
}

// ---------------- mainloop body (shared by both kernels) --------------------
template <int ASRC>
static __device__ __forceinline__ void mm_mainloop(
    uint32_t bufbase, const __half* __restrict__ A, const __half* __restrict__ A2,
    const __half* __restrict__ B, int K, int bm, int bn, int tid,
    int wm, int wn, int lane, float (*acc)[4][4])
{
    const int nst = K >> 6;

    loadh_stage<ASRC>(bufbase,              A, A2, B, K, 0,  bm, bn, tid);
    cp_commit();
    loadh_stage<ASRC>(bufbase + STGH_BYTES, A, A2, B, K, 64, bm, bn, tid);
    cp_commit();

    const int a_row = lane & 15;
    const int a_kb  = ((lane >> 4) & 1) * 16;
    const int b_row = (lane & 7) + ((lane >> 4) & 1) * 8;
    const int b_kb  = ((lane >> 3) & 1) * 16;

    uint32_t af[4][4], bf[4][2];

    int cur = 0;   // buffer index holding stage s
    for (int s = 0; s < nst; s++) {
        if (s < nst - 1) asm volatile("cp.async.wait_group 1;" ::: "memory");
        else             asm volatile("cp.async.wait_group 0;" ::: "memory");
        __syncthreads();   // stage s visible AND buffer (s-1) fully consumed

        const uint32_t buf = bufbase + (uint32_t)cur * STGH_BYTES;

#pragma unroll
        for (int kk = 0; kk < 4; kk++) {
            ldfragh(buf, kk, wm, wn, a_row, a_kb, b_row, b_kb, af, bf);
#pragma unroll
            for (int mt = 0; mt < 4; mt++)
#pragma unroll
                for (int nt = 0; nt < 4; nt++)
                    mma16816h(acc[mt][nt], af[mt], bf[nt]);
        }

        // load stage s+2 into the buffer consumed at s-1 (safe: top-of-s sync)
        if (s + 2 < nst) {
            int nb = cur + 2; if (nb >= 3) nb -= 3;
            loadh_stage<ASRC>(bufbase + (uint32_t)nb * STGH_BYTES,
                              A, A2, B, K, (s + 2) * 64, bm, bn, tid);
            cp_commit();
        }
        if (++cur == 3) cur = 0;
    }
}

// ---------------- fp16 single-MMA GEMM (mm1,2,3,4,8) ------------------------
template <int ASRC, int EPI>
__global__ __launch_bounds__(256, 2)
void mmh_k(const __half* __restrict__ A, const __half* __restrict__ A2,
           const __half* __restrict__ B,
           const float* __restrict__ bias, int K,
           float* __restrict__ Of, __half* __restrict__ Oh16,
           const float* __restrict__ e_gate, const float* __restrict__ e_xr)
{
    extern __shared__ char smraw[];
    const uint32_t bufbase = (s2u(smraw) + 1023u) & ~1023u;
    const int tid = threadIdx.x, wid = tid >> 5, lane = tid & 31;
    const int bn = blockIdx.x * 128, bm = blockIdx.y * 128;
    const int wm = (wid >> 2) * 64, wn = (wid & 3) * 32;

    float acc[4][4][4];
#pragma unroll
    for (int mt = 0; mt < 4; mt++)
#pragma unroll
        for (int nt = 0; nt < 4; nt++)
#pragma unroll
            for (int r = 0; r < 4; r++) acc[mt][nt][r] = 0.0f;

    mm_mainloop<ASRC>(bufbase, A, A2, B, K, bm, bn, tid, wm, wn, lane, acc);

    const int qr = lane >> 2;
    const int qc = (lane & 3) * 2;
#pragma unroll
    for (int mt = 0; mt < 4; mt++) {
#pragma unroll
        for (int nt = 0; nt < 4; nt++) {
            const int col = bn + wn + nt * 8 + qc;
            const float2 bs = *(const float2*)(bias + col);
#pragma unroll
            for (int h = 0; h < 2; h++) {
                const int row = bm + wm + mt * 16 + qr + h * 8;
                const size_t off = (size_t)row * 1024u + (size_t)col;
                float v0 = acc[mt][nt][2*h]     + bs.x;
                float v1 = acc[mt][nt][2*h + 1] + bs.y;
                if (EPI == EP_GELU_F16) {
                    v0 = gelu_exact(v0);  v1 = gelu_exact(v1);
                    *(__half2*)(Oh16 + off) = __floats2half2_rn(v0, v1);
                } else if (EPI == EP_F32_F16) {
                    *(float2*)(Of + off) = make_float2(v0, v1);
                    *(__half2*)(Oh16 + off) = __floats2half2_rn(v0, v1);
                } else if (EPI == EP_F32) {
                    *(float2*)(Of + off) = make_float2(v0, v1);
                } else if (EPI == EP_SIG) {
                    v0 = 1.0f / (1.0f + expf(-v0));
                    v1 = 1.0f / (1.0f + expf(-v1));
                    *(float2*)(Of + off) = make_float2(v0, v1);
                } else {  // EP_FINAL
                    const float2 g = *(const float2*)(e_gate + off);
                    const float2 x = *(const float2*)(e_xr + off);
                    *(float2*)(Of + off) = make_float2(
                        g.x * v0 + (1.0f - g.x) * x.x,
                        g.y * v1 + (1.0f - g.y) * x.y);
                }
            }
        }
    }
}

// ---------------- merged mm6+mm7 kernel (same A, two B's) -------------------
// grid (16,128): blockIdx.x<8 -> gate (g_w, sigmoid->f32); >=8 -> h_fc
// (fc_w1, gelu->fp16). Halves launch count + better wave quantization.
__global__ __launch_bounds__(256, 2)
void mmh67_k(const __half* __restrict__ Axr, const __half* __restrict__ Awt,
             const __half* __restrict__ Bgw, const __half* __restrict__ Bfc,
             const float* __restrict__ bias_g, const float* __restrict__ bias_fc,
             float* __restrict__ gate_out, __half* __restrict__ hfc_out)
{
    extern __shared__ char smraw[];
    const uint32_t bufbase = (s2u(smraw) + 1023u) & ~1023u;
    const int tid = threadIdx.x, wid = tid >> 5, lane = tid & 31;
    const bool is_fc = blockIdx.x >= 8;
    const int bn = (blockIdx.x & 7) * 128, bm = blockIdx.y * 128;
    const int wm = (wid >> 2) * 64, wn = (wid & 3) * 32;
    const __half* B = is_fc ? Bfc : Bgw;
    const float* bias = is_fc ? bias_fc : bias_g;

    float acc[4][4][4];
#pragma unroll
    for (int mt = 0; mt < 4; mt++)
#pragma unroll
        for (int nt = 0; nt < 4; nt++)
#pragma unroll
            for (int r = 0; r < 4; r++) acc[mt][nt][r] = 0.0f;

    mm_mainloop<A_CONCAT>(bufbase, Axr, Awt, B, 2048, bm, bn, tid, wm, wn, lane, acc);

    const int qr = lane >> 2;
    const int qc = (lane & 3) * 2;
#pragma unroll
    for (int mt = 0; mt < 4; mt++) {
#pragma unroll
        for (int nt = 0; nt < 4; nt++) {
            const int col = bn + wn + nt * 8 + qc;
            const float2 bs = *(const float2*)(bias + col);
#pragma unroll
            for (int h = 0; h < 2; h++) {
                const int row = bm + wm + mt * 16 + qr + h * 8;
                const size_t off = (size_t)row * 1024u + (size_t)col;
                float v0 = acc[mt][nt][2*h]     + bs.x;
                float v1 = acc[mt][nt][2*h + 1] + bs.y;
                if (is_fc) {
                    v0 = gelu_exact(v0);  v1 = gelu_exact(v1);
                    *(__half2*)(hfc_out + off) = __floats2half2_rn(v0, v1);
                } else {
                    v0 = 1.0f / (1.0f + expf(-v0));
                    v1 = 1.0f / (1.0f + expf(-v1));
                    *(float2*)(gate_out + off) = make_float2(v0, v1);
                }
            }
        }
    }
}

// ---------------- conversions ----------------
__global__ void qhconv_k(const float* __restrict__ Q, __half* __restrict__ H, int n)
{
    for (int i = blockIdx.x * 256 + threadIdx.x; i * 4 < n; i += gridDim.x * 256) {
        const float4 a = *(const float4*)(Q + i * 4);
        __half2 h0 = __floats2half2_rn(a.x, a.y);
        __half2 h1 = __floats2half2_rn(a.z, a.w);
        uint2 v;
        v.x = *(uint32_t*)&h0;  v.y = *(uint32_t*)&h1;
        *(uint2*)(H + i * 4) = v;
    }
}

// transpose-convert W [K,1024] f32 -> [1024,K] fp16
static __device__ __forceinline__ void whconv_body(
    const float* __restrict__ W, __half* __restrict__ T, int K, float* t)
{
    const int n0 = blockIdx.x * 32, k0 = blockIdx.y * 32;
    const int tx = threadIdx.x, ty = threadIdx.y;
#pragma unroll
    for (int i = 0; i < 4; i++)
        t[(ty + i * 8) * 33 + tx] = W[(size_t)(k0 + ty + i * 8) * 1024u + n0 + tx];
    __syncthreads();
#pragma unroll
    for (int i = 0; i < 4; i++) {
        const size_t o = (size_t)(n0 + ty + i * 8) * (size_t)K + k0 + tx;
        T[o] = __float2half_rn(t[tx * 33 + ty + i * 8]);
    }
}

__global__ void whconv_k(const float* __restrict__ W, __half* __restrict__ T, int K)
{
    __shared__ float t[32 * 33];
    whconv_body(W, T, K, t);
}

// 4 square fp16 weights in one launch: fr_w2, tc_w1, tc_w2, fc_w2
__global__ void whconv4_k(const float* W0, __half* T0, const float* W1, __half* T1,
                          const float* W2, __half* T2, const float* W3, __half* T3)
{
    __shared__ float t[32 * 33];
    const int z = blockIdx.z;
    if (z == 0)      whconv_body(W0, T0, 1024, t);
    else if (z == 1) whconv_body(W1, T1, 1024, t);
    else if (z == 2) whconv_body(W2, T2, 1024, t);
    else             whconv_body(W3, T3, 1024, t);
}

// ---------------- cluster softmax (fp16 weighted out) ----------------------
__global__ __launch_bounds__(256)
void cluster_k(const float* __restrict__ tproj, const float* __restrict__ centers,
               __half* __restrict__ wtf)
{
    __shared__ float sc[4 * 1024];
    const int tid = threadIdx.x;
    for (int i = tid * 4; i < 4096; i += 256 * 4)
        *(float4*)&sc[i] = *(const float4*)&centers[i];
    __syncthreads();

    const int warp = tid >> 5, lane = tid & 31;
    const size_t row = (size_t)blockIdx.x * 8 + warp;
    const float* tp = tproj + row * 1024u;

    float d0 = 0.f, d1 = 0.f, d2 = 0.f, d3 = 0.f;
    for (int d = lane * 4; d < 1024; d += 128) {
        float4 t  = *(const float4*)(tp + d);
        float4 c0 = *(const float4*)(sc + d);
        float4 c1 = *(const float4*)(sc + 1024 + d);
        float4 c2 = *(const float4*)(sc + 2048 + d);
        float4 c3 = *(const float4*)(sc + 3072 + d);
        d0 += t.x*c0.x + t.y*c0.y + t.z*c0.z + t.w*c0.w;
        d1 += t.x*c1.x + t.y*c1.y + t.z*c1.z + t.w*c1.w;
        d2 += t.x*c2.x + t.y*c2.y + t.z*c2.z + t.w*c2.w;
        d3 += t.x*c3.x + t.y*c3.y + t.z*c3.z + t.w*c3.w;
    }
#pragma unroll
    for (int off = 16; off > 0; off >>= 1) {
        d0 += __shfl_xor_sync(0xffffffffu, d0, off);
        d1 += __shfl_xor_sync(0xffffffffu, d1, off);
        d2 += __shfl_xor_sync(0xffffffffu, d2, off);
        d3 += __shfl_xor_sync(0xffffffffu, d3, off);
    }
    const float mx = fmaxf(fmaxf(d0, d1), fmaxf(d2, d3));
    const float e0 = expf(d0 - mx), e1 = expf(d1 - mx),
                e2 = expf(d2 - mx), e3 = expf(d3 - mx);
    const float inv = 1.0f / (e0 + e1 + e2 + e3);
    const float w0 = e0*inv, w1 = e1*inv, w2 = e2*inv, w3 = e3*inv;

    for (int d = lane * 4; d < 1024; d += 128) {
        float4 c0 = *(const float4*)(sc + d);
        float4 c1 = *(const float4*)(sc + 1024 + d);
        float4 c2 = *(const float4*)(sc + 2048 + d);
        float4 c3 = *(const float4*)(sc + 3072 + d);
        float o0 = w0*c0.x + w1*c1.x + w2*c2.x + w3*c3.x;
        float o1 = w0*c0.y + w1*c1.y + w2*c2.y + w3*c3.y;
        float o2 = w0*c0.z + w1*c1.z + w2*c2.z + w3*c3.z;
        float o3 = w0*c0.w + w1*c1.w + w2*c2.w + w3*c3.w;
        __half2 p0 = __floats2half2_rn(o0, o1);
        __half2 p1 = __floats2half2_rn(o2, o3);
        uint2 v;
        v.x = *(uint32_t*)&p0;  v.y = *(uint32_t*)&p1;
        *(uint2*)(wtf + row * 1024u + d) = v;
    }
}

// ---------------- launch ----------------
extern "C" void kernel_launch(void* const* d_in, const int* in_sizes, int n_in,
                              void* d_out, int out_size)
{
    const float* queries = (const float*)d_in[0];
    const float* fr_w1   = (const float*)d_in[1];
    const float* fr_b1   = (const float*)d_in[2];
    const float* fr_w2   = (const float*)d_in[3];
    const float* fr_b2   = (const float*)d_in[4];
    const float* tc_w1   = (const float*)d_in[5];
    const float* tc_b1   = (const float*)d_in[6];
    const float* tc_w2   = (const float*)d_in[7];
    const float* tc_b2   = (const float*)d_in[8];
    const float* centers = (const float*)d_in[9];
    const float* fc_w1   = (const float*)d_in[10];
    const float* fc_b1   = (const float*)d_in[11];
    const float* fc_w2   = (const float*)d_in[12];
    const float* fc_b2   = (const float*)d_in[13];
    const float* g_w     = (const float*)d_in[14];
    const float* g_b     = (const float*)d_in[15];
    float* out = (float*)d_out;

#define SYM(p, s) { void* _t; cudaGetSymbolAddress(&_t, s); p = (decltype(p))_t; }
    __half *qf, *w1f, *fc1f, *gwf, *w2f, *c1f, *c2f, *f2f;
    __half *h1f, *xrf16, *wtf, *t1f, *hff;
    float *xrf, *tpf, *gtf;
    SYM(qf, g_qf);     SYM(w1f, g_w1f);
    SYM(fc1f, g_fc1f); SYM(gwf, g_gwf);
    SYM(w2f, g_w2f);   SYM(c1f, g_c1f);
    SYM(c2f, g_c2f);   SYM(f2f, g_f2f);
    SYM(h1f, g_h1f);   SYM(xrf16, g_xrf16);
    SYM(wtf, g_wtf);   SYM(t1f, g_t1f);   SYM(hff, g_hff);
    SYM(xrf, g_xrf);   SYM(tpf, g_tpf);   SYM(gtf, g_gtf);
#undef SYM

    cudaFuncSetAttribute(mmh_k<A_ROLL,   EP_GELU_F16>, cudaFuncAttributeMaxDynamicSharedMemorySize, SMEM_DYN_H);
    cudaFuncSetAttribute(mmh_k<A_DIRECT, EP_F32_F16>,  cudaFuncAttributeMaxDynamicSharedMemorySize, SMEM_DYN_H);
    cudaFuncSetAttribute(mmh_k<A_DIRECT, EP_GELU_F16>, cudaFuncAttributeMaxDynamicSharedMemorySize, SMEM_DYN_H);
    cudaFuncSetAttribute(mmh_k<A_DIRECT, EP_F32>,      cudaFuncAttributeMaxDynamicSharedMemorySize, SMEM_DYN_H);
    cudaFuncSetAttribute(mmh_k<A_DIRECT, EP_FINAL>,    cudaFuncAttributeMaxDynamicSharedMemorySize, SMEM_DYN_H);
    cudaFuncSetAttribute(mmh67_k, cudaFuncAttributeMaxDynamicSharedMemorySize, SMEM_DYN_H);

    dim3 wcb(32, 8);

    // ---- conversions ----
    qhconv_k<<<2048, 256>>>(queries, qf, (int)NELE);
    whconv_k<<<dim3(32, 224), wcb>>>(fr_w1, w1f, 7168);
    whconv_k<<<dim3(32, 64),  wcb>>>(fc_w1, fc1f, 2048);
    whconv_k<<<dim3(32, 64),  wcb>>>(g_w,   gwf,  2048);
    whconv4_k<<<dim3(32, 32, 4), wcb>>>(fr_w2, w2f, tc_w1, c1f, tc_w2, c2f, fc_w2, f2f);

    dim3 grid(8, 128), block(256);

    // mm1: h1 = gelu(fusion @ fr_w1 + fr_b1)   K=7168, roll-gathered
    mmh_k<A_ROLL, EP_GELU_F16><<<grid, block, SMEM_DYN_H>>>(
        qf, nullptr, w1f, fr_b1, 7168, nullptr, h1f, nullptr, nullptr);
    // mm2: x_ring = h1 @ fr_w2 + fr_b2   -> f32 + fp16
    mmh_k<A_DIRECT, EP_F32_F16><<<grid, block, SMEM_DYN_H>>>(
        h1f, nullptr, w2f, fr_b2, 1024, xrf, xrf16, nullptr, nullptr);
    // mm3: t1 = gelu(x_ring @ tc_w1 + tc_b1)   -> fp16
    mmh_k<A_DIRECT, EP_GELU_F16><<<grid, block, SMEM_DYN_H>>>(
        xrf16, nullptr, c1f, tc_b1, 1024, nullptr, t1f, nullptr, nullptr);
    // mm4: token_proj = t1 @ tc_w2 + tc_b2   -> f32
    mmh_k<A_DIRECT, EP_F32><<<grid, block, SMEM_DYN_H>>>(
        t1f, nullptr, c2f, tc_b2, 1024, tpf, nullptr, nullptr, nullptr);
    // mm5: weighted = softmax(tp @ centers^T) @ centers  -> fp16
    cluster_k<<<MT / 8, 256>>>(tpf, centers, wtf);
    // mm6+mm7 merged: gate = sigmoid([xr|wt]@g_w+g_b); h_fc = gelu([xr|wt]@fc_w1+fc_b1)
    mmh67_k<<<dim3(16, 128), block, SMEM_DYN_H>>>(
        xrf16, wtf, gwf, fc1f, g_b, fc_b1, gtf, hff);
    // mm8: out = gate * (h_fc @ fc_w2 + fc_b2) + (1-gate) * x_ring
    mmh_k<A_DIRECT, EP_FINAL><<<grid, block, SMEM_DYN_H>>>(
        hff, nullptr, f2f, fc_b2, 1024, out, nullptr, gtf, xrf);
}

// round 15
// speedup vs baseline: 8.4781x; 1.0146x over previous
#include <cuda_runtime.h>
#include <cuda_fp16.h>
#include <cstdint>
#include <math.h>

// ---------------------------------------------------------------------------
// CenterRingFormerPlus: ALL GEMMs via single fp16 HMMA per k=16.
// Error model (validated R7-R13): ~3.5e-4 per fp16 GEMM + fp16 storage of
// gate/x_ring, quadrature w/ downstream attenuation => ~6.2e-4 < 1e-3.
// 128x128 CTA tiles, 3-stage cp.async ring (ONE sync/stage), 2 CTAs/SM,
// SW128 swizzle, fused epilogues; mm6+mm7 merged; all weight conversions
// in a single launch; fp16-only intermediates (tpf stays f32 for softmax).
// ---------------------------------------------------------------------------

#define MT 16384
#define NT 1024
#define NELE (16384u * 1024u)

// ---- scratch (device globals; no allocation allowed) ----
__device__ __half g_qf[NELE];                        // queries fp16
__device__ __half g_w1f[1024u*7168u];                // fr_w1^T fp16 [N,K]
__device__ __half g_fc1f[1024u*2048u];               // fc_w1^T fp16
__device__ __half g_gwf[1024u*2048u];                // g_w^T fp16
__device__ __half g_w2f[1024u*1024u];                // fr_w2^T fp16
__device__ __half g_c1f[1024u*1024u];                // tc_w1^T fp16
__device__ __half g_c2f[1024u*1024u];                // tc_w2^T fp16
__device__ __half g_f2f[1024u*1024u];                // fc_w2^T fp16
__device__ __half g_h1f[NELE];                       // h1 fp16
__device__ __half g_xrf16[NELE];                     // x_ring fp16
__device__ __half g_wtf[NELE];                       // weighted fp16
__device__ __half g_t1f[NELE];                       // t1 fp16
__device__ __half g_hff[NELE];                       // h_fc fp16
__device__ __half g_gtf16[NELE];                     // gate fp16
__device__ float g_tpf[NELE];                        // token_proj f32

__constant__ int c_shifts[7] = {1, -1, 0, 2, -2, 4, -4};

enum { A_DIRECT = 0, A_ROLL = 1, A_CONCAT = 2 };
enum { EP_GELU_F16 = 0, EP_F16 = 1, EP_F32 = 2, EP_FINAL = 4 };

// ---------------- helpers ----------------
static __device__ __forceinline__ uint32_t s2u(const void* p) {
    return (uint32_t)__cvta_generic_to_shared(p);
}
static __device__ __forceinline__ void cp16(uint32_t d, const void* s) {
    asm volatile("cp.async.cg.shared.global [%0], [%1], 16;\n" :: "r"(d), "l"(s));
}
static __device__ __forceinline__ void cp_commit() {
    asm volatile("cp.async.commit_group;\n" ::: "memory");
}
static __device__ __forceinline__ void ldm4(uint32_t& r0, uint32_t& r1,
                                            uint32_t& r2, uint32_t& r3, uint32_t a) {
    asm volatile("ldmatrix.sync.aligned.m8n8.x4.shared.b16 {%0,%1,%2,%3}, [%4];"
                 : "=r"(r0), "=r"(r1), "=r"(r2), "=r"(r3) : "r"(a));
}
static __device__ __forceinline__ void mma16816h(float* d, const uint32_t* a,
                                                 const uint32_t* b) {
    asm volatile(
        "mma.sync.aligned.m16n8k16.row.col.f32.f16.f16.f32 "
        "{%0,%1,%2,%3}, {%4,%5,%6,%7}, {%8,%9}, {%0,%1,%2,%3};"
        : "+f"(d[0]), "+f"(d[1]), "+f"(d[2]), "+f"(d[3])
        : "r"(a[0]), "r"(a[1]), "r"(a[2]), "r"(a[3]), "r"(b[0]), "r"(b[1]));
}
static __device__ __forceinline__ float gelu_exact(float x) {
    return 0.5f * x * (1.0f + erff(x * 0.7071067811865476f));
}

// ---------------- fp16 tile loader (BK=64, SW128) ----------------
#define STGH_BYTES 32768
#define TH_A 0
#define TH_B 16384
#define SMEM_DYN_H (1024 + 3 * STGH_BYTES)

template <int ASRC>
static __device__ __forceinline__ void loadh_stage(
    uint32_t buf, const __half* __restrict__ A, const __half* __restrict__ A2,
    const __half* __restrict__ B, int K, int k0, int bm, int bn, int tid)
{
#pragma unroll
    for (int i = 0; i < 4; i++) {
        const int c = tid + i * 256;
        const int r = c >> 3, ch = c & 7;
        const uint32_t bo = (uint32_t)(r * 128 + ch * 16);
        const uint32_t sw = bo ^ ((bo >> 3) & 0x70);

        const __half* pa;
        size_t aoff;
        if (ASRC == A_ROLL) {
            const int sh = c_shifts[k0 >> 10];
            const int m = bm + r, bb = m >> 11, nn = m & 2047;
            const int src = (nn - sh) & 2047;
            aoff = ((size_t)((bb << 11) | src)) * 1024u + (size_t)((k0 & 1023) + ch * 8);
            pa = A;
        } else if (ASRC == A_CONCAT) {
            pa = (k0 < 1024) ? A : A2;
            aoff = (size_t)(bm + r) * 1024u + (size_t)((k0 & 1023) + ch * 8);
        } else {  // A_DIRECT
            pa = A;
            aoff = (size_t)(bm + r) * (size_t)K + (size_t)(k0 + ch * 8);
        }
        cp16(buf + TH_A + sw, pa + aoff);

        const size_t boff = (size_t)(bn + r) * (size_t)K + (size_t)(k0 + ch * 8);
        cp16(buf + TH_B + sw, B + boff);
    }
}

static __device__ __forceinline__ void ldfragh(
    uint32_t buf, int kk, int wm, int wn,
    int a_row, int a_kb, int b_row, int b_kb,
    uint32_t (*af)[4], uint32_t (*bf)[2])
{
#pragma unroll
    for (int p = 0; p < 2; p++) {
        const uint32_t bo = (uint32_t)((wn + p * 16 + b_row) * 128 + kk * 32 + b_kb);
        const uint32_t sw = bo ^ ((bo >> 3) & 0x70);
        ldm4(bf[2*p][0], bf[2*p][1], bf[2*p+1][0], bf[2*p+1][1], buf + TH_B + sw);
    }
#pragma unroll
    for (int mt = 0; mt < 4; mt++) {
        const uint32_t bo = (uint32_t)((wm + mt * 16 + a_row) * 128 + kk * 32 + a_kb);
        const uint32_t sw = bo ^ ((bo >> 3) & 0x70);
        ldm4(af[mt][0], af[mt][1], af[mt][2], af[mt][3], buf + TH_A + sw);
    }
}

// ---------------- mainloop body (shared) ----------------
template <int ASRC>
static __device__ __forceinline__ void mm_mainloop(
    uint32_t bufbase, const __half* __restrict__ A, const __half* __restrict__ A2,
    const __half* __restrict__ B, int K, int bm, int bn, int tid,
    int wm, int wn, int lane, float (*acc)[4][4])
{
    const int nst = K >> 6;

    loadh_stage<ASRC>(bufbase,              A, A2, B, K, 0,  bm, bn, tid);
    cp_commit();
    loadh_stage<ASRC>(bufbase + STGH_BYTES, A, A2, B, K, 64, bm, bn, tid);
    cp_commit();

    const int a_row = lane & 15;
    const int a_kb  = ((lane >> 4) & 1) * 16;
    const int b_row = (lane & 7) + ((lane >> 4) & 1) * 8;
    const int b_kb  = ((lane >> 3) & 1) * 16;

    uint32_t af[4][4], bf[4][2];

    int cur = 0;
    for (int s = 0; s < nst; s++) {
        if (s < nst - 1) asm volatile("cp.async.wait_group 1;" ::: "memory");
        else             asm volatile("cp.async.wait_group 0;" ::: "memory");
        __syncthreads();   // stage s visible AND buffer (s-1) fully consumed

        const uint32_t buf = bufbase + (uint32_t)cur * STGH_BYTES;

#pragma unroll
        for (int kk = 0; kk < 4; kk++) {
            ldfragh(buf, kk, wm, wn, a_row, a_kb, b_row, b_kb, af, bf);
#pragma unroll
            for (int mt = 0; mt < 4; mt++)
#pragma unroll
                for (int nt = 0; nt < 4; nt++)
                    mma16816h(acc[mt][nt], af[mt], bf[nt]);
        }

        if (s + 2 < nst) {
            int nb = cur + 2; if (nb >= 3) nb -= 3;
            loadh_stage<ASRC>(bufbase + (uint32_t)nb * STGH_BYTES,
                              A, A2, B, K, (s + 2) * 64, bm, bn, tid);
            cp_commit();
        }
        if (++cur == 3) cur = 0;
    }
}

// ---------------- fp16 single-MMA GEMM (mm1,2,3,4,8) ------------------------
template <int ASRC, int EPI>
__global__ __launch_bounds__(256, 2)
void mmh_k(const __half* __restrict__ A, const __half* __restrict__ A2,
           const __half* __restrict__ B,
           const float* __restrict__ bias, int K,
           float* __restrict__ Of, __half* __restrict__ Oh16,
           const __half* __restrict__ e_gate, const __half* __restrict__ e_xr)
{
    extern __shared__ char smraw[];
    const uint32_t bufbase = (s2u(smraw) + 1023u) & ~1023u;
    const int tid = threadIdx.x, wid = tid >> 5, lane = tid & 31;
    const int bn = blockIdx.x * 128, bm = blockIdx.y * 128;
    const int wm = (wid >> 2) * 64, wn = (wid & 3) * 32;

    float acc[4][4][4];
#pragma unroll
    for (int mt = 0; mt < 4; mt++)
#pragma unroll
        for (int nt = 0; nt < 4; nt++)
#pragma unroll
            for (int r = 0; r < 4; r++) acc[mt][nt][r] = 0.0f;

    mm_mainloop<ASRC>(bufbase, A, A2, B, K, bm, bn, tid, wm, wn, lane, acc);

    const int qr = lane >> 2;
    const int qc = (lane & 3) * 2;
#pragma unroll
    for (int mt = 0; mt < 4; mt++) {
#pragma unroll
        for (int nt = 0; nt < 4; nt++) {
            const int col = bn + wn + nt * 8 + qc;
            const float2 bs = *(const float2*)(bias + col);
#pragma unroll
            for (int h = 0; h < 2; h++) {
                const int row = bm + wm + mt * 16 + qr + h * 8;
                const size_t off = (size_t)row * 1024u + (size_t)col;
                float v0 = acc[mt][nt][2*h]     + bs.x;
                float v1 = acc[mt][nt][2*h + 1] + bs.y;
                if (EPI == EP_GELU_F16) {
                    v0 = gelu_exact(v0);  v1 = gelu_exact(v1);
                    *(__half2*)(Oh16 + off) = __floats2half2_rn(v0, v1);
                } else if (EPI == EP_F16) {
                    *(__half2*)(Oh16 + off) = __floats2half2_rn(v0, v1);
                } else if (EPI == EP_F32) {
                    *(float2*)(Of + off) = make_float2(v0, v1);
                } else {  // EP_FINAL
                    const float2 g = __half22float2(*(const __half2*)(e_gate + off));
                    const float2 x = __half22float2(*(const __half2*)(e_xr + off));
                    *(float2*)(Of + off) = make_float2(
                        g.x * v0 + (1.0f - g.x) * x.x,
                        g.y * v1 + (1.0f - g.y) * x.y);
                }
            }
        }
    }
}

// ---------------- merged mm6+mm7 kernel (same A, two B's) -------------------
__global__ __launch_bounds__(256, 2)
void mmh67_k(const __half* __restrict__ Axr, const __half* __restrict__ Awt,
             const __half* __restrict__ Bgw, const __half* __restrict__ Bfc,
             const float* __restrict__ bias_g, const float* __restrict__ bias_fc,
             __half* __restrict__ gate_out, __half* __restrict__ hfc_out)
{
    extern __shared__ char smraw[];
    const uint32_t bufbase = (s2u(smraw) + 1023u) & ~1023u;
    const int tid = threadIdx.x, wid = tid >> 5, lane = tid & 31;
    const bool is_fc = blockIdx.x >= 8;
    const int bn = (blockIdx.x & 7) * 128, bm = blockIdx.y * 128;
    const int wm = (wid >> 2) * 64, wn = (wid & 3) * 32;
    const __half* B = is_fc ? Bfc : Bgw;
    const float* bias = is_fc ? bias_fc : bias_g;

    float acc[4][4][4];
#pragma unroll
    for (int mt = 0; mt < 4; mt++)
#pragma unroll
        for (int nt = 0; nt < 4; nt++)
#pragma unroll
            for (int r = 0; r < 4; r++) acc[mt][nt][r] = 0.0f;

    mm_mainloop<A_CONCAT>(bufbase, Axr, Awt, B, 2048, bm, bn, tid, wm, wn, lane, acc);

    const int qr = lane >> 2;
    const int qc = (lane & 3) * 2;
#pragma unroll
    for (int mt = 0; mt < 4; mt++) {
#pragma unroll
        for (int nt = 0; nt < 4; nt++) {
            const int col = bn + wn + nt * 8 + qc;
            const float2 bs = *(const float2*)(bias + col);
#pragma unroll
            for (int h = 0; h < 2; h++) {
                const int row = bm + wm + mt * 16 + qr + h * 8;
                const size_t off = (size_t)row * 1024u + (size_t)col;
                float v0 = acc[mt][nt][2*h]     + bs.x;
                float v1 = acc[mt][nt][2*h + 1] + bs.y;
                if (is_fc) {
                    v0 = gelu_exact(v0);  v1 = gelu_exact(v1);
                    *(__half2*)(hfc_out + off) = __floats2half2_rn(v0, v1);
                } else {
                    v0 = 1.0f / (1.0f + expf(-v0));
                    v1 = 1.0f / (1.0f + expf(-v1));
                    *(__half2*)(gate_out + off) = __floats2half2_rn(v0, v1);
                }
            }
        }
    }
}

// ---------------- conversions ----------------
__global__ void qhconv_k(const float* __restrict__ Q, __half* __restrict__ H, int n)
{
    for (int i = blockIdx.x * 256 + threadIdx.x; i * 4 < n; i += gridDim.x * 256) {
        const float4 a = *(const float4*)(Q + i * 4);
        __half2 h0 = __floats2half2_rn(a.x, a.y);
        __half2 h1 = __floats2half2_rn(a.z, a.w);
        uint2 v;
        v.x = *(uint32_t*)&h0;  v.y = *(uint32_t*)&h1;
        *(uint2*)(H + i * 4) = v;
    }
}

// ALL weight transpose-converts in ONE launch.
// grid = (480, 32): blockIdx.x = stacked k-tile index, blockIdx.y = n-tile.
//   [0,224)   fr_w1  K=7168    [224,288) fc_w1 K=2048   [288,352) g_w K=2048
//   [352,384) fr_w2  [384,416) tc_w1  [416,448) tc_w2  [448,480) fc_w2 (K=1024)
__global__ void wconvall_k(
    const float* W1, __half* T1, const float* Wfc1, __half* Tfc1,
    const float* Wgw, __half* Tgw, const float* Ww2, __half* Tw2,
    const float* Wc1, __half* Tc1, const float* Wc2, __half* Tc2,
    const float* Wf2, __half* Tf2)
{
    __shared__ float t[32 * 33];
    const int kt = blockIdx.x;
    const float* W; __half* T; int K, kl;
    if (kt < 224)      { W = W1;   T = T1;   K = 7168; kl = kt; }
    else if (kt < 288) { W = Wfc1; T = Tfc1; K = 2048; kl = kt - 224; }
    else if (kt < 352) { W = Wgw;  T = Tgw;  K = 2048; kl = kt - 288; }
    else if (kt < 384) { W = Ww2;  T = Tw2;  K = 1024; kl = kt - 352; }
    else if (kt < 416) { W = Wc1;  T = Tc1;  K = 1024; kl = kt - 384; }
    else if (kt < 448) { W = Wc2;  T = Tc2;  K = 1024; kl = kt - 416; }
    else               { W = Wf2;  T = Tf2;  K = 1024; kl = kt - 448; }

    const int n0 = blockIdx.y * 32, k0 = kl * 32;
    const int tx = threadIdx.x, ty = threadIdx.y;
#pragma unroll
    for (int i = 0; i < 4; i++)
        t[(ty + i * 8) * 33 + tx] = W[(size_t)(k0 + ty + i * 8) * 1024u + n0 + tx];
    __syncthreads();
#pragma unroll
    for (int i = 0; i < 4; i++) {
        const size_t o = (size_t)(n0 + ty + i * 8) * (size_t)K + k0 + tx;
        T[o] = __float2half_rn(t[tx * 33 + ty + i * 8]);
    }
}

// ---------------- cluster softmax (fp16 weighted out) ----------------------
__global__ __launch_bounds__(256)
void cluster_k(const float* __restrict__ tproj, const float* __restrict__ centers,
               __half* __restrict__ wtf)
{
    __shared__ float sc[4 * 1024];
    const int tid = threadIdx.x;
    for (int i = tid * 4; i < 4096; i += 256 * 4)
        *(float4*)&sc[i] = *(const float4*)&centers[i];
    __syncthreads();

    const int warp = tid >> 5, lane = tid & 31;
    const size_t row = (size_t)blockIdx.x * 8 + warp;
    const float* tp = tproj + row * 1024u;

    float d0 = 0.f, d1 = 0.f, d2 = 0.f, d3 = 0.f;
    for (int d = lane * 4; d < 1024; d += 128) {
        float4 t  = *(const float4*)(tp + d);
        float4 c0 = *(const float4*)(sc + d);
        float4 c1 = *(const float4*)(sc + 1024 + d);
        float4 c2 = *(const float4*)(sc + 2048 + d);
        float4 c3 = *(const float4*)(sc + 3072 + d);
        d0 += t.x*c0.x + t.y*c0.y + t.z*c0.z + t.w*c0.w;
        d1 += t.x*c1.x + t.y*c1.y + t.z*c1.z + t.w*c1.w;
        d2 += t.x*c2.x + t.y*c2.y + t.z*c2.z + t.w*c2.w;
        d3 += t.x*c3.x + t.y*c3.y + t.z*c3.z + t.w*c3.w;
    }
#pragma unroll
    for (int off = 16; off > 0; off >>= 1) {
        d0 += __shfl_xor_sync(0xffffffffu, d0, off);
        d1 += __shfl_xor_sync(0xffffffffu, d1, off);
        d2 += __shfl_xor_sync(0xffffffffu, d2, off);
        d3 += __shfl_xor_sync(0xffffffffu, d3, off);
    }
    const float mx = fmaxf(fmaxf(d0, d1), fmaxf(d2, d3));
    const float e0 = expf(d0 - mx), e1 = expf(d1 - mx),
                e2 = expf(d2 - mx), e3 = expf(d3 - mx);
    const float inv = 1.0f / (e0 + e1 + e2 + e3);
    const float w0 = e0*inv, w1 = e1*inv, w2 = e2*inv, w3 = e3*inv;

    for (int d = lane * 4; d < 1024; d += 128) {
        float4 c0 = *(const float4*)(sc + d);
        float4 c1 = *(const float4*)(sc + 1024 + d);
        float4 c2 = *(const float4*)(sc + 2048 + d);
        float4 c3 = *(const float4*)(sc + 3072 + d);
        float o0 = w0*c0.x + w1*c1.x + w2*c2.x + w3*c3.x;
        float o1 = w0*c0.y + w1*c1.y + w2*c2.y + w3*c3.y;
        float o2 = w0*c0.z + w1*c1.z + w2*c2.z + w3*c3.z;
        float o3 = w0*c0.w + w1*c1.w + w2*c2.w + w3*c3.w;
        __half2 p0 = __floats2half2_rn(o0, o1);
        __half2 p1 = __floats2half2_rn(o2, o3);
        uint2 v;
        v.x = *(uint32_t*)&p0;  v.y = *(uint32_t*)&p1;
        *(uint2*)(wtf + row * 1024u + d) = v;
    }
}

// ---------------- launch ----------------
extern "C" void kernel_launch(void* const* d_in, const int* in_sizes, int n_in,
                              void* d_out, int out_size)
{
    const float* queries = (const float*)d_in[0];
    const float* fr_w1   = (const float*)d_in[1];
    const float* fr_b1   = (const float*)d_in[2];
    const float* fr_w2   = (const float*)d_in[3];
    const float* fr_b2   = (const float*)d_in[4];
    const float* tc_w1   = (const float*)d_in[5];
    const float* tc_b1   = (const float*)d_in[6];
    const float* tc_w2   = (const float*)d_in[7];
    const float* tc_b2   = (const float*)d_in[8];
    const float* centers = (const float*)d_in[9];
    const float* fc_w1   = (const float*)d_in[10];
    const float* fc_b1   = (const float*)d_in[11];
    const float* fc_w2   = (const float*)d_in[12];
    const float* fc_b2   = (const float*)d_in[13];
    const float* g_w     = (const float*)d_in[14];
    const float* g_b     = (const float*)d_in[15];
    float* out = (float*)d_out;

#define SYM(p, s) { void* _t; cudaGetSymbolAddress(&_t, s); p = (decltype(p))_t; }
    __half *qf, *w1f, *fc1f, *gwf, *w2f, *c1f, *c2f, *f2f;
    __half *h1f, *xrf16, *wtf, *t1f, *hff, *gtf16;
    float *tpf;
    SYM(qf, g_qf);     SYM(w1f, g_w1f);
    SYM(fc1f, g_fc1f); SYM(gwf, g_gwf);
    SYM(w2f, g_w2f);   SYM(c1f, g_c1f);
    SYM(c2f, g_c2f);   SYM(f2f, g_f2f);
    SYM(h1f, g_h1f);   SYM(xrf16, g_xrf16);
    SYM(wtf, g_wtf);   SYM(t1f, g_t1f);   SYM(hff, g_hff);
    SYM(gtf16, g_gtf16); SYM(tpf, g_tpf);
#undef SYM

    cudaFuncSetAttribute(mmh_k<A_ROLL,   EP_GELU_F16>, cudaFuncAttributeMaxDynamicSharedMemorySize, SMEM_DYN_H);
    cudaFuncSetAttribute(mmh_k<A_DIRECT, EP_F16>,      cudaFuncAttributeMaxDynamicSharedMemorySize, SMEM_DYN_H);
    cudaFuncSetAttribute(mmh_k<A_DIRECT, EP_GELU_F16>, cudaFuncAttributeMaxDynamicSharedMemorySize, SMEM_DYN_H);
    cudaFuncSetAttribute(mmh_k<A_DIRECT, EP_F32>,      cudaFuncAttributeMaxDynamicSharedMemorySize, SMEM_DYN_H);
    cudaFuncSetAttribute(mmh_k<A_DIRECT, EP_FINAL>,    cudaFuncAttributeMaxDynamicSharedMemorySize, SMEM_DYN_H);
    cudaFuncSetAttribute(mmh67_k, cudaFuncAttributeMaxDynamicSharedMemorySize, SMEM_DYN_H);

    dim3 wcb(32, 8);

    // ---- conversions (2 launches total) ----
    qhconv_k<<<2048, 256>>>(queries, qf, (int)NELE);
    wconvall_k<<<dim3(480, 32), wcb>>>(fr_w1, w1f, fc_w1, fc1f, g_w, gwf,
                                       fr_w2, w2f, tc_w1, c1f, tc_w2, c2f,
                                       fc_w2, f2f);

    dim3 grid(8, 128), block(256);

    // mm1: h1 = gelu(fusion @ fr_w1 + fr_b1)   K=7168, roll-gathered
    mmh_k<A_ROLL, EP_GELU_F16><<<grid, block, SMEM_DYN_H>>>(
        qf, nullptr, w1f, fr_b1, 7168, nullptr, h1f, nullptr, nullptr);
    // mm2: x_ring = h1 @ fr_w2 + fr_b2   -> fp16
    mmh_k<A_DIRECT, EP_F16><<<grid, block, SMEM_DYN_H>>>(
        h1f, nullptr, w2f, fr_b2, 1024, nullptr, xrf16, nullptr, nullptr);
    // mm3: t1 = gelu(x_ring @ tc_w1 + tc_b1)   -> fp16
    mmh_k<A_DIRECT, EP_GELU_F16><<<grid, block, SMEM_DYN_H>>>(
        xrf16, nullptr, c1f, tc_b1, 1024, nullptr, t1f, nullptr, nullptr);
    // mm4: token_proj = t1 @ tc_w2 + tc_b2   -> f32
    mmh_k<A_DIRECT, EP_F32><<<grid, block, SMEM_DYN_H>>>(
        t1f, nullptr, c2f, tc_b2, 1024, tpf, nullptr, nullptr, nullptr);
    // mm5: weighted = softmax(tp @ centers^T) @ centers  -> fp16
    cluster_k<<<MT / 8, 256>>>(tpf, centers, wtf);
    // mm6+mm7 merged: gate (sigmoid->fp16) and h_fc (gelu->fp16)
    mmh67_k<<<dim3(16, 128), block, SMEM_DYN_H>>>(
        xrf16, wtf, gwf, fc1f, g_b, fc_b1, gtf16, hff);
    // mm8: out = gate * (h_fc @ fc_w2 + fc_b2) + (1-gate) * x_ring
    mmh_k<A_DIRECT, EP_FINAL><<<grid, block, SMEM_DYN_H>>>(
        hff, nullptr, f2f, fc_b2, 1024, out, nullptr, gtf16, xrf16);
}